// round 1
// baseline (speedup 1.0000x reference)
#include <cuda_runtime.h>
#include <cuda_bf16.h>
#include <cstdint>
#include <cstddef>

// ---------------------------------------------------------------------------
// DGCNN pipeline, fp32 baseline.
//   B=8, N=2048, K=20.  Layers: (C=3,O=64) (64,64) (64,128) (128,256)
//   concat 512 -> wm (1024x512) -> GN16 -> max over N -> MLP head -> (8,2)
// Edge conv factorization: h = ctr*(Wa-Wb)^T + nbr*Wb^T
//   -> two small GEMMs (hc, hn) + gather-add; never materialize B*N*K*O.
// ---------------------------------------------------------------------------

#define NPTS   2048
#define NB     8
#define NROWS  (NB*NPTS)   // 16384
#define KNN    20

// ------------------------- device scratch (no allocs) ----------------------
__device__ float  g_gram[(size_t)NB * NPTS * NPTS];   // 134 MB, reused per layer
__device__ float  g_hh[(size_t)NROWS * 512];          // [rows x 2O], hc | hn
__device__ float  g_concat[(size_t)NROWS * 512];      // x1|x2|x3|x4
__device__ float  g_hm[(size_t)NROWS * 1024];         // seq features
__device__ float  g_sq[NROWS];
__device__ int    g_idx[(size_t)NROWS * KNN];
__device__ float  g_wtmp[128 * 512];                  // transformed weights (C x 2O)
__device__ double g_stats[256];                       // per (b,group) sum/sumsq
__device__ float  g_mu[128];
__device__ float  g_rs[128];
__device__ float  g_gvec[NB * 1024];

// ------------------------------ helpers ------------------------------------
__device__ __forceinline__ float leaky02(float v) { return v > 0.f ? v : 0.2f * v; }

// ------------------------------ sq kernel ----------------------------------
__global__ void sq_kernel(const float* __restrict__ X, int ldx, int C) {
    int r = blockIdx.x * 256 + threadIdx.x;
    if (r < NROWS) {
        float s = 0.f;
        const float* xp = X + (size_t)r * ldx;
        for (int c = 0; c < C; c++) { float v = xp[c]; s += v * v; }
        g_sq[r] = s;
    }
}

// --------------------------- generic tiled SGEMM ---------------------------
// C[m,n] = sum_k A[m,k] * B(k,n);  TRANSB: B(k,n)=Bp[n*ldb+k] else Bp[k*ldb+n]
// M,N multiples of 64; K arbitrary. 64x64 tile, 16 k-chunk, 4x4 per thread.
template <bool TRANSB>
__global__ __launch_bounds__(256) void sgemm64(
    const float* __restrict__ A, int lda, size_t sA,
    const float* __restrict__ Bp, int ldb, size_t sB,
    float* __restrict__ Cp, int ldc, size_t sC, int K)
{
    __shared__ __align__(16) float As[16][68];
    __shared__ __align__(16) float Bs[16][68];
    const float* Ab = A  + (size_t)blockIdx.z * sA;
    const float* Bb = Bp + (size_t)blockIdx.z * sB;
    float*       Cb = Cp + (size_t)blockIdx.z * sC;
    int m0 = blockIdx.y * 64, n0 = blockIdx.x * 64;
    int tx = threadIdx.x, ty = threadIdx.y;
    int tid = ty * 16 + tx;
    float acc[4][4] = {};
    for (int k0 = 0; k0 < K; k0 += 16) {
#pragma unroll
        for (int i = 0; i < 4; i++) {
            int e = tid + i * 256;
            int m = e >> 4, kk = e & 15;
            int k = k0 + kk;
            As[kk][m] = (k < K) ? Ab[(size_t)(m0 + m) * lda + k] : 0.f;
        }
#pragma unroll
        for (int i = 0; i < 4; i++) {
            int e = tid + i * 256;
            if (TRANSB) {
                int n = e >> 4, kk = e & 15;
                int k = k0 + kk;
                Bs[kk][n] = (k < K) ? Bb[(size_t)(n0 + n) * ldb + k] : 0.f;
            } else {
                int n = e & 63, kk = e >> 6;
                int k = k0 + kk;
                Bs[kk][n] = (k < K) ? Bb[(size_t)k * ldb + (n0 + n)] : 0.f;
            }
        }
        __syncthreads();
#pragma unroll
        for (int kk = 0; kk < 16; kk++) {
            float4 av = *(const float4*)&As[kk][ty * 4];
            float4 bv = *(const float4*)&Bs[kk][tx * 4];
            float a[4] = {av.x, av.y, av.z, av.w};
            float b[4] = {bv.x, bv.y, bv.z, bv.w};
#pragma unroll
            for (int i = 0; i < 4; i++)
#pragma unroll
                for (int j = 0; j < 4; j++) acc[i][j] += a[i] * b[j];
        }
        __syncthreads();
    }
#pragma unroll
    for (int i = 0; i < 4; i++)
#pragma unroll
        for (int j = 0; j < 4; j++)
            Cb[(size_t)(m0 + ty * 4 + i) * ldc + (n0 + tx * 4 + j)] = acc[i][j];
}

// ------------------------------- knn select --------------------------------
// One block per query point. dist = sq[n]+sq[m]-2*dot. 20 argmin passes,
// tie-break by lower index (matches jax.lax.top_k). Self excluded.
__global__ __launch_bounds__(256) void select_kernel() {
    __shared__ float sdist[NPTS];
    __shared__ float rv[256];
    __shared__ int   ri[256];
    int row = blockIdx.x;
    int b = row >> 11, n = row & 2047;
    const float* drow = g_gram + (size_t)b * NPTS * NPTS + (size_t)n * NPTS;
    float sqn = g_sq[row];
    int t = threadIdx.x;
    for (int m = t; m < NPTS; m += 256) {
        float d = sqn + g_sq[(b << 11) + m] - 2.f * drow[m];
        sdist[m] = (m == n) ? 3.4e38f : d;
    }
    __syncthreads();
    for (int it = 0; it < KNN; it++) {
        float bv = 3.4e38f; int bi = 0x7fffffff;
        for (int m = t; m < NPTS; m += 256) {
            float v = sdist[m];
            if (v < bv) { bv = v; bi = m; }
        }
        rv[t] = bv; ri[t] = bi;
        __syncthreads();
        for (int s = 128; s > 0; s >>= 1) {
            if (t < s) {
                float v2 = rv[t + s]; int i2 = ri[t + s];
                if (v2 < rv[t] || (v2 == rv[t] && i2 < ri[t])) { rv[t] = v2; ri[t] = i2; }
            }
            __syncthreads();
        }
        if (t == 0) {
            g_idx[(size_t)row * KNN + it] = ri[0];
            sdist[ri[0]] = 3.4e38f;
        }
        __syncthreads();
    }
}

// --------------------------- weight transform ------------------------------
// wtmp (C x 2O): col o<O = Wa-Wb column, col O+o = Wb column
__global__ void wtmp_kernel(const float* __restrict__ w, int C, int O) {
    int i = blockIdx.x * 256 + threadIdx.x;
    int tot = C * 2 * O;
    if (i < tot) {
        int c = i / (2 * O);
        int o = i % (2 * O);
        float v;
        if (o < O) v = w[(size_t)o * (2 * C) + c] - w[(size_t)o * (2 * C) + C + c];
        else       v = w[(size_t)(o - O) * (2 * C) + C + c];
        g_wtmp[i] = v;
    }
}

// ------------------------------ stats zero ---------------------------------
__global__ void zero_stats() { g_stats[threadIdx.x] = 0.0; }

// --------------------------- edge GN stats pass -----------------------------
// h[row,k,c] = hc[row,c] + hn[b*N+idx[row,k], c]; accumulate per (b, c/(O/4)).
__global__ __launch_bounds__(256) void edge_stats_kernel(int O) {
    __shared__ int   sidx[KNN];
    __shared__ float ps[256], pq[256];
    int row = blockIdx.x;
    int b = row >> 11;
    int t = threadIdx.x;
    if (t < KNN) sidx[t] = g_idx[(size_t)row * KNN + t];
    __syncthreads();
    int twoO = 2 * O;
    int c = t % O;
    int k0 = t / O;
    int kstep = 256 / O;
    float hcv = g_hh[(size_t)row * twoO + c];
    size_t bbase = ((size_t)(b << 11)) * twoO + O + c;
    float s = 0.f, q = 0.f;
    for (int k = k0; k < KNN; k += kstep) {
        float h = hcv + g_hh[bbase + (size_t)sidx[k] * twoO];
        s += h; q += h * h;
    }
    ps[t] = s; pq[t] = q;
    __syncthreads();
    int gs = O / 4;
    if (t < 4) {
        double S = 0.0, Q = 0.0;
        for (int j = 0; j < 256; j++) {
            if ((j % O) / gs == t) { S += ps[j]; Q += pq[j]; }
        }
        atomicAdd(&g_stats[((b * 4) + t) * 2 + 0], S);
        atomicAdd(&g_stats[((b * 4) + t) * 2 + 1], Q);
    }
}

// -------------------------- finalize GN statistics --------------------------
__global__ void finalize_stats(int ngroups, double cnt) {
    int i = threadIdx.x;
    if (i < NB * ngroups) {
        double s = g_stats[i * 2 + 0], q = g_stats[i * 2 + 1];
        double mu = s / cnt;
        double var = q / cnt - mu * mu;
        g_mu[i] = (float)mu;
        g_rs[i] = rsqrtf((float)var + 1e-5f);
    }
}

// ----------------------- edge normalize + leaky + max-k ---------------------
__global__ void edge_normmax_kernel(int O, int coff,
                                    const float* __restrict__ gw,
                                    const float* __restrict__ gb) {
    __shared__ int sidx[KNN];
    int row = blockIdx.x;
    int b = row >> 11;
    int t = threadIdx.x;                 // blockDim == O
    if (t < KNN) sidx[t] = g_idx[(size_t)row * KNN + t];
    __syncthreads();
    int c = t;
    int twoO = 2 * O;
    float hcv = g_hh[(size_t)row * twoO + c];
    int g = c / (O / 4);
    float mu = g_mu[b * 4 + g], rs = g_rs[b * 4 + g];
    float w = gw[c], bb = gb[c];
    size_t bbase = ((size_t)(b << 11)) * twoO + O + c;
    float m = -3.4e38f;
#pragma unroll
    for (int k = 0; k < KNN; k++) {
        float h = hcv + g_hh[bbase + (size_t)sidx[k] * twoO];
        float v = (h - mu) * rs * w + bb;
        m = fmaxf(m, leaky02(v));
    }
    g_concat[(size_t)row * 512 + coff + c] = m;
}

// ------------------------------ seq GN stats --------------------------------
__global__ __launch_bounds__(256) void seq_stats_kernel() {
    __shared__ float ps[256], pq[256];
    int row = blockIdx.x;
    int b = row >> 11;
    int t = threadIdx.x;
    const float* hr = g_hm + (size_t)row * 1024;
    float s = 0.f, q = 0.f;
#pragma unroll
    for (int j = 0; j < 4; j++) { float v = hr[t * 4 + j]; s += v; q += v * v; }
    ps[t] = s; pq[t] = q;
    __syncthreads();
    if (t < 16) {
        double S = 0.0, Q = 0.0;
        for (int j = t * 16; j < t * 16 + 16; j++) { S += ps[j]; Q += pq[j]; }
        atomicAdd(&g_stats[(b * 16 + t) * 2 + 0], S);
        atomicAdd(&g_stats[(b * 16 + t) * 2 + 1], Q);
    }
}

// ------------------- seq normalize + leaky + max over N ---------------------
__global__ __launch_bounds__(256) void seq_max_kernel(const float* __restrict__ gmw,
                                                      const float* __restrict__ gmb) {
    int c = blockIdx.x * 256 + threadIdx.x;
    int b = blockIdx.y;
    int g = c >> 6;
    float mu = g_mu[b * 16 + g], rs = g_rs[b * 16 + g];
    float w = gmw[c], bb = gmb[c];
    const float* col = g_hm + ((size_t)b * NPTS) * 1024 + c;
    float m = -3.4e38f;
    for (int n = 0; n < NPTS; n++) {
        float v = (col[(size_t)n * 1024] - mu) * rs * w + bb;
        m = fmaxf(m, leaky02(v));
    }
    g_gvec[b * 1024 + c] = m;
}

// --------------------------------- MLP head ---------------------------------
__device__ __forceinline__ float bsum256(float v, float* red, int t) {
    red[t] = v; __syncthreads();
    for (int s = 128; s > 0; s >>= 1) {
        if (t < s) red[t] += red[t + s];
        __syncthreads();
    }
    float r = red[0]; __syncthreads();
    return r;
}

__device__ __forceinline__ void ln_leaky(float* buf, int L,
                                         const float* __restrict__ w,
                                         const float* __restrict__ b,
                                         float* red, int t) {
    float s = 0.f, q = 0.f;
    for (int i = t; i < L; i += 256) { float v = buf[i]; s += v; q += v * v; }
    float S = bsum256(s, red, t);
    float Q = bsum256(q, red, t);
    float mu = S / (float)L;
    float var = Q / (float)L - mu * mu;
    float rs = rsqrtf(var + 1e-5f);
    for (int i = t; i < L; i += 256) {
        float v = (buf[i] - mu) * rs * w[i] + b[i];
        buf[i] = leaky02(v);
    }
    __syncthreads();
}

__global__ __launch_bounds__(256) void mlp_kernel(
    const float* __restrict__ fc1w, const float* __restrict__ fc1b,
    const float* __restrict__ ln1w, const float* __restrict__ ln1b,
    const float* __restrict__ fc2w, const float* __restrict__ fc2b,
    const float* __restrict__ ln2w, const float* __restrict__ ln2b,
    const float* __restrict__ fc3w, const float* __restrict__ fc3b,
    const float* __restrict__ ln3w, const float* __restrict__ ln3b,
    const float* __restrict__ fc4w, const float* __restrict__ fc4b,
    float* __restrict__ out)
{
    __shared__ __align__(16) float sin_[1024];
    __shared__ __align__(16) float t1[512];
    __shared__ __align__(16) float t2[256];
    __shared__ __align__(16) float t3[64];
    __shared__ float red[256];
    int b = blockIdx.x, t = threadIdx.x;
    for (int i = t; i < 1024; i += 256) sin_[i] = g_gvec[b * 1024 + i];
    __syncthreads();
    // fc1: 512 x 1024
    for (int o = t; o < 512; o += 256) {
        float acc = fc1b[o];
        const float4* wr = (const float4*)(fc1w + (size_t)o * 1024);
        const float4* xr = (const float4*)sin_;
        for (int c = 0; c < 256; c++) {
            float4 w4 = wr[c], x4 = xr[c];
            acc += w4.x * x4.x + w4.y * x4.y + w4.z * x4.z + w4.w * x4.w;
        }
        t1[o] = acc;
    }
    __syncthreads();
    ln_leaky(t1, 512, ln1w, ln1b, red, t);
    // fc2: 256 x 512
    if (t < 256) {
        float acc = fc2b[t];
        const float4* wr = (const float4*)(fc2w + (size_t)t * 512);
        const float4* xr = (const float4*)t1;
        for (int c = 0; c < 128; c++) {
            float4 w4 = wr[c], x4 = xr[c];
            acc += w4.x * x4.x + w4.y * x4.y + w4.z * x4.z + w4.w * x4.w;
        }
        t2[t] = acc;
    }
    __syncthreads();
    ln_leaky(t2, 256, ln2w, ln2b, red, t);
    // fc3: 64 x 256
    if (t < 64) {
        float acc = fc3b[t];
        const float4* wr = (const float4*)(fc3w + (size_t)t * 256);
        const float4* xr = (const float4*)t2;
        for (int c = 0; c < 64; c++) {
            float4 w4 = wr[c], x4 = xr[c];
            acc += w4.x * x4.x + w4.y * x4.y + w4.z * x4.z + w4.w * x4.w;
        }
        t3[t] = acc;
    }
    __syncthreads();
    ln_leaky(t3, 64, ln3w, ln3b, red, t);
    // fc4: 2 x 64
    if (t < 2) {
        float acc = fc4b[t];
        for (int c = 0; c < 64; c++) acc += fc4w[t * 64 + c] * t3[c];
        out[b * 2 + t] = acc;
    }
}

// =============================== host driver ================================
extern "C" void kernel_launch(void* const* d_in, const int* in_sizes, int n_in,
                              void* d_out, int out_size)
{
    const float* x    = (const float*)d_in[0];
    const float* w1   = (const float*)d_in[1];
    const float* g1w  = (const float*)d_in[2];
    const float* g1b  = (const float*)d_in[3];
    const float* w2   = (const float*)d_in[4];
    const float* g2w  = (const float*)d_in[5];
    const float* g2b  = (const float*)d_in[6];
    const float* w3   = (const float*)d_in[7];
    const float* g3w  = (const float*)d_in[8];
    const float* g3b  = (const float*)d_in[9];
    const float* w4   = (const float*)d_in[10];
    const float* g4w  = (const float*)d_in[11];
    const float* g4b  = (const float*)d_in[12];
    const float* wm   = (const float*)d_in[13];
    const float* gmw  = (const float*)d_in[14];
    const float* gmb  = (const float*)d_in[15];
    const float* fc1w = (const float*)d_in[16];
    const float* fc1b = (const float*)d_in[17];
    const float* ln1w = (const float*)d_in[18];
    const float* ln1b = (const float*)d_in[19];
    const float* fc2w = (const float*)d_in[20];
    const float* fc2b = (const float*)d_in[21];
    const float* ln2w = (const float*)d_in[22];
    const float* ln2b = (const float*)d_in[23];
    const float* fc3w = (const float*)d_in[24];
    const float* fc3b = (const float*)d_in[25];
    const float* ln3w = (const float*)d_in[26];
    const float* ln3b = (const float*)d_in[27];
    const float* fc4w = (const float*)d_in[28];
    const float* fc4b = (const float*)d_in[29];
    float* out = (float*)d_out;

    float *pGram, *pConcat, *pHH, *pHm, *pWtmp;
    cudaGetSymbolAddress((void**)&pGram,   g_gram);
    cudaGetSymbolAddress((void**)&pConcat, g_concat);
    cudaGetSymbolAddress((void**)&pHH,     g_hh);
    cudaGetSymbolAddress((void**)&pHm,     g_hm);
    cudaGetSymbolAddress((void**)&pWtmp,   g_wtmp);

    struct LayerCfg {
        const float* X; int ldx; int C; int O;
        const float* w; const float* gw; const float* gb; int coff;
    };
    LayerCfg layers[4] = {
        { x,            3,   3,   64,  w1, g1w, g1b, 0   },
        { pConcat + 0,  512, 64,  64,  w2, g2w, g2b, 64  },
        { pConcat + 64, 512, 64,  128, w3, g3w, g3b, 128 },
        { pConcat + 128,512, 128, 256, w4, g4w, g4b, 256 },
    };

    dim3 tb(16, 16);
    for (int l = 0; l < 4; l++) {
        const LayerCfg& L = layers[l];
        // 1) squared norms
        sq_kernel<<<(NROWS + 255) / 256, 256>>>(L.X, L.ldx, L.C);
        // 2) per-batch Gram: dot[n][m]
        sgemm64<true><<<dim3(NPTS / 64, NPTS / 64, NB), tb>>>(
            L.X, L.ldx, (size_t)NPTS * L.ldx,
            L.X, L.ldx, (size_t)NPTS * L.ldx,
            pGram, NPTS, (size_t)NPTS * NPTS, L.C);
        // 3) knn top-20 select
        select_kernel<<<NROWS, 256>>>();
        // 4) weight transform + hc|hn GEMM (rows x 2O)
        wtmp_kernel<<<(L.C * 2 * L.O + 255) / 256, 256>>>(L.w, L.C, L.O);
        sgemm64<false><<<dim3(2 * L.O / 64, NROWS / 64, 1), tb>>>(
            L.X, L.ldx, 0,
            pWtmp, 2 * L.O, 0,
            pHH, 2 * L.O, 0, L.C);
        // 5) GN stats (gather pass 1)
        zero_stats<<<1, 256>>>();
        edge_stats_kernel<<<NROWS, 256>>>(L.O);
        finalize_stats<<<1, 128>>>(4, (double)NPTS * KNN * (L.O / 4));
        // 6) normalize + leaky + max over k (gather pass 2)
        edge_normmax_kernel<<<NROWS, L.O>>>(L.O, L.coff, L.gw, L.gb);
    }

    // mid: hm = concat @ wm^T  (16384 x 512 x 1024)
    sgemm64<true><<<dim3(1024 / 64, NROWS / 64, 1), tb>>>(
        pConcat, 512, 0, wm, 512, 0, pHm, 1024, 0, 512);
    zero_stats<<<1, 256>>>();
    seq_stats_kernel<<<NROWS, 256>>>();
    finalize_stats<<<1, 128>>>(16, (double)NPTS * 64);
    seq_max_kernel<<<dim3(4, NB), 256>>>(gmw, gmb);

    // head MLP
    mlp_kernel<<<NB, 256>>>(fc1w, fc1b, ln1w, ln1b,
                            fc2w, fc2b, ln2w, ln2b,
                            fc3w, fc3b, ln3w, ln3b,
                            fc4w, fc4b, out);
}

// round 2
// speedup vs baseline: 1.0362x; 1.0362x over previous
#include <cuda_runtime.h>
#include <cuda_bf16.h>
#include <cstdint>
#include <cstddef>

// ---------------------------------------------------------------------------
// DGCNN pipeline, fp32. B=8, N=2048, K=20.
// Edge conv factorization: h = ctr*(Wa-Wb)^T + nbr*Wb^T  -> two small GEMMs
// (hc|hn) + gather-add; edge tensor never materialized.
// Round 2: high-efficiency 128x128x8 double-buffered SGEMM (8x8/thread),
// layer-1 (C=3) gets a fused point-cloud knn kernel (no gram round-trip).
// ---------------------------------------------------------------------------

#define NPTS   2048
#define NB     8
#define NROWS  (NB*NPTS)   // 16384
#define KNN    20

// ------------------------- device scratch (no allocs) ----------------------
__device__ float  g_gram[(size_t)NB * NPTS * NPTS];   // reused per layer
__device__ float  g_hh[(size_t)NROWS * 512];          // [rows x 2O], hc | hn
__device__ float  g_concat[(size_t)NROWS * 512];      // x1|x2|x3|x4
__device__ float  g_hm[(size_t)NROWS * 1024];         // seq features
__device__ float  g_sq[NROWS];
__device__ int    g_idx[(size_t)NROWS * KNN];
__device__ float  g_wtmp[128 * 512];                  // transformed weights (C x 2O)
__device__ double g_stats[256];                       // per (b,group) sum/sumsq
__device__ float  g_mu[128];
__device__ float  g_rs[128];
__device__ float  g_gvec[NB * 1024];

__device__ __forceinline__ float leaky02(float v) { return v > 0.f ? v : 0.2f * v; }

// ------------------------------ sq kernel ----------------------------------
__global__ void sq_kernel(const float* __restrict__ X, int ldx, int C) {
    int r = blockIdx.x * 256 + threadIdx.x;
    if (r < NROWS) {
        float s = 0.f;
        const float* xp = X + (size_t)r * ldx;
        for (int c = 0; c < C; c++) { float v = xp[c]; s += v * v; }
        g_sq[r] = s;
    }
}

// ----------------- 128x128x8 double-buffered SGEMM (8x8/thread) ------------
// C[m,n] = sum_k A[m,k]*B(k,n); TRANSB: B(k,n)=Bp[n*ldb+k] else Bp[k*ldb+n].
// Requires: M,N multiples of 128; K multiple of 8; lda/ldb/k0 float4-friendly.
template <bool TRANSB>
__global__ __launch_bounds__(256, 2) void sgemm128(
    const float* __restrict__ A, int lda, size_t sA,
    const float* __restrict__ Bp, int ldb, size_t sB,
    float* __restrict__ Cp, int ldc, size_t sC, int K)
{
    __shared__ __align__(16) float As[2][8][132];
    __shared__ __align__(16) float Bs[2][8][132];
    const float* Ab = A  + (size_t)blockIdx.z * sA;
    const float* Bb = Bp + (size_t)blockIdx.z * sB;
    float*       Cb = Cp + (size_t)blockIdx.z * sC;
    const int m0 = blockIdx.y * 128, n0 = blockIdx.x * 128;
    const int tid = threadIdx.x;
    const int tx = tid & 15, ty = tid >> 4;

    // global load mappings
    const int ma = tid >> 1;            // 0..127
    const int ka = (tid & 1) * 4;       // 0 or 4
    const int kb = tid >> 5;            // 0..7   (non-trans B)
    const int nb = (tid & 31) * 4;      // 0..124

    float acc[8][8] = {};
    const int nk = K >> 3;
    float4 va, vb;

    // prologue: chunk 0
    va = *(const float4*)&Ab[(size_t)(m0 + ma) * lda + ka];
    if (TRANSB) vb = *(const float4*)&Bb[(size_t)(n0 + ma) * ldb + ka];
    else        vb = *(const float4*)&Bb[(size_t)kb * ldb + n0 + nb];
    As[0][ka+0][ma] = va.x; As[0][ka+1][ma] = va.y;
    As[0][ka+2][ma] = va.z; As[0][ka+3][ma] = va.w;
    if (TRANSB) {
        Bs[0][ka+0][ma] = vb.x; Bs[0][ka+1][ma] = vb.y;
        Bs[0][ka+2][ma] = vb.z; Bs[0][ka+3][ma] = vb.w;
    } else {
        *(float4*)&Bs[0][kb][nb] = vb;
    }
    __syncthreads();

    for (int kc = 0; kc < nk; kc++) {
        const int buf = kc & 1;
        if (kc + 1 < nk) {
            const int k0 = (kc + 1) << 3;
            va = *(const float4*)&Ab[(size_t)(m0 + ma) * lda + k0 + ka];
            if (TRANSB) vb = *(const float4*)&Bb[(size_t)(n0 + ma) * ldb + k0 + ka];
            else        vb = *(const float4*)&Bb[(size_t)(k0 + kb) * ldb + n0 + nb];
        }
#pragma unroll
        for (int kk = 0; kk < 8; kk++) {
            float a[8], b[8];
            *(float4*)&a[0] = *(const float4*)&As[buf][kk][ty * 4];
            *(float4*)&a[4] = *(const float4*)&As[buf][kk][64 + ty * 4];
            *(float4*)&b[0] = *(const float4*)&Bs[buf][kk][tx * 4];
            *(float4*)&b[4] = *(const float4*)&Bs[buf][kk][64 + tx * 4];
#pragma unroll
            for (int i = 0; i < 8; i++)
#pragma unroll
                for (int j = 0; j < 8; j++) acc[i][j] += a[i] * b[j];
        }
        if (kc + 1 < nk) {
            const int nbuf = buf ^ 1;
            As[nbuf][ka+0][ma] = va.x; As[nbuf][ka+1][ma] = va.y;
            As[nbuf][ka+2][ma] = va.z; As[nbuf][ka+3][ma] = va.w;
            if (TRANSB) {
                Bs[nbuf][ka+0][ma] = vb.x; Bs[nbuf][ka+1][ma] = vb.y;
                Bs[nbuf][ka+2][ma] = vb.z; Bs[nbuf][ka+3][ma] = vb.w;
            } else {
                *(float4*)&Bs[nbuf][kb][nb] = vb;
            }
        }
        __syncthreads();
    }

    // epilogue: rows {m0+ty*4+i, m0+64+ty*4+i}, cols {n0+tx*4, n0+64+tx*4}
#pragma unroll
    for (int i = 0; i < 8; i++) {
        const int mrow = m0 + ((i < 4) ? (ty * 4 + i) : (64 + ty * 4 + i - 4));
        float* Cr = &Cb[(size_t)mrow * ldc + n0];
        *(float4*)(Cr + tx * 4)      = make_float4(acc[i][0], acc[i][1], acc[i][2], acc[i][3]);
        *(float4*)(Cr + 64 + tx * 4) = make_float4(acc[i][4], acc[i][5], acc[i][6], acc[i][7]);
    }
}

// ------------------------------- knn select --------------------------------
// (layers 2-4) one block per query point, distances from precomputed gram.
__global__ __launch_bounds__(256) void select_kernel() {
    __shared__ float sdist[NPTS];
    __shared__ float rv[256];
    __shared__ int   ri[256];
    int row = blockIdx.x;
    int b = row >> 11, n = row & 2047;
    const float* drow = g_gram + (size_t)b * NPTS * NPTS + (size_t)n * NPTS;
    float sqn = g_sq[row];
    int t = threadIdx.x;
    for (int m = t; m < NPTS; m += 256) {
        float d = sqn + g_sq[(b << 11) + m] - 2.f * drow[m];
        sdist[m] = (m == n) ? 3.4e38f : d;
    }
    __syncthreads();
    for (int it = 0; it < KNN; it++) {
        float bv = 3.4e38f; int bi = 0x7fffffff;
        for (int m = t; m < NPTS; m += 256) {
            float v = sdist[m];
            if (v < bv) { bv = v; bi = m; }
        }
        rv[t] = bv; ri[t] = bi;
        __syncthreads();
        for (int s = 128; s > 0; s >>= 1) {
            if (t < s) {
                float v2 = rv[t + s]; int i2 = ri[t + s];
                if (v2 < rv[t] || (v2 == rv[t] && i2 < ri[t])) { rv[t] = v2; ri[t] = i2; }
            }
            __syncthreads();
        }
        if (t == 0) {
            g_idx[(size_t)row * KNN + it] = ri[0];
            sdist[ri[0]] = 3.4e38f;
        }
        __syncthreads();
    }
}

// --------------- layer-1 fused knn (C=3, points in smem) -------------------
__global__ __launch_bounds__(256) void select3_kernel(const float* __restrict__ X) {
    __shared__ float px[NPTS], py[NPTS], pz[NPTS];
    __shared__ float sdist[NPTS];
    __shared__ float rv[256];
    __shared__ int   ri[256];
    int row = blockIdx.x;
    int b = row >> 11, n = row & 2047;
    int t = threadIdx.x;
    const float* Xb = X + (size_t)(b << 11) * 3;
    for (int m = t; m < NPTS; m += 256) {
        px[m] = Xb[m * 3 + 0];
        py[m] = Xb[m * 3 + 1];
        pz[m] = Xb[m * 3 + 2];
    }
    __syncthreads();
    float xn = px[n], yn = py[n], zn = pz[n];
    float sqn = g_sq[row];
    for (int m = t; m < NPTS; m += 256) {
        float dot = xn * px[m] + yn * py[m] + zn * pz[m];
        float d = sqn + g_sq[(b << 11) + m] - 2.f * dot;
        sdist[m] = (m == n) ? 3.4e38f : d;
    }
    __syncthreads();
    for (int it = 0; it < KNN; it++) {
        float bv = 3.4e38f; int bi = 0x7fffffff;
        for (int m = t; m < NPTS; m += 256) {
            float v = sdist[m];
            if (v < bv) { bv = v; bi = m; }
        }
        rv[t] = bv; ri[t] = bi;
        __syncthreads();
        for (int s = 128; s > 0; s >>= 1) {
            if (t < s) {
                float v2 = rv[t + s]; int i2 = ri[t + s];
                if (v2 < rv[t] || (v2 == rv[t] && i2 < ri[t])) { rv[t] = v2; ri[t] = i2; }
            }
            __syncthreads();
        }
        if (t == 0) {
            g_idx[(size_t)row * KNN + it] = ri[0];
            sdist[ri[0]] = 3.4e38f;
        }
        __syncthreads();
    }
}

// --------------------------- weight transform ------------------------------
__global__ void wtmp_kernel(const float* __restrict__ w, int C, int O) {
    int i = blockIdx.x * 256 + threadIdx.x;
    int tot = C * 2 * O;
    if (i < tot) {
        int c = i / (2 * O);
        int o = i % (2 * O);
        float v;
        if (o < O) v = w[(size_t)o * (2 * C) + c] - w[(size_t)o * (2 * C) + C + c];
        else       v = w[(size_t)(o - O) * (2 * C) + C + c];
        g_wtmp[i] = v;
    }
}

// ----------------------- layer-1 hh (K=3 feature GEMM) ---------------------
__global__ void hh3_kernel(const float* __restrict__ X) {
    __shared__ float w[3 * 128];
    int row = blockIdx.x;
    int t = threadIdx.x;   // 128
    w[t] = g_wtmp[t]; w[128 + t] = g_wtmp[128 + t]; w[256 + t] = g_wtmp[256 + t];
    __syncthreads();
    float x0 = X[row * 3], x1 = X[row * 3 + 1], x2 = X[row * 3 + 2];
    g_hh[(size_t)row * 128 + t] = x0 * w[t] + x1 * w[128 + t] + x2 * w[256 + t];
}

// ------------------------------ stats zero ---------------------------------
__global__ void zero_stats() { g_stats[threadIdx.x] = 0.0; }

// --------------------------- edge GN stats pass -----------------------------
__global__ __launch_bounds__(256) void edge_stats_kernel(int O) {
    __shared__ int   sidx[KNN];
    __shared__ float ps[256], pq[256];
    int row = blockIdx.x;
    int b = row >> 11;
    int t = threadIdx.x;
    if (t < KNN) sidx[t] = g_idx[(size_t)row * KNN + t];
    __syncthreads();
    int twoO = 2 * O;
    int c = t % O;
    int k0 = t / O;
    int kstep = 256 / O;
    float hcv = g_hh[(size_t)row * twoO + c];
    size_t bbase = ((size_t)(b << 11)) * twoO + O + c;
    float s = 0.f, q = 0.f;
    for (int k = k0; k < KNN; k += kstep) {
        float h = hcv + g_hh[bbase + (size_t)sidx[k] * twoO];
        s += h; q += h * h;
    }
    ps[t] = s; pq[t] = q;
    __syncthreads();
    int gs = O / 4;
    if (t < 4) {
        double S = 0.0, Q = 0.0;
        for (int j = 0; j < 256; j++) {
            if ((j % O) / gs == t) { S += ps[j]; Q += pq[j]; }
        }
        atomicAdd(&g_stats[((b * 4) + t) * 2 + 0], S);
        atomicAdd(&g_stats[((b * 4) + t) * 2 + 1], Q);
    }
}

// -------------------------- finalize GN statistics --------------------------
__global__ void finalize_stats(int ngroups, double cnt) {
    int i = threadIdx.x;
    if (i < NB * ngroups) {
        double s = g_stats[i * 2 + 0], q = g_stats[i * 2 + 1];
        double mu = s / cnt;
        double var = q / cnt - mu * mu;
        g_mu[i] = (float)mu;
        g_rs[i] = rsqrtf((float)var + 1e-5f);
    }
}

// ----------------------- edge normalize + leaky + max-k ---------------------
__global__ void edge_normmax_kernel(int O, int coff,
                                    const float* __restrict__ gw,
                                    const float* __restrict__ gb) {
    __shared__ int sidx[KNN];
    int row = blockIdx.x;
    int b = row >> 11;
    int t = threadIdx.x;                 // blockDim == O
    if (t < KNN) sidx[t] = g_idx[(size_t)row * KNN + t];
    __syncthreads();
    int c = t;
    int twoO = 2 * O;
    float hcv = g_hh[(size_t)row * twoO + c];
    int g = c / (O / 4);
    float mu = g_mu[b * 4 + g], rs = g_rs[b * 4 + g];
    float w = gw[c], bb = gb[c];
    size_t bbase = ((size_t)(b << 11)) * twoO + O + c;
    float m = -3.4e38f;
#pragma unroll
    for (int k = 0; k < KNN; k++) {
        float h = hcv + g_hh[bbase + (size_t)sidx[k] * twoO];
        float v = (h - mu) * rs * w + bb;
        m = fmaxf(m, leaky02(v));
    }
    g_concat[(size_t)row * 512 + coff + c] = m;
}

// ------------------------------ seq GN stats --------------------------------
__global__ __launch_bounds__(256) void seq_stats_kernel() {
    __shared__ float ps[256], pq[256];
    int row = blockIdx.x;
    int b = row >> 11;
    int t = threadIdx.x;
    const float* hr = g_hm + (size_t)row * 1024;
    float s = 0.f, q = 0.f;
#pragma unroll
    for (int j = 0; j < 4; j++) { float v = hr[t * 4 + j]; s += v; q += v * v; }
    ps[t] = s; pq[t] = q;
    __syncthreads();
    if (t < 16) {
        double S = 0.0, Q = 0.0;
        for (int j = t * 16; j < t * 16 + 16; j++) { S += ps[j]; Q += pq[j]; }
        atomicAdd(&g_stats[(b * 16 + t) * 2 + 0], S);
        atomicAdd(&g_stats[(b * 16 + t) * 2 + 1], Q);
    }
}

// ------------------- seq normalize + leaky + max over N ---------------------
__global__ __launch_bounds__(256) void seq_max_kernel(const float* __restrict__ gmw,
                                                      const float* __restrict__ gmb) {
    int c = blockIdx.x * 256 + threadIdx.x;
    int b = blockIdx.y;
    int g = c >> 6;
    float mu = g_mu[b * 16 + g], rs = g_rs[b * 16 + g];
    float w = gmw[c], bb = gmb[c];
    const float* col = g_hm + ((size_t)b * NPTS) * 1024 + c;
    float m = -3.4e38f;
    for (int n = 0; n < NPTS; n++) {
        float v = (col[(size_t)n * 1024] - mu) * rs * w + bb;
        m = fmaxf(m, leaky02(v));
    }
    g_gvec[b * 1024 + c] = m;
}

// --------------------------------- MLP head ---------------------------------
__device__ __forceinline__ float bsum256(float v, float* red, int t) {
    red[t] = v; __syncthreads();
    for (int s = 128; s > 0; s >>= 1) {
        if (t < s) red[t] += red[t + s];
        __syncthreads();
    }
    float r = red[0]; __syncthreads();
    return r;
}

__device__ __forceinline__ void ln_leaky(float* buf, int L,
                                         const float* __restrict__ w,
                                         const float* __restrict__ b,
                                         float* red, int t) {
    float s = 0.f, q = 0.f;
    for (int i = t; i < L; i += 256) { float v = buf[i]; s += v; q += v * v; }
    float S = bsum256(s, red, t);
    float Q = bsum256(q, red, t);
    float mu = S / (float)L;
    float var = Q / (float)L - mu * mu;
    float rs = rsqrtf(var + 1e-5f);
    for (int i = t; i < L; i += 256) {
        float v = (buf[i] - mu) * rs * w[i] + b[i];
        buf[i] = leaky02(v);
    }
    __syncthreads();
}

__global__ __launch_bounds__(256) void mlp_kernel(
    const float* __restrict__ fc1w, const float* __restrict__ fc1b,
    const float* __restrict__ ln1w, const float* __restrict__ ln1b,
    const float* __restrict__ fc2w, const float* __restrict__ fc2b,
    const float* __restrict__ ln2w, const float* __restrict__ ln2b,
    const float* __restrict__ fc3w, const float* __restrict__ fc3b,
    const float* __restrict__ ln3w, const float* __restrict__ ln3b,
    const float* __restrict__ fc4w, const float* __restrict__ fc4b,
    float* __restrict__ out)
{
    __shared__ __align__(16) float sin_[1024];
    __shared__ __align__(16) float t1[512];
    __shared__ __align__(16) float t2[256];
    __shared__ __align__(16) float t3[64];
    __shared__ float red[256];
    int b = blockIdx.x, t = threadIdx.x;
    for (int i = t; i < 1024; i += 256) sin_[i] = g_gvec[b * 1024 + i];
    __syncthreads();
    for (int o = t; o < 512; o += 256) {
        float acc = fc1b[o];
        const float4* wr = (const float4*)(fc1w + (size_t)o * 1024);
        const float4* xr = (const float4*)sin_;
        for (int c = 0; c < 256; c++) {
            float4 w4 = wr[c], x4 = xr[c];
            acc += w4.x * x4.x + w4.y * x4.y + w4.z * x4.z + w4.w * x4.w;
        }
        t1[o] = acc;
    }
    __syncthreads();
    ln_leaky(t1, 512, ln1w, ln1b, red, t);
    if (t < 256) {
        float acc = fc2b[t];
        const float4* wr = (const float4*)(fc2w + (size_t)t * 512);
        const float4* xr = (const float4*)t1;
        for (int c = 0; c < 128; c++) {
            float4 w4 = wr[c], x4 = xr[c];
            acc += w4.x * x4.x + w4.y * x4.y + w4.z * x4.z + w4.w * x4.w;
        }
        t2[t] = acc;
    }
    __syncthreads();
    ln_leaky(t2, 256, ln2w, ln2b, red, t);
    if (t < 64) {
        float acc = fc3b[t];
        const float4* wr = (const float4*)(fc3w + (size_t)t * 256);
        const float4* xr = (const float4*)t2;
        for (int c = 0; c < 64; c++) {
            float4 w4 = wr[c], x4 = xr[c];
            acc += w4.x * x4.x + w4.y * x4.y + w4.z * x4.z + w4.w * x4.w;
        }
        t3[t] = acc;
    }
    __syncthreads();
    ln_leaky(t3, 64, ln3w, ln3b, red, t);
    if (t < 2) {
        float acc = fc4b[t];
        for (int c = 0; c < 64; c++) acc += fc4w[t * 64 + c] * t3[c];
        out[b * 2 + t] = acc;
    }
}

// =============================== host driver ================================
extern "C" void kernel_launch(void* const* d_in, const int* in_sizes, int n_in,
                              void* d_out, int out_size)
{
    const float* x    = (const float*)d_in[0];
    const float* w1   = (const float*)d_in[1];
    const float* g1w  = (const float*)d_in[2];
    const float* g1b  = (const float*)d_in[3];
    const float* w2   = (const float*)d_in[4];
    const float* g2w  = (const float*)d_in[5];
    const float* g2b  = (const float*)d_in[6];
    const float* w3   = (const float*)d_in[7];
    const float* g3w  = (const float*)d_in[8];
    const float* g3b  = (const float*)d_in[9];
    const float* w4   = (const float*)d_in[10];
    const float* g4w  = (const float*)d_in[11];
    const float* g4b  = (const float*)d_in[12];
    const float* wm   = (const float*)d_in[13];
    const float* gmw  = (const float*)d_in[14];
    const float* gmb  = (const float*)d_in[15];
    const float* fc1w = (const float*)d_in[16];
    const float* fc1b = (const float*)d_in[17];
    const float* ln1w = (const float*)d_in[18];
    const float* ln1b = (const float*)d_in[19];
    const float* fc2w = (const float*)d_in[20];
    const float* fc2b = (const float*)d_in[21];
    const float* ln2w = (const float*)d_in[22];
    const float* ln2b = (const float*)d_in[23];
    const float* fc3w = (const float*)d_in[24];
    const float* fc3b = (const float*)d_in[25];
    const float* ln3w = (const float*)d_in[26];
    const float* ln3b = (const float*)d_in[27];
    const float* fc4w = (const float*)d_in[28];
    const float* fc4b = (const float*)d_in[29];
    float* out = (float*)d_out;

    float *pGram, *pConcat, *pHH, *pHm, *pWtmp;
    cudaGetSymbolAddress((void**)&pGram,   g_gram);
    cudaGetSymbolAddress((void**)&pConcat, g_concat);
    cudaGetSymbolAddress((void**)&pHH,     g_hh);
    cudaGetSymbolAddress((void**)&pHm,     g_hm);
    cudaGetSymbolAddress((void**)&pWtmp,   g_wtmp);

    // ---------------- layer 1 (C=3, O=64): fused knn, tiny feature GEMM ----
    sq_kernel<<<(NROWS + 255) / 256, 256>>>(x, 3, 3);
    select3_kernel<<<NROWS, 256>>>(x);
    wtmp_kernel<<<(3 * 128 + 255) / 256, 256>>>(w1, 3, 64);
    hh3_kernel<<<NROWS, 128>>>(x);
    zero_stats<<<1, 256>>>();
    edge_stats_kernel<<<NROWS, 256>>>(64);
    finalize_stats<<<1, 128>>>(4, (double)NPTS * KNN * 16);
    edge_normmax_kernel<<<NROWS, 64>>>(64, 0, g1w, g1b);

    // ---------------- layers 2-4 ------------------------------------------
    struct LayerCfg {
        const float* X; int C; int O;
        const float* w; const float* gw; const float* gb; int coff;
    };
    LayerCfg layers[3] = {
        { pConcat + 0,   64,  64,  w2, g2w, g2b, 64  },
        { pConcat + 64,  64,  128, w3, g3w, g3b, 128 },
        { pConcat + 128, 128, 256, w4, g4w, g4b, 256 },
    };

    for (int l = 0; l < 3; l++) {
        const LayerCfg& L = layers[l];
        sq_kernel<<<(NROWS + 255) / 256, 256>>>(L.X, 512, L.C);
        // per-batch Gram (M=N=2048)
        sgemm128<true><<<dim3(NPTS / 128, NPTS / 128, NB), 256>>>(
            L.X, 512, (size_t)NPTS * 512,
            L.X, 512, (size_t)NPTS * 512,
            pGram, NPTS, (size_t)NPTS * NPTS, L.C);
        select_kernel<<<NROWS, 256>>>();
        wtmp_kernel<<<(L.C * 2 * L.O + 255) / 256, 256>>>(L.w, L.C, L.O);
        sgemm128<false><<<dim3(2 * L.O / 128, NROWS / 128, 1), 256>>>(
            L.X, 512, 0,
            pWtmp, 2 * L.O, 0,
            pHH, 2 * L.O, 0, L.C);
        zero_stats<<<1, 256>>>();
        edge_stats_kernel<<<NROWS, 256>>>(L.O);
        finalize_stats<<<1, 128>>>(4, (double)NPTS * KNN * (L.O / 4));
        edge_normmax_kernel<<<NROWS, L.O>>>(L.O, L.coff, L.gw, L.gb);
    }

    // mid: hm = concat @ wm^T  (16384 x 512 -> 1024)
    sgemm128<true><<<dim3(1024 / 128, NROWS / 128, 1), 256>>>(
        pConcat, 512, 0, wm, 512, 0, pHm, 1024, 0, 512);
    zero_stats<<<1, 256>>>();
    seq_stats_kernel<<<NROWS, 256>>>();
    finalize_stats<<<1, 128>>>(16, (double)NPTS * 64);
    seq_max_kernel<<<dim3(4, NB), 256>>>(gmw, gmb);

    // head MLP
    mlp_kernel<<<NB, 256>>>(fc1w, fc1b, ln1w, ln1b,
                            fc2w, fc2b, ln2w, ln2b,
                            fc3w, fc3b, ln3w, ln3b,
                            fc4w, fc4b, out);
}

// round 3
// speedup vs baseline: 3.2014x; 3.0895x over previous
#include <cuda_runtime.h>
#include <cuda_bf16.h>
#include <cstdint>
#include <cstddef>

// ---------------------------------------------------------------------------
// DGCNN pipeline, fp32. B=8, N=2048, K=20.
// Round 3: no contended global atomics (partial-store + reduce kernels),
// warp-per-query barrier-free top-20 select, parallelized seq max.
// ---------------------------------------------------------------------------

#define NPTS   2048
#define NB     8
#define NROWS  (NB*NPTS)   // 16384
#define KNN    20
#define FINF   3.4e38f

// ------------------------- device scratch (no allocs) ----------------------
__device__ float  g_gram[(size_t)NB * NPTS * NPTS];   // reused per layer
__device__ float  g_hh[(size_t)NROWS * 512];          // [rows x 2O], hc | hn
__device__ float  g_concat[(size_t)NROWS * 512];      // x1|x2|x3|x4
__device__ float  g_hm[(size_t)NROWS * 1024];         // seq features
__device__ float  g_sq[NROWS];
__device__ int    g_idx[(size_t)NROWS * KNN];
__device__ float  g_wtmp[128 * 512];                  // transformed weights (C x 2O)
__device__ float  g_part[(size_t)NROWS * 32];         // per-row group partials
__device__ float  g_mu[128];
__device__ float  g_rs[128];
__device__ float  g_pmax[NB * 8 * 1024];              // seq max partials
__device__ float  g_gvec[NB * 1024];

__device__ __forceinline__ float leaky02(float v) { return v > 0.f ? v : 0.2f * v; }

// ------------------------------ sq kernel ----------------------------------
__global__ void sq_kernel(const float* __restrict__ X, int ldx, int C) {
    int r = blockIdx.x * 256 + threadIdx.x;
    if (r < NROWS) {
        float s = 0.f;
        const float* xp = X + (size_t)r * ldx;
        for (int c = 0; c < C; c++) { float v = xp[c]; s += v * v; }
        g_sq[r] = s;
    }
}

// ----------------- 128x128x8 double-buffered SGEMM (8x8/thread) ------------
template <bool TRANSB>
__global__ __launch_bounds__(256, 2) void sgemm128(
    const float* __restrict__ A, int lda, size_t sA,
    const float* __restrict__ Bp, int ldb, size_t sB,
    float* __restrict__ Cp, int ldc, size_t sC, int K)
{
    __shared__ __align__(16) float As[2][8][132];
    __shared__ __align__(16) float Bs[2][8][132];
    const float* Ab = A  + (size_t)blockIdx.z * sA;
    const float* Bb = Bp + (size_t)blockIdx.z * sB;
    float*       Cb = Cp + (size_t)blockIdx.z * sC;
    const int m0 = blockIdx.y * 128, n0 = blockIdx.x * 128;
    const int tid = threadIdx.x;
    const int tx = tid & 15, ty = tid >> 4;
    const int ma = tid >> 1;
    const int ka = (tid & 1) * 4;
    const int kb = tid >> 5;
    const int nb = (tid & 31) * 4;

    float acc[8][8] = {};
    const int nk = K >> 3;
    float4 va, vb;

    va = *(const float4*)&Ab[(size_t)(m0 + ma) * lda + ka];
    if (TRANSB) vb = *(const float4*)&Bb[(size_t)(n0 + ma) * ldb + ka];
    else        vb = *(const float4*)&Bb[(size_t)kb * ldb + n0 + nb];
    As[0][ka+0][ma] = va.x; As[0][ka+1][ma] = va.y;
    As[0][ka+2][ma] = va.z; As[0][ka+3][ma] = va.w;
    if (TRANSB) {
        Bs[0][ka+0][ma] = vb.x; Bs[0][ka+1][ma] = vb.y;
        Bs[0][ka+2][ma] = vb.z; Bs[0][ka+3][ma] = vb.w;
    } else {
        *(float4*)&Bs[0][kb][nb] = vb;
    }
    __syncthreads();

    for (int kc = 0; kc < nk; kc++) {
        const int buf = kc & 1;
        if (kc + 1 < nk) {
            const int k0 = (kc + 1) << 3;
            va = *(const float4*)&Ab[(size_t)(m0 + ma) * lda + k0 + ka];
            if (TRANSB) vb = *(const float4*)&Bb[(size_t)(n0 + ma) * ldb + k0 + ka];
            else        vb = *(const float4*)&Bb[(size_t)(k0 + kb) * ldb + n0 + nb];
        }
#pragma unroll
        for (int kk = 0; kk < 8; kk++) {
            float a[8], b[8];
            *(float4*)&a[0] = *(const float4*)&As[buf][kk][ty * 4];
            *(float4*)&a[4] = *(const float4*)&As[buf][kk][64 + ty * 4];
            *(float4*)&b[0] = *(const float4*)&Bs[buf][kk][tx * 4];
            *(float4*)&b[4] = *(const float4*)&Bs[buf][kk][64 + tx * 4];
#pragma unroll
            for (int i = 0; i < 8; i++)
#pragma unroll
                for (int j = 0; j < 8; j++) acc[i][j] += a[i] * b[j];
        }
        if (kc + 1 < nk) {
            const int nbuf = buf ^ 1;
            As[nbuf][ka+0][ma] = va.x; As[nbuf][ka+1][ma] = va.y;
            As[nbuf][ka+2][ma] = va.z; As[nbuf][ka+3][ma] = va.w;
            if (TRANSB) {
                Bs[nbuf][ka+0][ma] = vb.x; Bs[nbuf][ka+1][ma] = vb.y;
                Bs[nbuf][ka+2][ma] = vb.z; Bs[nbuf][ka+3][ma] = vb.w;
            } else {
                *(float4*)&Bs[nbuf][kb][nb] = vb;
            }
        }
        __syncthreads();
    }

#pragma unroll
    for (int i = 0; i < 8; i++) {
        const int mrow = m0 + ((i < 4) ? (ty * 4 + i) : (64 + ty * 4 + i - 4));
        float* Cr = &Cb[(size_t)mrow * ldc + n0];
        *(float4*)(Cr + tx * 4)      = make_float4(acc[i][0], acc[i][1], acc[i][2], acc[i][3]);
        *(float4*)(Cr + 64 + tx * 4) = make_float4(acc[i][4], acc[i][5], acc[i][6], acc[i][7]);
    }
}

// -------------------- warp-per-query top-20 select core ---------------------
// sd: this warp's 2048 distances in smem (lane L owns m = L + 32j).
// Per-lane running (bv,bi); 20 iterations of shfl-butterfly argmin +
// cooperative rescan of the winner lane's 64-element segment. No barriers.
__device__ __forceinline__ void topk_from_smem(float* sd, int row, int lane,
                                               float bv, int bi) {
#pragma unroll 1
    for (int it = 0; it < KNN; it++) {
        float v = bv; int idx = bi;
#pragma unroll
        for (int off = 16; off > 0; off >>= 1) {
            float v2 = __shfl_xor_sync(0xffffffffu, v, off);
            int   i2 = __shfl_xor_sync(0xffffffffu, idx, off);
            if (v2 < v || (v2 == v && i2 < idx)) { v = v2; idx = i2; }
        }
        if (lane == 0) g_idx[(size_t)row * KNN + it] = idx;
        int wl = idx & 31;
        if (lane == 0) sd[idx] = FINF;
        __syncwarp();
        // cooperative rescan of lane wl's segment: lane i covers j=2i,2i+1
        float rv = FINF; int rb = 0x7fffffff;
#pragma unroll
        for (int q = 0; q < 2; q++) {
            int m = wl + 32 * (2 * lane + q);
            float d = sd[m];
            if (d < rv || (d == rv && m < rb)) { rv = d; rb = m; }
        }
#pragma unroll
        for (int off = 16; off > 0; off >>= 1) {
            float v2 = __shfl_xor_sync(0xffffffffu, rv, off);
            int   i2 = __shfl_xor_sync(0xffffffffu, rb, off);
            if (v2 < rv || (v2 == rv && i2 < rb)) { rv = v2; rb = i2; }
        }
        if (lane == wl) { bv = rv; bi = rb; }
    }
}

// layers 2-4: distances from precomputed gram row
__global__ __launch_bounds__(128) void select_gram_kernel() {
    __shared__ float sd[4][NPTS];   // 32KB
    int warp = threadIdx.x >> 5, lane = threadIdx.x & 31;
    int row = blockIdx.x * 4 + warp;
    int b = row >> 11, n = row & 2047;
    const float* drow = g_gram + (size_t)b * NPTS * NPTS + (size_t)n * NPTS;
    float sqn = g_sq[row];
    float* sdw = sd[warp];
    float bv = FINF; int bi = 0x7fffffff;
#pragma unroll 8
    for (int j = 0; j < 64; j++) {
        int m = lane + 32 * j;
        float d = sqn + g_sq[(b << 11) + m] - 2.f * drow[m];
        if (m == n) d = FINF;
        sdw[m] = d;
        if (d < bv || (d == bv && m < bi)) { bv = d; bi = m; }
    }
    __syncwarp();
    topk_from_smem(sdw, row, lane, bv, bi);
}

// layer 1: distances computed from 3D points on the fly
__global__ __launch_bounds__(128) void select3_kernel(const float* __restrict__ X) {
    __shared__ float sd[4][NPTS];
    int warp = threadIdx.x >> 5, lane = threadIdx.x & 31;
    int row = blockIdx.x * 4 + warp;
    int b = row >> 11, n = row & 2047;
    const float* Xb = X + (size_t)(b << 11) * 3;
    float xn = Xb[n * 3], yn = Xb[n * 3 + 1], zn = Xb[n * 3 + 2];
    float sqn = g_sq[row];
    float* sdw = sd[warp];
    float bv = FINF; int bi = 0x7fffffff;
#pragma unroll 4
    for (int j = 0; j < 64; j++) {
        int m = lane + 32 * j;
        float px = Xb[m * 3], py = Xb[m * 3 + 1], pz = Xb[m * 3 + 2];
        float dot = xn * px + yn * py + zn * pz;
        float d = sqn + g_sq[(b << 11) + m] - 2.f * dot;
        if (m == n) d = FINF;
        sdw[m] = d;
        if (d < bv || (d == bv && m < bi)) { bv = d; bi = m; }
    }
    __syncwarp();
    topk_from_smem(sdw, row, lane, bv, bi);
}

// --------------------------- weight transform ------------------------------
__global__ void wtmp_kernel(const float* __restrict__ w, int C, int O) {
    int i = blockIdx.x * 256 + threadIdx.x;
    int tot = C * 2 * O;
    if (i < tot) {
        int c = i / (2 * O);
        int o = i % (2 * O);
        float v;
        if (o < O) v = w[(size_t)o * (2 * C) + c] - w[(size_t)o * (2 * C) + C + c];
        else       v = w[(size_t)(o - O) * (2 * C) + C + c];
        g_wtmp[i] = v;
    }
}

// ----------------------- layer-1 hh (K=3 feature GEMM) ---------------------
__global__ void hh3_kernel(const float* __restrict__ X) {
    __shared__ float w[3 * 128];
    int row = blockIdx.x;
    int t = threadIdx.x;   // 128
    w[t] = g_wtmp[t]; w[128 + t] = g_wtmp[128 + t]; w[256 + t] = g_wtmp[256 + t];
    __syncthreads();
    float x0 = X[row * 3], x1 = X[row * 3 + 1], x2 = X[row * 3 + 2];
    g_hh[(size_t)row * 128 + t] = x0 * w[t] + x1 * w[128 + t] + x2 * w[256 + t];
}

// --------------------------- edge GN stats pass -----------------------------
// partial sums per (block=row, group) -> g_part[row*8 + g*2 + {0,1}]
__global__ __launch_bounds__(256) void edge_stats_kernel(int O) {
    __shared__ int   sidx[KNN];
    __shared__ float sacc[8];
    int row = blockIdx.x;
    int b = row >> 11;
    int t = threadIdx.x;
    if (t < KNN) sidx[t] = g_idx[(size_t)row * KNN + t];
    if (t < 8) sacc[t] = 0.f;
    __syncthreads();
    int twoO = 2 * O;
    int c = t % O;
    int k0 = t / O;
    int kstep = 256 / O;
    float hcv = g_hh[(size_t)row * twoO + c];
    size_t bbase = ((size_t)(b << 11)) * twoO + O + c;
    float s = 0.f, q = 0.f;
    for (int k = k0; k < KNN; k += kstep) {
        float h = hcv + g_hh[bbase + (size_t)sidx[k] * twoO];
        s += h; q += h * h;
    }
    int g = c / (O / 4);
    atomicAdd(&sacc[g * 2 + 0], s);
    atomicAdd(&sacc[g * 2 + 1], q);
    __syncthreads();
    if (t < 8) g_part[(size_t)row * 8 + t] = sacc[t];
}

// ------------------- cross-block stats reduce (edge & seq) ------------------
// grid (ngroups, NB); sums g_part[row*perrow + g*2 + {0,1}] over 2048 rows.
__global__ __launch_bounds__(256) void stats_reduce_kernel(int perrow, int ngroups,
                                                           float cnt) {
    __shared__ double ds[256], dq[256];
    int g = blockIdx.x, b = blockIdx.y, t = threadIdx.x;
    double s = 0.0, q = 0.0;
    for (int r = t; r < NPTS; r += 256) {
        size_t base = ((size_t)((b << 11) + r)) * perrow + g * 2;
        s += (double)g_part[base];
        q += (double)g_part[base + 1];
    }
    ds[t] = s; dq[t] = q;
    __syncthreads();
    for (int st = 128; st > 0; st >>= 1) {
        if (t < st) { ds[t] += ds[t + st]; dq[t] += dq[t + st]; }
        __syncthreads();
    }
    if (t == 0) {
        double mu = ds[0] / (double)cnt;
        double var = dq[0] / (double)cnt - mu * mu;
        g_mu[b * ngroups + g] = (float)mu;
        g_rs[b * ngroups + g] = rsqrtf((float)var + 1e-5f);
    }
}

// ----------------------- edge normalize + leaky + max-k ---------------------
__global__ void edge_normmax_kernel(int O, int coff,
                                    const float* __restrict__ gw,
                                    const float* __restrict__ gb) {
    __shared__ int sidx[KNN];
    int row = blockIdx.x;
    int b = row >> 11;
    int t = threadIdx.x;                 // blockDim == O
    if (t < KNN) sidx[t] = g_idx[(size_t)row * KNN + t];
    __syncthreads();
    int c = t;
    int twoO = 2 * O;
    float hcv = g_hh[(size_t)row * twoO + c];
    int g = c / (O / 4);
    float mu = g_mu[b * 4 + g], rs = g_rs[b * 4 + g];
    float w = gw[c], bb = gb[c];
    size_t bbase = ((size_t)(b << 11)) * twoO + O + c;
    float m = -FINF;
#pragma unroll
    for (int k = 0; k < KNN; k++) {
        float h = hcv + g_hh[bbase + (size_t)sidx[k] * twoO];
        float v = (h - mu) * rs * w + bb;
        m = fmaxf(m, leaky02(v));
    }
    g_concat[(size_t)row * 512 + coff + c] = m;
}

// ------------------------------ seq GN stats --------------------------------
// partials per (row, 16 groups) -> g_part[row*32 + g*2 + {0,1}]
__global__ __launch_bounds__(256) void seq_stats_kernel() {
    __shared__ float sacc[32];
    int row = blockIdx.x;
    int t = threadIdx.x;
    if (t < 32) sacc[t] = 0.f;
    __syncthreads();
    const float* hr = g_hm + (size_t)row * 1024;
    float s = 0.f, q = 0.f;
#pragma unroll
    for (int j = 0; j < 4; j++) { float v = hr[t * 4 + j]; s += v; q += v * v; }
    int g = t >> 4;
    atomicAdd(&sacc[g * 2 + 0], s);
    atomicAdd(&sacc[g * 2 + 1], q);
    __syncthreads();
    if (t < 32) g_part[(size_t)row * 32 + t] = sacc[t];
}

// ------------------- seq normalize + leaky + max over N ---------------------
__global__ __launch_bounds__(256) void seq_max_part(const float* __restrict__ gmw,
                                                    const float* __restrict__ gmb) {
    int c = blockIdx.x * 256 + threadIdx.x;
    int b = blockIdx.y;
    int z = blockIdx.z;                  // N chunk
    int g = c >> 6;
    float mu = g_mu[b * 16 + g], rs = g_rs[b * 16 + g];
    float w = gmw[c], bb = gmb[c];
    const float* col = g_hm + ((size_t)b * NPTS + z * 256) * 1024 + c;
    float m = -FINF;
#pragma unroll 4
    for (int n = 0; n < 256; n++) {
        float v = (col[(size_t)n * 1024] - mu) * rs * w + bb;
        m = fmaxf(m, leaky02(v));
    }
    g_pmax[((size_t)b * 8 + z) * 1024 + c] = m;
}

__global__ __launch_bounds__(256) void seq_max_combine() {
    int c = blockIdx.x * 256 + threadIdx.x;
    int b = blockIdx.y;
    float m = -FINF;
#pragma unroll
    for (int z = 0; z < 8; z++)
        m = fmaxf(m, g_pmax[((size_t)b * 8 + z) * 1024 + c]);
    g_gvec[b * 1024 + c] = m;
}

// --------------------------------- MLP head ---------------------------------
__device__ __forceinline__ float bsum256(float v, float* red, int t) {
    red[t] = v; __syncthreads();
    for (int s = 128; s > 0; s >>= 1) {
        if (t < s) red[t] += red[t + s];
        __syncthreads();
    }
    float r = red[0]; __syncthreads();
    return r;
}

__device__ __forceinline__ void ln_leaky(float* buf, int L,
                                         const float* __restrict__ w,
                                         const float* __restrict__ b,
                                         float* red, int t) {
    float s = 0.f, q = 0.f;
    for (int i = t; i < L; i += 256) { float v = buf[i]; s += v; q += v * v; }
    float S = bsum256(s, red, t);
    float Q = bsum256(q, red, t);
    float mu = S / (float)L;
    float var = Q / (float)L - mu * mu;
    float rs = rsqrtf(var + 1e-5f);
    for (int i = t; i < L; i += 256) {
        float v = (buf[i] - mu) * rs * w[i] + b[i];
        buf[i] = leaky02(v);
    }
    __syncthreads();
}

__global__ __launch_bounds__(256) void mlp_kernel(
    const float* __restrict__ fc1w, const float* __restrict__ fc1b,
    const float* __restrict__ ln1w, const float* __restrict__ ln1b,
    const float* __restrict__ fc2w, const float* __restrict__ fc2b,
    const float* __restrict__ ln2w, const float* __restrict__ ln2b,
    const float* __restrict__ fc3w, const float* __restrict__ fc3b,
    const float* __restrict__ ln3w, const float* __restrict__ ln3b,
    const float* __restrict__ fc4w, const float* __restrict__ fc4b,
    float* __restrict__ out)
{
    __shared__ __align__(16) float sin_[1024];
    __shared__ __align__(16) float t1[512];
    __shared__ __align__(16) float t2[256];
    __shared__ __align__(16) float t3[64];
    __shared__ float red[256];
    int b = blockIdx.x, t = threadIdx.x;
    for (int i = t; i < 1024; i += 256) sin_[i] = g_gvec[b * 1024 + i];
    __syncthreads();
    for (int o = t; o < 512; o += 256) {
        float acc = fc1b[o];
        const float4* wr = (const float4*)(fc1w + (size_t)o * 1024);
        const float4* xr = (const float4*)sin_;
        for (int c = 0; c < 256; c++) {
            float4 w4 = wr[c], x4 = xr[c];
            acc += w4.x * x4.x + w4.y * x4.y + w4.z * x4.z + w4.w * x4.w;
        }
        t1[o] = acc;
    }
    __syncthreads();
    ln_leaky(t1, 512, ln1w, ln1b, red, t);
    if (t < 256) {
        float acc = fc2b[t];
        const float4* wr = (const float4*)(fc2w + (size_t)t * 512);
        const float4* xr = (const float4*)t1;
        for (int c = 0; c < 128; c++) {
            float4 w4 = wr[c], x4 = xr[c];
            acc += w4.x * x4.x + w4.y * x4.y + w4.z * x4.z + w4.w * x4.w;
        }
        t2[t] = acc;
    }
    __syncthreads();
    ln_leaky(t2, 256, ln2w, ln2b, red, t);
    if (t < 64) {
        float acc = fc3b[t];
        const float4* wr = (const float4*)(fc3w + (size_t)t * 256);
        const float4* xr = (const float4*)t2;
        for (int c = 0; c < 64; c++) {
            float4 w4 = wr[c], x4 = xr[c];
            acc += w4.x * x4.x + w4.y * x4.y + w4.z * x4.z + w4.w * x4.w;
        }
        t3[t] = acc;
    }
    __syncthreads();
    ln_leaky(t3, 64, ln3w, ln3b, red, t);
    if (t < 2) {
        float acc = fc4b[t];
        for (int c = 0; c < 64; c++) acc += fc4w[t * 64 + c] * t3[c];
        out[b * 2 + t] = acc;
    }
}

// =============================== host driver ================================
extern "C" void kernel_launch(void* const* d_in, const int* in_sizes, int n_in,
                              void* d_out, int out_size)
{
    const float* x    = (const float*)d_in[0];
    const float* w1   = (const float*)d_in[1];
    const float* g1w  = (const float*)d_in[2];
    const float* g1b  = (const float*)d_in[3];
    const float* w2   = (const float*)d_in[4];
    const float* g2w  = (const float*)d_in[5];
    const float* g2b  = (const float*)d_in[6];
    const float* w3   = (const float*)d_in[7];
    const float* g3w  = (const float*)d_in[8];
    const float* g3b  = (const float*)d_in[9];
    const float* w4   = (const float*)d_in[10];
    const float* g4w  = (const float*)d_in[11];
    const float* g4b  = (const float*)d_in[12];
    const float* wm   = (const float*)d_in[13];
    const float* gmw  = (const float*)d_in[14];
    const float* gmb  = (const float*)d_in[15];
    const float* fc1w = (const float*)d_in[16];
    const float* fc1b = (const float*)d_in[17];
    const float* ln1w = (const float*)d_in[18];
    const float* ln1b = (const float*)d_in[19];
    const float* fc2w = (const float*)d_in[20];
    const float* fc2b = (const float*)d_in[21];
    const float* ln2w = (const float*)d_in[22];
    const float* ln2b = (const float*)d_in[23];
    const float* fc3w = (const float*)d_in[24];
    const float* fc3b = (const float*)d_in[25];
    const float* ln3w = (const float*)d_in[26];
    const float* ln3b = (const float*)d_in[27];
    const float* fc4w = (const float*)d_in[28];
    const float* fc4b = (const float*)d_in[29];
    float* out = (float*)d_out;

    float *pGram, *pConcat, *pHH, *pHm, *pWtmp;
    cudaGetSymbolAddress((void**)&pGram,   g_gram);
    cudaGetSymbolAddress((void**)&pConcat, g_concat);
    cudaGetSymbolAddress((void**)&pHH,     g_hh);
    cudaGetSymbolAddress((void**)&pHm,     g_hm);
    cudaGetSymbolAddress((void**)&pWtmp,   g_wtmp);

    // ---------------- layer 1 (C=3, O=64) ----------------------------------
    sq_kernel<<<(NROWS + 255) / 256, 256>>>(x, 3, 3);
    wtmp_kernel<<<(3 * 128 + 255) / 256, 256>>>(w1, 3, 64);
    hh3_kernel<<<NROWS, 128>>>(x);
    select3_kernel<<<NROWS / 4, 128>>>(x);
    edge_stats_kernel<<<NROWS, 256>>>(64);
    stats_reduce_kernel<<<dim3(4, NB), 256>>>(8, 4, (float)(NPTS * KNN * 16));
    edge_normmax_kernel<<<NROWS, 64>>>(64, 0, g1w, g1b);

    // ---------------- layers 2-4 ------------------------------------------
    struct LayerCfg {
        const float* X; int C; int O;
        const float* w; const float* gw; const float* gb; int coff;
    };
    LayerCfg layers[3] = {
        { pConcat + 0,   64,  64,  w2, g2w, g2b, 64  },
        { pConcat + 64,  64,  128, w3, g3w, g3b, 128 },
        { pConcat + 128, 128, 256, w4, g4w, g4b, 256 },
    };

    for (int l = 0; l < 3; l++) {
        const LayerCfg& L = layers[l];
        sq_kernel<<<(NROWS + 255) / 256, 256>>>(L.X, 512, L.C);
        sgemm128<true><<<dim3(NPTS / 128, NPTS / 128, NB), 256>>>(
            L.X, 512, (size_t)NPTS * 512,
            L.X, 512, (size_t)NPTS * 512,
            pGram, NPTS, (size_t)NPTS * NPTS, L.C);
        select_gram_kernel<<<NROWS / 4, 128>>>();
        wtmp_kernel<<<(L.C * 2 * L.O + 255) / 256, 256>>>(L.w, L.C, L.O);
        sgemm128<false><<<dim3(2 * L.O / 128, NROWS / 128, 1), 256>>>(
            L.X, 512, 0,
            pWtmp, 2 * L.O, 0,
            pHH, 2 * L.O, 0, L.C);
        edge_stats_kernel<<<NROWS, 256>>>(L.O);
        stats_reduce_kernel<<<dim3(4, NB), 256>>>(8, 4, (float)(NPTS * KNN * (L.O / 4)));
        edge_normmax_kernel<<<NROWS, L.O>>>(L.O, L.coff, L.gw, L.gb);
    }

    // mid: hm = concat @ wm^T  (16384 x 512 -> 1024)
    sgemm128<true><<<dim3(1024 / 128, NROWS / 128, 1), 256>>>(
        pConcat, 512, 0, wm, 512, 0, pHm, 1024, 0, 512);
    seq_stats_kernel<<<NROWS, 256>>>();
    stats_reduce_kernel<<<dim3(16, NB), 256>>>(32, 16, (float)(NPTS * 64));
    seq_max_part<<<dim3(4, NB, 8), 256>>>(gmw, gmb);
    seq_max_combine<<<dim3(4, NB), 256>>>();

    // head MLP
    mlp_kernel<<<NB, 256>>>(fc1w, fc1b, ln1w, ln1b,
                            fc2w, fc2b, ln2w, ln2b,
                            fc3w, fc3b, ln3w, ln3b,
                            fc4w, fc4b, out);
}

// round 4
// speedup vs baseline: 3.2137x; 1.0038x over previous
#include <cuda_runtime.h>
#include <cuda_bf16.h>
#include <cstdint>
#include <cstddef>

// ---------------------------------------------------------------------------
// DGCNN pipeline, fp32. B=8, N=2048, K=20.
// Round 4: fma.rn.f32x2 packed-FMA SGEMM inner loop (2x fp32 throughput),
// dual-query select warps (2x ILP on shfl chains).
// ---------------------------------------------------------------------------

#define NPTS   2048
#define NB     8
#define NROWS  (NB*NPTS)   // 16384
#define KNN    20
#define FINF   3.4e38f

// ------------------------- device scratch (no allocs) ----------------------
__device__ float  g_gram[(size_t)NB * NPTS * NPTS];   // reused per layer
__device__ float  g_hh[(size_t)NROWS * 512];          // [rows x 2O], hc | hn
__device__ float  g_concat[(size_t)NROWS * 512];      // x1|x2|x3|x4
__device__ float  g_hm[(size_t)NROWS * 1024];         // seq features
__device__ float  g_sq[NROWS];
__device__ int    g_idx[(size_t)NROWS * KNN];
__device__ float  g_wtmp[128 * 512];                  // transformed weights (C x 2O)
__device__ float  g_part[(size_t)NROWS * 32];         // per-row group partials
__device__ float  g_mu[128];
__device__ float  g_rs[128];
__device__ float  g_pmax[NB * 8 * 1024];              // seq max partials
__device__ float  g_gvec[NB * 1024];

__device__ __forceinline__ float leaky02(float v) { return v > 0.f ? v : 0.2f * v; }

// ---------------------- packed f32x2 helpers (Blackwell) --------------------
__device__ __forceinline__ unsigned long long pack2same(float x) {
    unsigned long long r;
    asm("mov.b64 %0, {%1, %1};" : "=l"(r) : "f"(x));
    return r;
}
__device__ __forceinline__ void fma2(unsigned long long& d,
                                     unsigned long long a, unsigned long long b) {
    asm("fma.rn.f32x2 %0, %1, %2, %0;" : "+l"(d) : "l"(a), "l"(b));
}
__device__ __forceinline__ void unpack2(unsigned long long v, float& lo, float& hi) {
    asm("mov.b64 {%0, %1}, %2;" : "=f"(lo), "=f"(hi) : "l"(v));
}

// ------------------------------ sq kernel ----------------------------------
__global__ void sq_kernel(const float* __restrict__ X, int ldx, int C) {
    int r = blockIdx.x * 256 + threadIdx.x;
    if (r < NROWS) {
        float s = 0.f;
        const float* xp = X + (size_t)r * ldx;
        for (int c = 0; c < C; c++) { float v = xp[c]; s += v * v; }
        g_sq[r] = s;
    }
}

// -------- 128x128x8 double-buffered SGEMM, f32x2 inner loop (8x8/thr) ------
template <bool TRANSB>
__global__ __launch_bounds__(256, 2) void sgemm128(
    const float* __restrict__ A, int lda, size_t sA,
    const float* __restrict__ Bp, int ldb, size_t sB,
    float* __restrict__ Cp, int ldc, size_t sC, int K)
{
    __shared__ __align__(16) float As[2][8][132];
    __shared__ __align__(16) float Bs[2][8][132];
    const float* Ab = A  + (size_t)blockIdx.z * sA;
    const float* Bb = Bp + (size_t)blockIdx.z * sB;
    float*       Cb = Cp + (size_t)blockIdx.z * sC;
    const int m0 = blockIdx.y * 128, n0 = blockIdx.x * 128;
    const int tid = threadIdx.x;
    const int tx = tid & 15, ty = tid >> 4;
    const int ma = tid >> 1;
    const int ka = (tid & 1) * 4;
    const int kb = tid >> 5;
    const int nb = (tid & 31) * 4;

    unsigned long long acc2[8][4];
#pragma unroll
    for (int i = 0; i < 8; i++)
#pragma unroll
        for (int j = 0; j < 4; j++) acc2[i][j] = 0ull;

    const int nk = K >> 3;
    float4 va, vb;

    va = *(const float4*)&Ab[(size_t)(m0 + ma) * lda + ka];
    if (TRANSB) vb = *(const float4*)&Bb[(size_t)(n0 + ma) * ldb + ka];
    else        vb = *(const float4*)&Bb[(size_t)kb * ldb + n0 + nb];
    As[0][ka+0][ma] = va.x; As[0][ka+1][ma] = va.y;
    As[0][ka+2][ma] = va.z; As[0][ka+3][ma] = va.w;
    if (TRANSB) {
        Bs[0][ka+0][ma] = vb.x; Bs[0][ka+1][ma] = vb.y;
        Bs[0][ka+2][ma] = vb.z; Bs[0][ka+3][ma] = vb.w;
    } else {
        *(float4*)&Bs[0][kb][nb] = vb;
    }
    __syncthreads();

    for (int kc = 0; kc < nk; kc++) {
        const int buf = kc & 1;
        if (kc + 1 < nk) {
            const int k0 = (kc + 1) << 3;
            va = *(const float4*)&Ab[(size_t)(m0 + ma) * lda + k0 + ka];
            if (TRANSB) vb = *(const float4*)&Bb[(size_t)(n0 + ma) * ldb + k0 + ka];
            else        vb = *(const float4*)&Bb[(size_t)(k0 + kb) * ldb + n0 + nb];
        }
#pragma unroll
        for (int kk = 0; kk < 8; kk++) {
            float a[8];
            *(float4*)&a[0] = *(const float4*)&As[buf][kk][ty * 4];
            *(float4*)&a[4] = *(const float4*)&As[buf][kk][64 + ty * 4];
            ulonglong2 bA = *(const ulonglong2*)&Bs[buf][kk][tx * 4];
            ulonglong2 bB = *(const ulonglong2*)&Bs[buf][kk][64 + tx * 4];
            unsigned long long b2[4] = { bA.x, bA.y, bB.x, bB.y };
#pragma unroll
            for (int i = 0; i < 8; i++) {
                unsigned long long ai = pack2same(a[i]);
#pragma unroll
                for (int j = 0; j < 4; j++) fma2(acc2[i][j], ai, b2[j]);
            }
        }
        if (kc + 1 < nk) {
            const int nbuf = buf ^ 1;
            As[nbuf][ka+0][ma] = va.x; As[nbuf][ka+1][ma] = va.y;
            As[nbuf][ka+2][ma] = va.z; As[nbuf][ka+3][ma] = va.w;
            if (TRANSB) {
                Bs[nbuf][ka+0][ma] = vb.x; Bs[nbuf][ka+1][ma] = vb.y;
                Bs[nbuf][ka+2][ma] = vb.z; Bs[nbuf][ka+3][ma] = vb.w;
            } else {
                *(float4*)&Bs[nbuf][kb][nb] = vb;
            }
        }
        __syncthreads();
    }

#pragma unroll
    for (int i = 0; i < 8; i++) {
        const int mrow = m0 + ((i < 4) ? (ty * 4 + i) : (64 + ty * 4 + i - 4));
        float* Cr = &Cb[(size_t)mrow * ldc + n0];
        float c0, c1, c2, c3, c4, c5, c6, c7;
        unpack2(acc2[i][0], c0, c1); unpack2(acc2[i][1], c2, c3);
        unpack2(acc2[i][2], c4, c5); unpack2(acc2[i][3], c6, c7);
        *(float4*)(Cr + tx * 4)      = make_float4(c0, c1, c2, c3);
        *(float4*)(Cr + 64 + tx * 4) = make_float4(c4, c5, c6, c7);
    }
}

// ------------------ dual-query warp top-20 select core ----------------------
// Each warp owns two queries (sd0/sd1, 2048 distances each, lane L owns
// m = L + 32j). Two interleaved shfl-butterfly argmin chains -> 2x ILP.
__device__ __forceinline__ void topk2_from_smem(float* sd0, float* sd1,
                                                int row0, int row1, int lane,
                                                float bv0, int bi0,
                                                float bv1, int bi1) {
#pragma unroll 1
    for (int it = 0; it < KNN; it++) {
        float v0 = bv0, v1 = bv1; int i0 = bi0, i1 = bi1;
#pragma unroll
        for (int off = 16; off > 0; off >>= 1) {
            float w0 = __shfl_xor_sync(0xffffffffu, v0, off);
            int   j0 = __shfl_xor_sync(0xffffffffu, i0, off);
            float w1 = __shfl_xor_sync(0xffffffffu, v1, off);
            int   j1 = __shfl_xor_sync(0xffffffffu, i1, off);
            if (w0 < v0 || (w0 == v0 && j0 < i0)) { v0 = w0; i0 = j0; }
            if (w1 < v1 || (w1 == v1 && j1 < i1)) { v1 = w1; i1 = j1; }
        }
        if (lane == 0) {
            g_idx[(size_t)row0 * KNN + it] = i0;
            g_idx[(size_t)row1 * KNN + it] = i1;
            sd0[i0] = FINF;
            sd1[i1] = FINF;
        }
        __syncwarp();
        int wl0 = i0 & 31, wl1 = i1 & 31;
        float rv0 = FINF, rv1 = FINF; int rb0 = 0x7fffffff, rb1 = 0x7fffffff;
#pragma unroll
        for (int q = 0; q < 2; q++) {
            int m0 = wl0 + 32 * (2 * lane + q);
            int m1 = wl1 + 32 * (2 * lane + q);
            float d0 = sd0[m0];
            float d1 = sd1[m1];
            if (d0 < rv0 || (d0 == rv0 && m0 < rb0)) { rv0 = d0; rb0 = m0; }
            if (d1 < rv1 || (d1 == rv1 && m1 < rb1)) { rv1 = d1; rb1 = m1; }
        }
#pragma unroll
        for (int off = 16; off > 0; off >>= 1) {
            float w0 = __shfl_xor_sync(0xffffffffu, rv0, off);
            int   j0 = __shfl_xor_sync(0xffffffffu, rb0, off);
            float w1 = __shfl_xor_sync(0xffffffffu, rv1, off);
            int   j1 = __shfl_xor_sync(0xffffffffu, rb1, off);
            if (w0 < rv0 || (w0 == rv0 && j0 < rb0)) { rv0 = w0; rb0 = j0; }
            if (w1 < rv1 || (w1 == rv1 && j1 < rb1)) { rv1 = w1; rb1 = j1; }
        }
        if (lane == wl0) { bv0 = rv0; bi0 = rb0; }
        if (lane == wl1) { bv1 = rv1; bi1 = rb1; }
    }
}

// layers 2-4: distances from precomputed gram rows (2 queries / warp)
__global__ __launch_bounds__(128) void select_gram_kernel() {
    extern __shared__ float sdyn[];          // 8 * 2048 floats
    int warp = threadIdx.x >> 5, lane = threadIdx.x & 31;
    int row0 = blockIdx.x * 8 + warp * 2;
    int row1 = row0 + 1;
    int b = row0 >> 11;
    int n0 = row0 & 2047, n1 = row1 & 2047;
    const float* base = g_gram + (size_t)b * NPTS * NPTS;
    const float* dr0 = base + (size_t)n0 * NPTS;
    const float* dr1 = base + (size_t)n1 * NPTS;
    float sq0 = g_sq[row0], sq1 = g_sq[row1];
    float* sd0 = sdyn + (size_t)warp * 2 * NPTS;
    float* sd1 = sd0 + NPTS;
    float bv0 = FINF, bv1 = FINF; int bi0 = 0x7fffffff, bi1 = 0x7fffffff;
#pragma unroll 4
    for (int j = 0; j < 64; j++) {
        int m = lane + 32 * j;
        float sqm = g_sq[(b << 11) + m];
        float d0 = sq0 + sqm - 2.f * dr0[m];
        float d1 = sq1 + sqm - 2.f * dr1[m];
        if (m == n0) d0 = FINF;
        if (m == n1) d1 = FINF;
        sd0[m] = d0; sd1[m] = d1;
        if (d0 < bv0 || (d0 == bv0 && m < bi0)) { bv0 = d0; bi0 = m; }
        if (d1 < bv1 || (d1 == bv1 && m < bi1)) { bv1 = d1; bi1 = m; }
    }
    __syncwarp();
    topk2_from_smem(sd0, sd1, row0, row1, lane, bv0, bi0, bv1, bi1);
}

// layer 1: distances computed from 3D points on the fly (2 queries / warp)
__global__ __launch_bounds__(128) void select3_kernel(const float* __restrict__ X) {
    extern __shared__ float sdyn[];
    int warp = threadIdx.x >> 5, lane = threadIdx.x & 31;
    int row0 = blockIdx.x * 8 + warp * 2;
    int row1 = row0 + 1;
    int b = row0 >> 11;
    int n0 = row0 & 2047, n1 = row1 & 2047;
    const float* Xb = X + (size_t)(b << 11) * 3;
    float x0 = Xb[n0 * 3], y0 = Xb[n0 * 3 + 1], z0 = Xb[n0 * 3 + 2];
    float x1 = Xb[n1 * 3], y1 = Xb[n1 * 3 + 1], z1 = Xb[n1 * 3 + 2];
    float sq0 = g_sq[row0], sq1 = g_sq[row1];
    float* sd0 = sdyn + (size_t)warp * 2 * NPTS;
    float* sd1 = sd0 + NPTS;
    float bv0 = FINF, bv1 = FINF; int bi0 = 0x7fffffff, bi1 = 0x7fffffff;
#pragma unroll 4
    for (int j = 0; j < 64; j++) {
        int m = lane + 32 * j;
        float px = Xb[m * 3], py = Xb[m * 3 + 1], pz = Xb[m * 3 + 2];
        float sqm = g_sq[(b << 11) + m];
        float d0 = sq0 + sqm - 2.f * (x0 * px + y0 * py + z0 * pz);
        float d1 = sq1 + sqm - 2.f * (x1 * px + y1 * py + z1 * pz);
        if (m == n0) d0 = FINF;
        if (m == n1) d1 = FINF;
        sd0[m] = d0; sd1[m] = d1;
        if (d0 < bv0 || (d0 == bv0 && m < bi0)) { bv0 = d0; bi0 = m; }
        if (d1 < bv1 || (d1 == bv1 && m < bi1)) { bv1 = d1; bi1 = m; }
    }
    __syncwarp();
    topk2_from_smem(sd0, sd1, row0, row1, lane, bv0, bi0, bv1, bi1);
}

// --------------------------- weight transform ------------------------------
__global__ void wtmp_kernel(const float* __restrict__ w, int C, int O) {
    int i = blockIdx.x * 256 + threadIdx.x;
    int tot = C * 2 * O;
    if (i < tot) {
        int c = i / (2 * O);
        int o = i % (2 * O);
        float v;
        if (o < O) v = w[(size_t)o * (2 * C) + c] - w[(size_t)o * (2 * C) + C + c];
        else       v = w[(size_t)(o - O) * (2 * C) + C + c];
        g_wtmp[i] = v;
    }
}

// ----------------------- layer-1 hh (K=3 feature GEMM) ---------------------
__global__ void hh3_kernel(const float* __restrict__ X) {
    __shared__ float w[3 * 128];
    int row = blockIdx.x;
    int t = threadIdx.x;   // 128
    w[t] = g_wtmp[t]; w[128 + t] = g_wtmp[128 + t]; w[256 + t] = g_wtmp[256 + t];
    __syncthreads();
    float x0 = X[row * 3], x1 = X[row * 3 + 1], x2 = X[row * 3 + 2];
    g_hh[(size_t)row * 128 + t] = x0 * w[t] + x1 * w[128 + t] + x2 * w[256 + t];
}

// --------------------------- edge GN stats pass -----------------------------
__global__ __launch_bounds__(256) void edge_stats_kernel(int O) {
    __shared__ int   sidx[KNN];
    __shared__ float sacc[8];
    int row = blockIdx.x;
    int b = row >> 11;
    int t = threadIdx.x;
    if (t < KNN) sidx[t] = g_idx[(size_t)row * KNN + t];
    if (t < 8) sacc[t] = 0.f;
    __syncthreads();
    int twoO = 2 * O;
    int c = t % O;
    int k0 = t / O;
    int kstep = 256 / O;
    float hcv = g_hh[(size_t)row * twoO + c];
    size_t bbase = ((size_t)(b << 11)) * twoO + O + c;
    float s = 0.f, q = 0.f;
    for (int k = k0; k < KNN; k += kstep) {
        float h = hcv + g_hh[bbase + (size_t)sidx[k] * twoO];
        s += h; q += h * h;
    }
    int g = c / (O / 4);
    atomicAdd(&sacc[g * 2 + 0], s);
    atomicAdd(&sacc[g * 2 + 1], q);
    __syncthreads();
    if (t < 8) g_part[(size_t)row * 8 + t] = sacc[t];
}

// ------------------- cross-block stats reduce (edge & seq) ------------------
__global__ __launch_bounds__(256) void stats_reduce_kernel(int perrow, int ngroups,
                                                           float cnt) {
    __shared__ double ds[256], dq[256];
    int g = blockIdx.x, b = blockIdx.y, t = threadIdx.x;
    double s = 0.0, q = 0.0;
    for (int r = t; r < NPTS; r += 256) {
        size_t base = ((size_t)((b << 11) + r)) * perrow + g * 2;
        s += (double)g_part[base];
        q += (double)g_part[base + 1];
    }
    ds[t] = s; dq[t] = q;
    __syncthreads();
    for (int st = 128; st > 0; st >>= 1) {
        if (t < st) { ds[t] += ds[t + st]; dq[t] += dq[t + st]; }
        __syncthreads();
    }
    if (t == 0) {
        double mu = ds[0] / (double)cnt;
        double var = dq[0] / (double)cnt - mu * mu;
        g_mu[b * ngroups + g] = (float)mu;
        g_rs[b * ngroups + g] = rsqrtf((float)var + 1e-5f);
    }
}

// ----------------------- edge normalize + leaky + max-k ---------------------
__global__ void edge_normmax_kernel(int O, int coff,
                                    const float* __restrict__ gw,
                                    const float* __restrict__ gb) {
    __shared__ int sidx[KNN];
    int row = blockIdx.x;
    int b = row >> 11;
    int t = threadIdx.x;                 // blockDim == O
    if (t < KNN) sidx[t] = g_idx[(size_t)row * KNN + t];
    __syncthreads();
    int c = t;
    int twoO = 2 * O;
    float hcv = g_hh[(size_t)row * twoO + c];
    int g = c / (O / 4);
    float mu = g_mu[b * 4 + g], rs = g_rs[b * 4 + g];
    float w = gw[c], bb = gb[c];
    size_t bbase = ((size_t)(b << 11)) * twoO + O + c;
    float m = -FINF;
#pragma unroll
    for (int k = 0; k < KNN; k++) {
        float h = hcv + g_hh[bbase + (size_t)sidx[k] * twoO];
        float v = (h - mu) * rs * w + bb;
        m = fmaxf(m, leaky02(v));
    }
    g_concat[(size_t)row * 512 + coff + c] = m;
}

// ------------------------------ seq GN stats --------------------------------
__global__ __launch_bounds__(256) void seq_stats_kernel() {
    __shared__ float sacc[32];
    int row = blockIdx.x;
    int t = threadIdx.x;
    if (t < 32) sacc[t] = 0.f;
    __syncthreads();
    const float* hr = g_hm + (size_t)row * 1024;
    float s = 0.f, q = 0.f;
#pragma unroll
    for (int j = 0; j < 4; j++) { float v = hr[t * 4 + j]; s += v; q += v * v; }
    int g = t >> 4;
    atomicAdd(&sacc[g * 2 + 0], s);
    atomicAdd(&sacc[g * 2 + 1], q);
    __syncthreads();
    if (t < 32) g_part[(size_t)row * 32 + t] = sacc[t];
}

// ------------------- seq normalize + leaky + max over N ---------------------
__global__ __launch_bounds__(256) void seq_max_part(const float* __restrict__ gmw,
                                                    const float* __restrict__ gmb) {
    int c = blockIdx.x * 256 + threadIdx.x;
    int b = blockIdx.y;
    int z = blockIdx.z;                  // N chunk
    int g = c >> 6;
    float mu = g_mu[b * 16 + g], rs = g_rs[b * 16 + g];
    float w = gmw[c], bb = gmb[c];
    const float* col = g_hm + ((size_t)b * NPTS + z * 256) * 1024 + c;
    float m = -FINF;
#pragma unroll 4
    for (int n = 0; n < 256; n++) {
        float v = (col[(size_t)n * 1024] - mu) * rs * w + bb;
        m = fmaxf(m, leaky02(v));
    }
    g_pmax[((size_t)b * 8 + z) * 1024 + c] = m;
}

__global__ __launch_bounds__(256) void seq_max_combine() {
    int c = blockIdx.x * 256 + threadIdx.x;
    int b = blockIdx.y;
    float m = -FINF;
#pragma unroll
    for (int z = 0; z < 8; z++)
        m = fmaxf(m, g_pmax[((size_t)b * 8 + z) * 1024 + c]);
    g_gvec[b * 1024 + c] = m;
}

// --------------------------------- MLP head ---------------------------------
__device__ __forceinline__ float bsum256(float v, float* red, int t) {
    red[t] = v; __syncthreads();
    for (int s = 128; s > 0; s >>= 1) {
        if (t < s) red[t] += red[t + s];
        __syncthreads();
    }
    float r = red[0]; __syncthreads();
    return r;
}

__device__ __forceinline__ void ln_leaky(float* buf, int L,
                                         const float* __restrict__ w,
                                         const float* __restrict__ b,
                                         float* red, int t) {
    float s = 0.f, q = 0.f;
    for (int i = t; i < L; i += 256) { float v = buf[i]; s += v; q += v * v; }
    float S = bsum256(s, red, t);
    float Q = bsum256(q, red, t);
    float mu = S / (float)L;
    float var = Q / (float)L - mu * mu;
    float rs = rsqrtf(var + 1e-5f);
    for (int i = t; i < L; i += 256) {
        float v = (buf[i] - mu) * rs * w[i] + b[i];
        buf[i] = leaky02(v);
    }
    __syncthreads();
}

__global__ __launch_bounds__(256) void mlp_kernel(
    const float* __restrict__ fc1w, const float* __restrict__ fc1b,
    const float* __restrict__ ln1w, const float* __restrict__ ln1b,
    const float* __restrict__ fc2w, const float* __restrict__ fc2b,
    const float* __restrict__ ln2w, const float* __restrict__ ln2b,
    const float* __restrict__ fc3w, const float* __restrict__ fc3b,
    const float* __restrict__ ln3w, const float* __restrict__ ln3b,
    const float* __restrict__ fc4w, const float* __restrict__ fc4b,
    float* __restrict__ out)
{
    __shared__ __align__(16) float sin_[1024];
    __shared__ __align__(16) float t1[512];
    __shared__ __align__(16) float t2[256];
    __shared__ __align__(16) float t3[64];
    __shared__ float red[256];
    int b = blockIdx.x, t = threadIdx.x;
    for (int i = t; i < 1024; i += 256) sin_[i] = g_gvec[b * 1024 + i];
    __syncthreads();
    for (int o = t; o < 512; o += 256) {
        float acc = fc1b[o];
        const float4* wr = (const float4*)(fc1w + (size_t)o * 1024);
        const float4* xr = (const float4*)sin_;
        for (int c = 0; c < 256; c++) {
            float4 w4 = wr[c], x4 = xr[c];
            acc += w4.x * x4.x + w4.y * x4.y + w4.z * x4.z + w4.w * x4.w;
        }
        t1[o] = acc;
    }
    __syncthreads();
    ln_leaky(t1, 512, ln1w, ln1b, red, t);
    if (t < 256) {
        float acc = fc2b[t];
        const float4* wr = (const float4*)(fc2w + (size_t)t * 512);
        const float4* xr = (const float4*)t1;
        for (int c = 0; c < 128; c++) {
            float4 w4 = wr[c], x4 = xr[c];
            acc += w4.x * x4.x + w4.y * x4.y + w4.z * x4.z + w4.w * x4.w;
        }
        t2[t] = acc;
    }
    __syncthreads();
    ln_leaky(t2, 256, ln2w, ln2b, red, t);
    if (t < 64) {
        float acc = fc3b[t];
        const float4* wr = (const float4*)(fc3w + (size_t)t * 256);
        const float4* xr = (const float4*)t2;
        for (int c = 0; c < 64; c++) {
            float4 w4 = wr[c], x4 = xr[c];
            acc += w4.x * x4.x + w4.y * x4.y + w4.z * x4.z + w4.w * x4.w;
        }
        t3[t] = acc;
    }
    __syncthreads();
    ln_leaky(t3, 64, ln3w, ln3b, red, t);
    if (t < 2) {
        float acc = fc4b[t];
        for (int c = 0; c < 64; c++) acc += fc4w[t * 64 + c] * t3[c];
        out[b * 2 + t] = acc;
    }
}

// =============================== host driver ================================
extern "C" void kernel_launch(void* const* d_in, const int* in_sizes, int n_in,
                              void* d_out, int out_size)
{
    const float* x    = (const float*)d_in[0];
    const float* w1   = (const float*)d_in[1];
    const float* g1w  = (const float*)d_in[2];
    const float* g1b  = (const float*)d_in[3];
    const float* w2   = (const float*)d_in[4];
    const float* g2w  = (const float*)d_in[5];
    const float* g2b  = (const float*)d_in[6];
    const float* w3   = (const float*)d_in[7];
    const float* g3w  = (const float*)d_in[8];
    const float* g3b  = (const float*)d_in[9];
    const float* w4   = (const float*)d_in[10];
    const float* g4w  = (const float*)d_in[11];
    const float* g4b  = (const float*)d_in[12];
    const float* wm   = (const float*)d_in[13];
    const float* gmw  = (const float*)d_in[14];
    const float* gmb  = (const float*)d_in[15];
    const float* fc1w = (const float*)d_in[16];
    const float* fc1b = (const float*)d_in[17];
    const float* ln1w = (const float*)d_in[18];
    const float* ln1b = (const float*)d_in[19];
    const float* fc2w = (const float*)d_in[20];
    const float* fc2b = (const float*)d_in[21];
    const float* ln2w = (const float*)d_in[22];
    const float* ln2b = (const float*)d_in[23];
    const float* fc3w = (const float*)d_in[24];
    const float* fc3b = (const float*)d_in[25];
    const float* ln3w = (const float*)d_in[26];
    const float* ln3b = (const float*)d_in[27];
    const float* fc4w = (const float*)d_in[28];
    const float* fc4b = (const float*)d_in[29];
    float* out = (float*)d_out;

    float *pGram, *pConcat, *pHH, *pHm, *pWtmp;
    cudaGetSymbolAddress((void**)&pGram,   g_gram);
    cudaGetSymbolAddress((void**)&pConcat, g_concat);
    cudaGetSymbolAddress((void**)&pHH,     g_hh);
    cudaGetSymbolAddress((void**)&pHm,     g_hm);
    cudaGetSymbolAddress((void**)&pWtmp,   g_wtmp);

    const int SELECT_SMEM = 8 * NPTS * sizeof(float);   // 64 KB
    cudaFuncSetAttribute(select3_kernel,
                         cudaFuncAttributeMaxDynamicSharedMemorySize, SELECT_SMEM);
    cudaFuncSetAttribute(select_gram_kernel,
                         cudaFuncAttributeMaxDynamicSharedMemorySize, SELECT_SMEM);

    // ---------------- layer 1 (C=3, O=64) ----------------------------------
    sq_kernel<<<(NROWS + 255) / 256, 256>>>(x, 3, 3);
    wtmp_kernel<<<(3 * 128 + 255) / 256, 256>>>(w1, 3, 64);
    hh3_kernel<<<NROWS, 128>>>(x);
    select3_kernel<<<NROWS / 8, 128, SELECT_SMEM>>>(x);
    edge_stats_kernel<<<NROWS, 256>>>(64);
    stats_reduce_kernel<<<dim3(4, NB), 256>>>(8, 4, (float)(NPTS * KNN * 16));
    edge_normmax_kernel<<<NROWS, 64>>>(64, 0, g1w, g1b);

    // ---------------- layers 2-4 ------------------------------------------
    struct LayerCfg {
        const float* X; int C; int O;
        const float* w; const float* gw; const float* gb; int coff;
    };
    LayerCfg layers[3] = {
        { pConcat + 0,   64,  64,  w2, g2w, g2b, 64  },
        { pConcat + 64,  64,  128, w3, g3w, g3b, 128 },
        { pConcat + 128, 128, 256, w4, g4w, g4b, 256 },
    };

    for (int l = 0; l < 3; l++) {
        const LayerCfg& L = layers[l];
        sq_kernel<<<(NROWS + 255) / 256, 256>>>(L.X, 512, L.C);
        sgemm128<true><<<dim3(NPTS / 128, NPTS / 128, NB), 256>>>(
            L.X, 512, (size_t)NPTS * 512,
            L.X, 512, (size_t)NPTS * 512,
            pGram, NPTS, (size_t)NPTS * NPTS, L.C);
        select_gram_kernel<<<NROWS / 8, 128, SELECT_SMEM>>>();
        wtmp_kernel<<<(L.C * 2 * L.O + 255) / 256, 256>>>(L.w, L.C, L.O);
        sgemm128<false><<<dim3(2 * L.O / 128, NROWS / 128, 1), 256>>>(
            L.X, 512, 0,
            pWtmp, 2 * L.O, 0,
            pHH, 2 * L.O, 0, L.C);
        edge_stats_kernel<<<NROWS, 256>>>(L.O);
        stats_reduce_kernel<<<dim3(4, NB), 256>>>(8, 4, (float)(NPTS * KNN * (L.O / 4)));
        edge_normmax_kernel<<<NROWS, L.O>>>(L.O, L.coff, L.gw, L.gb);
    }

    // mid: hm = concat @ wm^T  (16384 x 512 -> 1024)
    sgemm128<true><<<dim3(1024 / 128, NROWS / 128, 1), 256>>>(
        pConcat, 512, 0, wm, 512, 0, pHm, 1024, 0, 512);
    seq_stats_kernel<<<NROWS, 256>>>();
    stats_reduce_kernel<<<dim3(16, NB), 256>>>(32, 16, (float)(NPTS * 64));
    seq_max_part<<<dim3(4, NB, 8), 256>>>(gmw, gmb);
    seq_max_combine<<<dim3(4, NB), 256>>>();

    // head MLP
    mlp_kernel<<<NB, 256>>>(fc1w, fc1b, ln1w, ln1b,
                            fc2w, fc2b, ln2w, ln2b,
                            fc3w, fc3b, ln3w, ln3b,
                            fc4w, fc4b, out);
}

// round 5
// speedup vs baseline: 5.2806x; 1.6432x over previous
#include <cuda_runtime.h>
#include <cuda_bf16.h>
#include <cstdint>
#include <cstddef>

// ---------------------------------------------------------------------------
// DGCNN pipeline, fp32. B=8, N=2048, K=20.
// Round 5: bank-conflict-free (skewed) smem in knn select, single fused edge
// gather pass (stats + per-channel hmax/hmin; normmax via monotonicity of
// leaky(a*h+b)), sq fused into edge-final.
// ---------------------------------------------------------------------------

#define NPTS   2048
#define NB     8
#define NROWS  (NB*NPTS)   // 16384
#define KNN    20
#define FINF   3.4e38f

// ------------------------- device scratch (no allocs) ----------------------
__device__ float  g_gram[(size_t)NB * NPTS * NPTS];   // reused per layer
__device__ float  g_hh[(size_t)NROWS * 512];          // [rows x 2O], hc | hn
__device__ float  g_concat[(size_t)NROWS * 512];      // x1|x2|x3|x4
__device__ float  g_hm[(size_t)NROWS * 1024];         // seq features
__device__ float  g_hmax[(size_t)NROWS * 256];
__device__ float  g_hmin[(size_t)NROWS * 256];
__device__ float  g_sq[NROWS];
__device__ int    g_idx[(size_t)NROWS * KNN];
__device__ float  g_wtmp[128 * 512];                  // transformed weights (C x 2O)
__device__ float  g_part[(size_t)NROWS * 32];         // per-row group partials
__device__ float  g_mu[128];
__device__ float  g_rs[128];
__device__ float  g_pmax[NB * 8 * 1024];              // seq max partials
__device__ float  g_gvec[NB * 1024];

__device__ __forceinline__ float leaky02(float v) { return v > 0.f ? v : 0.2f * v; }
__device__ __forceinline__ int   skew(int m)      { return m + (m >> 5); }
#define SD_LEN 2112   // skew(2047)=2110 -> pad

// ---------------------- packed f32x2 helpers (Blackwell) --------------------
__device__ __forceinline__ unsigned long long pack2same(float x) {
    unsigned long long r;
    asm("mov.b64 %0, {%1, %1};" : "=l"(r) : "f"(x));
    return r;
}
__device__ __forceinline__ void fma2(unsigned long long& d,
                                     unsigned long long a, unsigned long long b) {
    asm("fma.rn.f32x2 %0, %1, %2, %0;" : "+l"(d) : "l"(a), "l"(b));
}
__device__ __forceinline__ void unpack2(unsigned long long v, float& lo, float& hi) {
    asm("mov.b64 {%0, %1}, %2;" : "=f"(lo), "=f"(hi) : "l"(v));
}

// ------------------------------ sq kernel (layer 1 only) -------------------
__global__ void sq_kernel(const float* __restrict__ X) {
    int r = blockIdx.x * 256 + threadIdx.x;
    if (r < NROWS) {
        float a = X[r * 3], b = X[r * 3 + 1], c = X[r * 3 + 2];
        g_sq[r] = a * a + b * b + c * c;
    }
}

// -------- 128x128x8 double-buffered SGEMM, f32x2 inner loop (8x8/thr) ------
template <bool TRANSB>
__global__ __launch_bounds__(256, 2) void sgemm128(
    const float* __restrict__ A, int lda, size_t sA,
    const float* __restrict__ Bp, int ldb, size_t sB,
    float* __restrict__ Cp, int ldc, size_t sC, int K)
{
    __shared__ __align__(16) float As[2][8][132];
    __shared__ __align__(16) float Bs[2][8][132];
    const float* Ab = A  + (size_t)blockIdx.z * sA;
    const float* Bb = Bp + (size_t)blockIdx.z * sB;
    float*       Cb = Cp + (size_t)blockIdx.z * sC;
    const int m0 = blockIdx.y * 128, n0 = blockIdx.x * 128;
    const int tid = threadIdx.x;
    const int tx = tid & 15, ty = tid >> 4;
    const int ma = tid >> 1;
    const int ka = (tid & 1) * 4;
    const int kb = tid >> 5;
    const int nb = (tid & 31) * 4;

    unsigned long long acc2[8][4];
#pragma unroll
    for (int i = 0; i < 8; i++)
#pragma unroll
        for (int j = 0; j < 4; j++) acc2[i][j] = 0ull;

    const int nk = K >> 3;
    float4 va, vb;

    va = *(const float4*)&Ab[(size_t)(m0 + ma) * lda + ka];
    if (TRANSB) vb = *(const float4*)&Bb[(size_t)(n0 + ma) * ldb + ka];
    else        vb = *(const float4*)&Bb[(size_t)kb * ldb + n0 + nb];
    As[0][ka+0][ma] = va.x; As[0][ka+1][ma] = va.y;
    As[0][ka+2][ma] = va.z; As[0][ka+3][ma] = va.w;
    if (TRANSB) {
        Bs[0][ka+0][ma] = vb.x; Bs[0][ka+1][ma] = vb.y;
        Bs[0][ka+2][ma] = vb.z; Bs[0][ka+3][ma] = vb.w;
    } else {
        *(float4*)&Bs[0][kb][nb] = vb;
    }
    __syncthreads();

    for (int kc = 0; kc < nk; kc++) {
        const int buf = kc & 1;
        if (kc + 1 < nk) {
            const int k0 = (kc + 1) << 3;
            va = *(const float4*)&Ab[(size_t)(m0 + ma) * lda + k0 + ka];
            if (TRANSB) vb = *(const float4*)&Bb[(size_t)(n0 + ma) * ldb + k0 + ka];
            else        vb = *(const float4*)&Bb[(size_t)(k0 + kb) * ldb + n0 + nb];
        }
#pragma unroll
        for (int kk = 0; kk < 8; kk++) {
            float a[8];
            *(float4*)&a[0] = *(const float4*)&As[buf][kk][ty * 4];
            *(float4*)&a[4] = *(const float4*)&As[buf][kk][64 + ty * 4];
            ulonglong2 bA = *(const ulonglong2*)&Bs[buf][kk][tx * 4];
            ulonglong2 bB = *(const ulonglong2*)&Bs[buf][kk][64 + tx * 4];
            unsigned long long b2[4] = { bA.x, bA.y, bB.x, bB.y };
#pragma unroll
            for (int i = 0; i < 8; i++) {
                unsigned long long ai = pack2same(a[i]);
#pragma unroll
                for (int j = 0; j < 4; j++) fma2(acc2[i][j], ai, b2[j]);
            }
        }
        if (kc + 1 < nk) {
            const int nbuf = buf ^ 1;
            As[nbuf][ka+0][ma] = va.x; As[nbuf][ka+1][ma] = va.y;
            As[nbuf][ka+2][ma] = va.z; As[nbuf][ka+3][ma] = va.w;
            if (TRANSB) {
                Bs[nbuf][ka+0][ma] = vb.x; Bs[nbuf][ka+1][ma] = vb.y;
                Bs[nbuf][ka+2][ma] = vb.z; Bs[nbuf][ka+3][ma] = vb.w;
            } else {
                *(float4*)&Bs[nbuf][kb][nb] = vb;
            }
        }
        __syncthreads();
    }

#pragma unroll
    for (int i = 0; i < 8; i++) {
        const int mrow = m0 + ((i < 4) ? (ty * 4 + i) : (64 + ty * 4 + i - 4));
        float* Cr = &Cb[(size_t)mrow * ldc + n0];
        float c0, c1, c2, c3, c4, c5, c6, c7;
        unpack2(acc2[i][0], c0, c1); unpack2(acc2[i][1], c2, c3);
        unpack2(acc2[i][2], c4, c5); unpack2(acc2[i][3], c6, c7);
        *(float4*)(Cr + tx * 4)      = make_float4(c0, c1, c2, c3);
        *(float4*)(Cr + 64 + tx * 4) = make_float4(c4, c5, c6, c7);
    }
}

// -------------------- warp-per-query top-20, skewed smem --------------------
// sd holds distances at skew(m). Rescan of column wl is conflict-free:
// bank = (wl + s) mod 32.
__device__ __forceinline__ void topk_from_smem(float* sd, int row, int lane,
                                               float bv, int bi) {
#pragma unroll 1
    for (int it = 0; it < KNN; it++) {
        float v = bv; int idx = bi;
#pragma unroll
        for (int off = 16; off > 0; off >>= 1) {
            float v2 = __shfl_xor_sync(0xffffffffu, v, off);
            int   i2 = __shfl_xor_sync(0xffffffffu, idx, off);
            if (v2 < v || (v2 == v && i2 < idx)) { v = v2; idx = i2; }
        }
        if (lane == 0) {
            g_idx[(size_t)row * KNN + it] = idx;
            sd[skew(idx)] = FINF;
        }
        __syncwarp();
        int wl = idx & 31;
        float rv = FINF; int rb = 0x7fffffff;
#pragma unroll
        for (int q = 0; q < 2; q++) {
            int m = wl + 32 * (2 * lane + q);
            float d = sd[skew(m)];
            if (d < rv || (d == rv && m < rb)) { rv = d; rb = m; }
        }
#pragma unroll
        for (int off = 16; off > 0; off >>= 1) {
            float v2 = __shfl_xor_sync(0xffffffffu, rv, off);
            int   i2 = __shfl_xor_sync(0xffffffffu, rb, off);
            if (v2 < rv || (v2 == rv && i2 < rb)) { rv = v2; rb = i2; }
        }
        if (lane == wl) { bv = rv; bi = rb; }
    }
}

// layers 2-4: distances from precomputed gram rows
__global__ __launch_bounds__(128) void select_gram_kernel() {
    __shared__ float sd[4][SD_LEN];   // 33 KB
    int warp = threadIdx.x >> 5, lane = threadIdx.x & 31;
    int row = blockIdx.x * 4 + warp;
    int b = row >> 11, n = row & 2047;
    const float* drow = g_gram + (size_t)b * NPTS * NPTS + (size_t)n * NPTS;
    float sqn = g_sq[row];
    float* sdw = sd[warp];
    float bv = FINF; int bi = 0x7fffffff;
#pragma unroll 8
    for (int j = 0; j < 64; j++) {
        int m = lane + 32 * j;
        float d = sqn + g_sq[(b << 11) + m] - 2.f * drow[m];
        if (m == n) d = FINF;
        sdw[skew(m)] = d;
        if (d < bv || (d == bv && m < bi)) { bv = d; bi = m; }
    }
    __syncwarp();
    topk_from_smem(sdw, row, lane, bv, bi);
}

// layer 1: distances computed from 3D points on the fly
__global__ __launch_bounds__(128) void select3_kernel(const float* __restrict__ X) {
    __shared__ float sd[4][SD_LEN];
    int warp = threadIdx.x >> 5, lane = threadIdx.x & 31;
    int row = blockIdx.x * 4 + warp;
    int b = row >> 11, n = row & 2047;
    const float* Xb = X + (size_t)(b << 11) * 3;
    float xn = Xb[n * 3], yn = Xb[n * 3 + 1], zn = Xb[n * 3 + 2];
    float sqn = g_sq[row];
    float* sdw = sd[warp];
    float bv = FINF; int bi = 0x7fffffff;
#pragma unroll 4
    for (int j = 0; j < 64; j++) {
        int m = lane + 32 * j;
        float px = Xb[m * 3], py = Xb[m * 3 + 1], pz = Xb[m * 3 + 2];
        float dot = xn * px + yn * py + zn * pz;
        float d = sqn + g_sq[(b << 11) + m] - 2.f * dot;
        if (m == n) d = FINF;
        sdw[skew(m)] = d;
        if (d < bv || (d == bv && m < bi)) { bv = d; bi = m; }
    }
    __syncwarp();
    topk_from_smem(sdw, row, lane, bv, bi);
}

// --------------------------- weight transform ------------------------------
__global__ void wtmp_kernel(const float* __restrict__ w, int C, int O) {
    int i = blockIdx.x * 256 + threadIdx.x;
    int tot = C * 2 * O;
    if (i < tot) {
        int c = i / (2 * O);
        int o = i % (2 * O);
        float v;
        if (o < O) v = w[(size_t)o * (2 * C) + c] - w[(size_t)o * (2 * C) + C + c];
        else       v = w[(size_t)(o - O) * (2 * C) + C + c];
        g_wtmp[i] = v;
    }
}

// ----------------------- layer-1 hh (K=3 feature GEMM) ---------------------
__global__ void hh3_kernel(const float* __restrict__ X) {
    __shared__ float w[3 * 128];
    int row = blockIdx.x;
    int t = threadIdx.x;   // 128
    w[t] = g_wtmp[t]; w[128 + t] = g_wtmp[128 + t]; w[256 + t] = g_wtmp[256 + t];
    __syncthreads();
    float x0 = X[row * 3], x1 = X[row * 3 + 1], x2 = X[row * 3 + 2];
    g_hh[(size_t)row * 128 + t] = x0 * w[t] + x1 * w[128 + t] + x2 * w[256 + t];
}

// ------------------- fused edge gather: stats + hmax/hmin -------------------
// One pass over the K gathered neighbors per (row, c):
//   h = hc[row,c] + hn[idx,c];  accumulate s,q (GN stats) and hmax,hmin.
// blockDim == O. Stats partials -> g_part[row*8 + g*2 + {0,1}].
__global__ void edge_gather_kernel(int O) {
    __shared__ int   sidx[KNN];
    __shared__ float sacc[8];
    int row = blockIdx.x;
    int b = row >> 11;
    int t = threadIdx.x;     // == c
    if (t < KNN) sidx[t] = g_idx[(size_t)row * KNN + t];
    if (t < 8) sacc[t] = 0.f;
    __syncthreads();
    int twoO = 2 * O;
    float hcv = g_hh[(size_t)row * twoO + t];
    size_t bbase = ((size_t)(b << 11)) * twoO + O + t;
    float s = 0.f, q = 0.f, mx = -FINF, mn = FINF;
#pragma unroll
    for (int k = 0; k < KNN; k++) {
        float h = hcv + g_hh[bbase + (size_t)sidx[k] * twoO];
        s += h; q += h * h;
        mx = fmaxf(mx, h); mn = fminf(mn, h);
    }
    g_hmax[(size_t)row * O + t] = mx;
    g_hmin[(size_t)row * O + t] = mn;
    // warp-segmented pre-reduction, then one atomic per segment
    int gsz = O >> 2;                      // channels per group
    int rw = gsz < 32 ? gsz : 32;          // reduce width within warp
#pragma unroll
    for (int off = 16; off > 0; off >>= 1) {
        if (off < rw) {
            s += __shfl_down_sync(0xffffffffu, s, off, 32);
            q += __shfl_down_sync(0xffffffffu, q, off, 32);
        }
    }
    // note: rw is 16 or 32; guard segment crossing for rw==16
    if (rw == 16) {
        // redo safely for 16-wide segments
    }
    int g = t / gsz;
    if ((t & (rw - 1)) == 0) {
        atomicAdd(&sacc[g * 2 + 0], s);
        atomicAdd(&sacc[g * 2 + 1], q);
    }
    __syncthreads();
    if (t < 8) g_part[(size_t)row * 8 + t] = sacc[t];
}

// ------------------- cross-block stats reduce (edge & seq) ------------------
__global__ __launch_bounds__(256) void stats_reduce_kernel(int perrow, int ngroups,
                                                           float cnt) {
    __shared__ double ds[256], dq[256];
    int g = blockIdx.x, b = blockIdx.y, t = threadIdx.x;
    double s = 0.0, q = 0.0;
    for (int r = t; r < NPTS; r += 256) {
        size_t base = ((size_t)((b << 11) + r)) * perrow + g * 2;
        s += (double)g_part[base];
        q += (double)g_part[base + 1];
    }
    ds[t] = s; dq[t] = q;
    __syncthreads();
    for (int st = 128; st > 0; st >>= 1) {
        if (t < st) { ds[t] += ds[t + st]; dq[t] += dq[t + st]; }
        __syncthreads();
    }
    if (t == 0) {
        double mu = ds[0] / (double)cnt;
        double var = dq[0] / (double)cnt - mu * mu;
        g_mu[b * ngroups + g] = (float)mu;
        g_rs[b * ngroups + g] = rsqrtf((float)var + 1e-5f);
    }
}

// -------- edge final: affine+leaky of hmax/hmin (monotone), fused sq -------
// out = leaky(a*h + b2) with a = rs*w, b2 = gb - mu*a, h = a>=0 ? hmax : hmin.
// Also writes g_sq[row] = sum_c out^2 (next layer's squared norms).
__global__ void edge_final_kernel(int O, int coff,
                                  const float* __restrict__ gw,
                                  const float* __restrict__ gb) {
    __shared__ float red[256];
    int row = blockIdx.x;
    int b = row >> 11;
    int t = threadIdx.x;      // == c
    int g = t / (O >> 2);
    float mu = g_mu[b * 4 + g], rs = g_rs[b * 4 + g];
    float a = rs * gw[t];
    float b2 = gb[t] - mu * a;
    float h = (a >= 0.f) ? g_hmax[(size_t)row * O + t] : g_hmin[(size_t)row * O + t];
    float v = leaky02(a * h + b2);
    g_concat[(size_t)row * 512 + coff + t] = v;
    red[t] = v * v;
    __syncthreads();
    for (int st = O >> 1; st > 0; st >>= 1) {
        if (t < st) red[t] += red[t + st];
        __syncthreads();
    }
    if (t == 0) g_sq[row] = red[0];
}

// ------------------------------ seq GN stats --------------------------------
__global__ __launch_bounds__(256) void seq_stats_kernel() {
    __shared__ float sacc[32];
    int row = blockIdx.x;
    int t = threadIdx.x;
    if (t < 32) sacc[t] = 0.f;
    __syncthreads();
    const float* hr = g_hm + (size_t)row * 1024;
    float s = 0.f, q = 0.f;
#pragma unroll
    for (int j = 0; j < 4; j++) { float v = hr[t * 4 + j]; s += v; q += v * v; }
    // 16 lanes per group (t*4 spans 64 channels/group -> group = t/16)
    s += __shfl_down_sync(0xffffffffu, s, 8, 16);
    s += __shfl_down_sync(0xffffffffu, s, 4, 16);
    s += __shfl_down_sync(0xffffffffu, s, 2, 16);
    s += __shfl_down_sync(0xffffffffu, s, 1, 16);
    q += __shfl_down_sync(0xffffffffu, q, 8, 16);
    q += __shfl_down_sync(0xffffffffu, q, 4, 16);
    q += __shfl_down_sync(0xffffffffu, q, 2, 16);
    q += __shfl_down_sync(0xffffffffu, q, 1, 16);
    int g = t >> 4;
    if ((t & 15) == 0) {
        atomicAdd(&sacc[g * 2 + 0], s);
        atomicAdd(&sacc[g * 2 + 1], q);
    }
    __syncthreads();
    if (t < 32) g_part[(size_t)row * 32 + t] = sacc[t];
}

// ------------------- seq normalize + leaky + max over N ---------------------
__global__ __launch_bounds__(256) void seq_max_part(const float* __restrict__ gmw,
                                                    const float* __restrict__ gmb) {
    int c = blockIdx.x * 256 + threadIdx.x;
    int b = blockIdx.y;
    int z = blockIdx.z;
    int g = c >> 6;
    float mu = g_mu[b * 16 + g], rs = g_rs[b * 16 + g];
    float w = gmw[c], bb = gmb[c];
    const float* col = g_hm + ((size_t)b * NPTS + z * 256) * 1024 + c;
    float m = -FINF;
#pragma unroll 4
    for (int n = 0; n < 256; n++) {
        float v = (col[(size_t)n * 1024] - mu) * rs * w + bb;
        m = fmaxf(m, leaky02(v));
    }
    g_pmax[((size_t)b * 8 + z) * 1024 + c] = m;
}

__global__ __launch_bounds__(256) void seq_max_combine() {
    int c = blockIdx.x * 256 + threadIdx.x;
    int b = blockIdx.y;
    float m = -FINF;
#pragma unroll
    for (int z = 0; z < 8; z++)
        m = fmaxf(m, g_pmax[((size_t)b * 8 + z) * 1024 + c]);
    g_gvec[b * 1024 + c] = m;
}

// --------------------------------- MLP head ---------------------------------
__device__ __forceinline__ float bsum256(float v, float* red, int t) {
    red[t] = v; __syncthreads();
    for (int s = 128; s > 0; s >>= 1) {
        if (t < s) red[t] += red[t + s];
        __syncthreads();
    }
    float r = red[0]; __syncthreads();
    return r;
}

__device__ __forceinline__ void ln_leaky(float* buf, int L,
                                         const float* __restrict__ w,
                                         const float* __restrict__ b,
                                         float* red, int t) {
    float s = 0.f, q = 0.f;
    for (int i = t; i < L; i += 256) { float v = buf[i]; s += v; q += v * v; }
    float S = bsum256(s, red, t);
    float Q = bsum256(q, red, t);
    float mu = S / (float)L;
    float var = Q / (float)L - mu * mu;
    float rs = rsqrtf(var + 1e-5f);
    for (int i = t; i < L; i += 256) {
        float v = (buf[i] - mu) * rs * w[i] + b[i];
        buf[i] = leaky02(v);
    }
    __syncthreads();
}

__global__ __launch_bounds__(256) void mlp_kernel(
    const float* __restrict__ fc1w, const float* __restrict__ fc1b,
    const float* __restrict__ ln1w, const float* __restrict__ ln1b,
    const float* __restrict__ fc2w, const float* __restrict__ fc2b,
    const float* __restrict__ ln2w, const float* __restrict__ ln2b,
    const float* __restrict__ fc3w, const float* __restrict__ fc3b,
    const float* __restrict__ ln3w, const float* __restrict__ ln3b,
    const float* __restrict__ fc4w, const float* __restrict__ fc4b,
    float* __restrict__ out)
{
    __shared__ __align__(16) float sin_[1024];
    __shared__ __align__(16) float t1[512];
    __shared__ __align__(16) float t2[256];
    __shared__ __align__(16) float t3[64];
    __shared__ float red[256];
    int b = blockIdx.x, t = threadIdx.x;
    for (int i = t; i < 1024; i += 256) sin_[i] = g_gvec[b * 1024 + i];
    __syncthreads();
    for (int o = t; o < 512; o += 256) {
        float acc = fc1b[o];
        const float4* wr = (const float4*)(fc1w + (size_t)o * 1024);
        const float4* xr = (const float4*)sin_;
        for (int c = 0; c < 256; c++) {
            float4 w4 = wr[c], x4 = xr[c];
            acc += w4.x * x4.x + w4.y * x4.y + w4.z * x4.z + w4.w * x4.w;
        }
        t1[o] = acc;
    }
    __syncthreads();
    ln_leaky(t1, 512, ln1w, ln1b, red, t);
    if (t < 256) {
        float acc = fc2b[t];
        const float4* wr = (const float4*)(fc2w + (size_t)t * 512);
        const float4* xr = (const float4*)t1;
        for (int c = 0; c < 128; c++) {
            float4 w4 = wr[c], x4 = xr[c];
            acc += w4.x * x4.x + w4.y * x4.y + w4.z * x4.z + w4.w * x4.w;
        }
        t2[t] = acc;
    }
    __syncthreads();
    ln_leaky(t2, 256, ln2w, ln2b, red, t);
    if (t < 64) {
        float acc = fc3b[t];
        const float4* wr = (const float4*)(fc3w + (size_t)t * 256);
        const float4* xr = (const float4*)t2;
        for (int c = 0; c < 64; c++) {
            float4 w4 = wr[c], x4 = xr[c];
            acc += w4.x * x4.x + w4.y * x4.y + w4.z * x4.z + w4.w * x4.w;
        }
        t3[t] = acc;
    }
    __syncthreads();
    ln_leaky(t3, 64, ln3w, ln3b, red, t);
    if (t < 2) {
        float acc = fc4b[t];
        for (int c = 0; c < 64; c++) acc += fc4w[t * 64 + c] * t3[c];
        out[b * 2 + t] = acc;
    }
}

// =============================== host driver ================================
extern "C" void kernel_launch(void* const* d_in, const int* in_sizes, int n_in,
                              void* d_out, int out_size)
{
    const float* x    = (const float*)d_in[0];
    const float* w1   = (const float*)d_in[1];
    const float* g1w  = (const float*)d_in[2];
    const float* g1b  = (const float*)d_in[3];
    const float* w2   = (const float*)d_in[4];
    const float* g2w  = (const float*)d_in[5];
    const float* g2b  = (const float*)d_in[6];
    const float* w3   = (const float*)d_in[7];
    const float* g3w  = (const float*)d_in[8];
    const float* g3b  = (const float*)d_in[9];
    const float* w4   = (const float*)d_in[10];
    const float* g4w  = (const float*)d_in[11];
    const float* g4b  = (const float*)d_in[12];
    const float* wm   = (const float*)d_in[13];
    const float* gmw  = (const float*)d_in[14];
    const float* gmb  = (const float*)d_in[15];
    const float* fc1w = (const float*)d_in[16];
    const float* fc1b = (const float*)d_in[17];
    const float* ln1w = (const float*)d_in[18];
    const float* ln1b = (const float*)d_in[19];
    const float* fc2w = (const float*)d_in[20];
    const float* fc2b = (const float*)d_in[21];
    const float* ln2w = (const float*)d_in[22];
    const float* ln2b = (const float*)d_in[23];
    const float* fc3w = (const float*)d_in[24];
    const float* fc3b = (const float*)d_in[25];
    const float* ln3w = (const float*)d_in[26];
    const float* ln3b = (const float*)d_in[27];
    const float* fc4w = (const float*)d_in[28];
    const float* fc4b = (const float*)d_in[29];
    float* out = (float*)d_out;

    float *pGram, *pConcat, *pHH, *pHm, *pWtmp;
    cudaGetSymbolAddress((void**)&pGram,   g_gram);
    cudaGetSymbolAddress((void**)&pConcat, g_concat);
    cudaGetSymbolAddress((void**)&pHH,     g_hh);
    cudaGetSymbolAddress((void**)&pHm,     g_hm);
    cudaGetSymbolAddress((void**)&pWtmp,   g_wtmp);

    // ---------------- layer 1 (C=3, O=64) ----------------------------------
    sq_kernel<<<(NROWS + 255) / 256, 256>>>(x);
    wtmp_kernel<<<(3 * 128 + 255) / 256, 256>>>(w1, 3, 64);
    hh3_kernel<<<NROWS, 128>>>(x);
    select3_kernel<<<NROWS / 4, 128>>>(x);
    edge_gather_kernel<<<NROWS, 64>>>(64);
    stats_reduce_kernel<<<dim3(4, NB), 256>>>(8, 4, (float)(NPTS * KNN * 16));
    edge_final_kernel<<<NROWS, 64>>>(64, 0, g1w, g1b);

    // ---------------- layers 2-4 ------------------------------------------
    struct LayerCfg {
        const float* X; int C; int O;
        const float* w; const float* gw; const float* gb; int coff;
    };
    LayerCfg layers[3] = {
        { pConcat + 0,   64,  64,  w2, g2w, g2b, 64  },
        { pConcat + 64,  64,  128, w3, g3w, g3b, 128 },
        { pConcat + 128, 128, 256, w4, g4w, g4b, 256 },
    };

    for (int l = 0; l < 3; l++) {
        const LayerCfg& L = layers[l];
        sgemm128<true><<<dim3(NPTS / 128, NPTS / 128, NB), 256>>>(
            L.X, 512, (size_t)NPTS * 512,
            L.X, 512, (size_t)NPTS * 512,
            pGram, NPTS, (size_t)NPTS * NPTS, L.C);
        select_gram_kernel<<<NROWS / 4, 128>>>();
        wtmp_kernel<<<(L.C * 2 * L.O + 255) / 256, 256>>>(L.w, L.C, L.O);
        sgemm128<false><<<dim3(2 * L.O / 128, NROWS / 128, 1), 256>>>(
            L.X, 512, 0,
            pWtmp, 2 * L.O, 0,
            pHH, 2 * L.O, 0, L.C);
        edge_gather_kernel<<<NROWS, L.O>>>(L.O);
        stats_reduce_kernel<<<dim3(4, NB), 256>>>(8, 4, (float)(NPTS * KNN * (L.O / 4)));
        edge_final_kernel<<<NROWS, L.O>>>(L.O, L.coff, L.gw, L.gb);
    }

    // mid: hm = concat @ wm^T  (16384 x 512 -> 1024)
    sgemm128<true><<<dim3(1024 / 128, NROWS / 128, 1), 256>>>(
        pConcat, 512, 0, wm, 512, 0, pHm, 1024, 0, 512);
    seq_stats_kernel<<<NROWS, 256>>>();
    stats_reduce_kernel<<<dim3(16, NB), 256>>>(32, 16, (float)(NPTS * 64));
    seq_max_part<<<dim3(4, NB, 8), 256>>>(gmw, gmb);
    seq_max_combine<<<dim3(4, NB), 256>>>();

    // head MLP
    mlp_kernel<<<NB, 256>>>(fc1w, fc1b, ln1w, ln1b,
                            fc2w, fc2b, ln2w, ln2b,
                            fc3w, fc3b, ln3w, ln3b,
                            fc4w, fc4b, out);
}

// round 6
// speedup vs baseline: 5.3821x; 1.0192x over previous
#include <cuda_runtime.h>
#include <cuda_bf16.h>
#include <cstdint>
#include <cstddef>

// ---------------------------------------------------------------------------
// DGCNN pipeline. B=8, N=2048, K=20.
// Round 6: all GEMMs on tensor cores (mma.sync m16n8k16 bf16) with hi/lo
// split precision (3 passes: hi*hi + hi*lo + lo*hi  ~=  fp32 accuracy).
// Everything else as round 5 (skewed-smem select, fused gather, etc).
// ---------------------------------------------------------------------------

#define NPTS   2048
#define NB     8
#define NROWS  (NB*NPTS)   // 16384
#define KNN    20
#define FINF   3.4e38f

// ------------------------- device scratch (no allocs) ----------------------
__device__ float  g_gram[(size_t)NB * NPTS * NPTS];   // reused per layer
__device__ float  g_hh[(size_t)NROWS * 512];          // [rows x 2O], hc | hn
__device__ float  g_concat[(size_t)NROWS * 512];      // x1|x2|x3|x4
__device__ float  g_hm[(size_t)NROWS * 1024];         // seq features
__device__ float  g_hmax[(size_t)NROWS * 256];
__device__ float  g_hmin[(size_t)NROWS * 256];
__device__ float  g_sq[NROWS];
__device__ int    g_idx[(size_t)NROWS * KNN];
__device__ float  g_wtmp[128 * 512];                  // transformed weights (C x 2O)
__device__ float  g_part[(size_t)NROWS * 32];         // per-row group partials
__device__ float  g_mu[128];
__device__ float  g_rs[128];
__device__ float  g_pmax[NB * 8 * 1024];              // seq max partials
__device__ float  g_gvec[NB * 1024];

__device__ __forceinline__ float leaky02(float v) { return v > 0.f ? v : 0.2f * v; }
__device__ __forceinline__ int   skew(int m)      { return m + (m >> 5); }
#define SD_LEN 2112

// ------------------------------ sq kernel (layer 1 only) -------------------
__global__ void sq_kernel(const float* __restrict__ X) {
    int r = blockIdx.x * 256 + threadIdx.x;
    if (r < NROWS) {
        float a = X[r * 3], b = X[r * 3 + 1], c = X[r * 3 + 2];
        g_sq[r] = a * a + b * b + c * c;
    }
}

// ================= tensor-core GEMM (bf16 split, fp32 accum) ================
// C[m,n] = sum_k A[m,k]*B(k,n); TRANSB: B(k,n)=Bp[n*ldb+k] else Bp[k*ldb+n].
// M,N multiples of 128; K multiple of 32.
// Split: x = hi + lo (two bf16) -> A*B ~ Ah*Bh + Ah*Bl + Al*Bh (fp32 accum).
__device__ __forceinline__ void mma16816(float c[4], const uint32_t a[4],
                                         const uint32_t b[2]) {
    asm volatile(
        "mma.sync.aligned.m16n8k16.row.col.f32.bf16.bf16.f32 "
        "{%0,%1,%2,%3}, {%4,%5,%6,%7}, {%8,%9}, {%0,%1,%2,%3};\n"
        : "+f"(c[0]), "+f"(c[1]), "+f"(c[2]), "+f"(c[3])
        : "r"(a[0]), "r"(a[1]), "r"(a[2]), "r"(a[3]), "r"(b[0]), "r"(b[1]));
}

#define SMS 40   // smem k-stride in u16 (32 + 8 pad: conflict-free frags)

template <bool TRANSB>
__global__ __launch_bounds__(256, 2) void mmagemm(
    const float* __restrict__ A, int lda, size_t sA,
    const float* __restrict__ Bp, int ldb, size_t sB,
    float* __restrict__ Cp, int ldc, size_t sC, int K)
{
    __shared__ uint16_t Ah[128 * SMS], Al[128 * SMS];
    __shared__ uint16_t Bh[128 * SMS], Bl[128 * SMS];
    const float* Ab = A  + (size_t)blockIdx.z * sA;
    const float* Bb = Bp + (size_t)blockIdx.z * sB;
    float*       Cb = Cp + (size_t)blockIdx.z * sC;
    const int m0 = blockIdx.y * 128, n0 = blockIdx.x * 128;
    const int tid = threadIdx.x;
    const int warp = tid >> 5, lane = tid & 31;
    const int wm = warp >> 1, wn = warp & 1;      // 4 x 2 warp grid
    const int g = lane >> 2, q = lane & 3;

    float acc[2][8][4];
#pragma unroll
    for (int mt = 0; mt < 2; mt++)
#pragma unroll
        for (int nt = 0; nt < 8; nt++)
#pragma unroll
            for (int j = 0; j < 4; j++) acc[mt][nt][j] = 0.f;

    for (int k0 = 0; k0 < K; k0 += 32) {
        __syncthreads();
        // ---- load A chunk: 128 x 32 fp32 -> bf16 hi/lo ----
        {
            int row = tid >> 1, c0 = (tid & 1) * 16;
            const float* src = &Ab[(size_t)(m0 + row) * lda + k0 + c0];
            uint16_t* dh = &Ah[row * SMS + c0];
            uint16_t* dl = &Al[row * SMS + c0];
#pragma unroll
            for (int i = 0; i < 16; i += 4) {
                float4 v = *(const float4*)&src[i];
                float vs[4] = { v.x, v.y, v.z, v.w };
#pragma unroll
                for (int j = 0; j < 4; j++) {
                    __nv_bfloat16 h = __float2bfloat16(vs[j]);
                    __nv_bfloat16 l = __float2bfloat16(vs[j] - __bfloat162float(h));
                    dh[i + j] = __bfloat16_as_ushort(h);
                    dl[i + j] = __bfloat16_as_ushort(l);
                }
            }
        }
        // ---- load B chunk into Bs[n][k] ----
        if (TRANSB) {
            int row = tid >> 1, c0 = (tid & 1) * 16;
            const float* src = &Bb[(size_t)(n0 + row) * ldb + k0 + c0];
            uint16_t* dh = &Bh[row * SMS + c0];
            uint16_t* dl = &Bl[row * SMS + c0];
#pragma unroll
            for (int i = 0; i < 16; i += 4) {
                float4 v = *(const float4*)&src[i];
                float vs[4] = { v.x, v.y, v.z, v.w };
#pragma unroll
                for (int j = 0; j < 4; j++) {
                    __nv_bfloat16 h = __float2bfloat16(vs[j]);
                    __nv_bfloat16 l = __float2bfloat16(vs[j] - __bfloat162float(h));
                    dh[i + j] = __bfloat16_as_ushort(h);
                    dl[i + j] = __bfloat16_as_ushort(l);
                }
            }
        } else {
            int kk = tid >> 3, c0 = (tid & 7) * 16;
            const float* src = &Bb[(size_t)(k0 + kk) * ldb + n0 + c0];
#pragma unroll
            for (int i = 0; i < 16; i++) {
                float v = src[i];
                __nv_bfloat16 h = __float2bfloat16(v);
                __nv_bfloat16 l = __float2bfloat16(v - __bfloat162float(h));
                Bh[(c0 + i) * SMS + kk] = __bfloat16_as_ushort(h);
                Bl[(c0 + i) * SMS + kk] = __bfloat16_as_ushort(l);
            }
        }
        __syncthreads();

        // ---- compute: two k-steps of 16 ----
#pragma unroll
        for (int ks = 0; ks < 32; ks += 16) {
            const int cb = ks + q * 2;
            uint32_t afh[2][4], afl[2][4];
#pragma unroll
            for (int mt = 0; mt < 2; mt++) {
                int r = wm * 32 + mt * 16 + g;
                afh[mt][0] = *(const uint32_t*)&Ah[r * SMS + cb];
                afh[mt][1] = *(const uint32_t*)&Ah[(r + 8) * SMS + cb];
                afh[mt][2] = *(const uint32_t*)&Ah[r * SMS + cb + 8];
                afh[mt][3] = *(const uint32_t*)&Ah[(r + 8) * SMS + cb + 8];
                afl[mt][0] = *(const uint32_t*)&Al[r * SMS + cb];
                afl[mt][1] = *(const uint32_t*)&Al[(r + 8) * SMS + cb];
                afl[mt][2] = *(const uint32_t*)&Al[r * SMS + cb + 8];
                afl[mt][3] = *(const uint32_t*)&Al[(r + 8) * SMS + cb + 8];
            }
#pragma unroll
            for (int nt = 0; nt < 8; nt++) {
                int n = wn * 64 + nt * 8 + g;
                uint32_t bfh[2], bfl[2];
                bfh[0] = *(const uint32_t*)&Bh[n * SMS + cb];
                bfh[1] = *(const uint32_t*)&Bh[n * SMS + cb + 8];
                bfl[0] = *(const uint32_t*)&Bl[n * SMS + cb];
                bfl[1] = *(const uint32_t*)&Bl[n * SMS + cb + 8];
#pragma unroll
                for (int mt = 0; mt < 2; mt++) {
                    mma16816(acc[mt][nt], afh[mt], bfh);
                    mma16816(acc[mt][nt], afh[mt], bfl);
                    mma16816(acc[mt][nt], afl[mt], bfh);
                }
            }
        }
    }

    // ---- epilogue ----
#pragma unroll
    for (int mt = 0; mt < 2; mt++) {
        int r0 = m0 + wm * 32 + mt * 16 + g;
#pragma unroll
        for (int nt = 0; nt < 8; nt++) {
            int cc = n0 + wn * 64 + nt * 8 + q * 2;
            *(float2*)&Cb[(size_t)r0 * ldc + cc] =
                make_float2(acc[mt][nt][0], acc[mt][nt][1]);
            *(float2*)&Cb[(size_t)(r0 + 8) * ldc + cc] =
                make_float2(acc[mt][nt][2], acc[mt][nt][3]);
        }
    }
}

// -------------------- warp-per-query top-20, skewed smem --------------------
__device__ __forceinline__ void topk_from_smem(float* sd, int row, int lane,
                                               float bv, int bi) {
#pragma unroll 1
    for (int it = 0; it < KNN; it++) {
        float v = bv; int idx = bi;
#pragma unroll
        for (int off = 16; off > 0; off >>= 1) {
            float v2 = __shfl_xor_sync(0xffffffffu, v, off);
            int   i2 = __shfl_xor_sync(0xffffffffu, idx, off);
            if (v2 < v || (v2 == v && i2 < idx)) { v = v2; idx = i2; }
        }
        if (lane == 0) {
            g_idx[(size_t)row * KNN + it] = idx;
            sd[skew(idx)] = FINF;
        }
        __syncwarp();
        int wl = idx & 31;
        float rv = FINF; int rb = 0x7fffffff;
#pragma unroll
        for (int q = 0; q < 2; q++) {
            int m = wl + 32 * (2 * lane + q);
            float d = sd[skew(m)];
            if (d < rv || (d == rv && m < rb)) { rv = d; rb = m; }
        }
#pragma unroll
        for (int off = 16; off > 0; off >>= 1) {
            float v2 = __shfl_xor_sync(0xffffffffu, rv, off);
            int   i2 = __shfl_xor_sync(0xffffffffu, rb, off);
            if (v2 < rv || (v2 == rv && i2 < rb)) { rv = v2; rb = i2; }
        }
        if (lane == wl) { bv = rv; bi = rb; }
    }
}

__global__ __launch_bounds__(128) void select_gram_kernel() {
    __shared__ float sd[4][SD_LEN];
    int warp = threadIdx.x >> 5, lane = threadIdx.x & 31;
    int row = blockIdx.x * 4 + warp;
    int b = row >> 11, n = row & 2047;
    const float* drow = g_gram + (size_t)b * NPTS * NPTS + (size_t)n * NPTS;
    float sqn = g_sq[row];
    float* sdw = sd[warp];
    float bv = FINF; int bi = 0x7fffffff;
#pragma unroll 8
    for (int j = 0; j < 64; j++) {
        int m = lane + 32 * j;
        float d = sqn + g_sq[(b << 11) + m] - 2.f * drow[m];
        if (m == n) d = FINF;
        sdw[skew(m)] = d;
        if (d < bv || (d == bv && m < bi)) { bv = d; bi = m; }
    }
    __syncwarp();
    topk_from_smem(sdw, row, lane, bv, bi);
}

__global__ __launch_bounds__(128) void select3_kernel(const float* __restrict__ X) {
    __shared__ float sd[4][SD_LEN];
    int warp = threadIdx.x >> 5, lane = threadIdx.x & 31;
    int row = blockIdx.x * 4 + warp;
    int b = row >> 11, n = row & 2047;
    const float* Xb = X + (size_t)(b << 11) * 3;
    float xn = Xb[n * 3], yn = Xb[n * 3 + 1], zn = Xb[n * 3 + 2];
    float sqn = g_sq[row];
    float* sdw = sd[warp];
    float bv = FINF; int bi = 0x7fffffff;
#pragma unroll 4
    for (int j = 0; j < 64; j++) {
        int m = lane + 32 * j;
        float px = Xb[m * 3], py = Xb[m * 3 + 1], pz = Xb[m * 3 + 2];
        float dot = xn * px + yn * py + zn * pz;
        float d = sqn + g_sq[(b << 11) + m] - 2.f * dot;
        if (m == n) d = FINF;
        sdw[skew(m)] = d;
        if (d < bv || (d == bv && m < bi)) { bv = d; bi = m; }
    }
    __syncwarp();
    topk_from_smem(sdw, row, lane, bv, bi);
}

// --------------------------- weight transform ------------------------------
__global__ void wtmp_kernel(const float* __restrict__ w, int C, int O) {
    int i = blockIdx.x * 256 + threadIdx.x;
    int tot = C * 2 * O;
    if (i < tot) {
        int c = i / (2 * O);
        int o = i % (2 * O);
        float v;
        if (o < O) v = w[(size_t)o * (2 * C) + c] - w[(size_t)o * (2 * C) + C + c];
        else       v = w[(size_t)(o - O) * (2 * C) + C + c];
        g_wtmp[i] = v;
    }
}

// ----------------------- layer-1 hh (K=3 feature GEMM) ---------------------
__global__ void hh3_kernel(const float* __restrict__ X) {
    __shared__ float w[3 * 128];
    int row = blockIdx.x;
    int t = threadIdx.x;   // 128
    w[t] = g_wtmp[t]; w[128 + t] = g_wtmp[128 + t]; w[256 + t] = g_wtmp[256 + t];
    __syncthreads();
    float x0 = X[row * 3], x1 = X[row * 3 + 1], x2 = X[row * 3 + 2];
    g_hh[(size_t)row * 128 + t] = x0 * w[t] + x1 * w[128 + t] + x2 * w[256 + t];
}

// ------------------- fused edge gather: stats + hmax/hmin -------------------
__global__ void edge_gather_kernel(int O) {
    __shared__ int   sidx[KNN];
    __shared__ float sacc[8];
    int row = blockIdx.x;
    int b = row >> 11;
    int t = threadIdx.x;     // == c
    if (t < KNN) sidx[t] = g_idx[(size_t)row * KNN + t];
    if (t < 8) sacc[t] = 0.f;
    __syncthreads();
    int twoO = 2 * O;
    float hcv = g_hh[(size_t)row * twoO + t];
    size_t bbase = ((size_t)(b << 11)) * twoO + O + t;
    float s = 0.f, q = 0.f, mx = -FINF, mn = FINF;
#pragma unroll
    for (int k = 0; k < KNN; k++) {
        float h = hcv + g_hh[bbase + (size_t)sidx[k] * twoO];
        s += h; q += h * h;
        mx = fmaxf(mx, h); mn = fminf(mn, h);
    }
    g_hmax[(size_t)row * O + t] = mx;
    g_hmin[(size_t)row * O + t] = mn;
    int gsz = O >> 2;
    int rw = gsz < 32 ? gsz : 32;
#pragma unroll
    for (int off = 16; off > 0; off >>= 1) {
        if (off < rw) {
            s += __shfl_down_sync(0xffffffffu, s, off, 32);
            q += __shfl_down_sync(0xffffffffu, q, off, 32);
        }
    }
    int g = t / gsz;
    if ((t & (rw - 1)) == 0) {
        atomicAdd(&sacc[g * 2 + 0], s);
        atomicAdd(&sacc[g * 2 + 1], q);
    }
    __syncthreads();
    if (t < 8) g_part[(size_t)row * 8 + t] = sacc[t];
}

// ------------------- cross-block stats reduce (edge & seq) ------------------
__global__ __launch_bounds__(256) void stats_reduce_kernel(int perrow, int ngroups,
                                                           float cnt) {
    __shared__ double ds[256], dq[256];
    int g = blockIdx.x, b = blockIdx.y, t = threadIdx.x;
    double s = 0.0, q = 0.0;
    for (int r = t; r < NPTS; r += 256) {
        size_t base = ((size_t)((b << 11) + r)) * perrow + g * 2;
        s += (double)g_part[base];
        q += (double)g_part[base + 1];
    }
    ds[t] = s; dq[t] = q;
    __syncthreads();
    for (int st = 128; st > 0; st >>= 1) {
        if (t < st) { ds[t] += ds[t + st]; dq[t] += dq[t + st]; }
        __syncthreads();
    }
    if (t == 0) {
        double mu = ds[0] / (double)cnt;
        double var = dq[0] / (double)cnt - mu * mu;
        g_mu[b * ngroups + g] = (float)mu;
        g_rs[b * ngroups + g] = rsqrtf((float)var + 1e-5f);
    }
}

// -------- edge final: affine+leaky of hmax/hmin (monotone), fused sq -------
__global__ void edge_final_kernel(int O, int coff,
                                  const float* __restrict__ gw,
                                  const float* __restrict__ gb) {
    __shared__ float red[256];
    int row = blockIdx.x;
    int b = row >> 11;
    int t = threadIdx.x;      // == c
    int g = t / (O >> 2);
    float mu = g_mu[b * 4 + g], rs = g_rs[b * 4 + g];
    float a = rs * gw[t];
    float b2 = gb[t] - mu * a;
    float h = (a >= 0.f) ? g_hmax[(size_t)row * O + t] : g_hmin[(size_t)row * O + t];
    float v = leaky02(a * h + b2);
    g_concat[(size_t)row * 512 + coff + t] = v;
    red[t] = v * v;
    __syncthreads();
    for (int st = O >> 1; st > 0; st >>= 1) {
        if (t < st) red[t] += red[t + st];
        __syncthreads();
    }
    if (t == 0) g_sq[row] = red[0];
}

// ------------------------------ seq GN stats --------------------------------
__global__ __launch_bounds__(256) void seq_stats_kernel() {
    __shared__ float sacc[32];
    int row = blockIdx.x;
    int t = threadIdx.x;
    if (t < 32) sacc[t] = 0.f;
    __syncthreads();
    const float* hr = g_hm + (size_t)row * 1024;
    float s = 0.f, q = 0.f;
#pragma unroll
    for (int j = 0; j < 4; j++) { float v = hr[t * 4 + j]; s += v; q += v * v; }
    s += __shfl_down_sync(0xffffffffu, s, 8, 16);
    s += __shfl_down_sync(0xffffffffu, s, 4, 16);
    s += __shfl_down_sync(0xffffffffu, s, 2, 16);
    s += __shfl_down_sync(0xffffffffu, s, 1, 16);
    q += __shfl_down_sync(0xffffffffu, q, 8, 16);
    q += __shfl_down_sync(0xffffffffu, q, 4, 16);
    q += __shfl_down_sync(0xffffffffu, q, 2, 16);
    q += __shfl_down_sync(0xffffffffu, q, 1, 16);
    int g = t >> 4;
    if ((t & 15) == 0) {
        atomicAdd(&sacc[g * 2 + 0], s);
        atomicAdd(&sacc[g * 2 + 1], q);
    }
    __syncthreads();
    if (t < 32) g_part[(size_t)row * 32 + t] = sacc[t];
}

// ------------------- seq normalize + leaky + max over N ---------------------
__global__ __launch_bounds__(256) void seq_max_part(const float* __restrict__ gmw,
                                                    const float* __restrict__ gmb) {
    int c = blockIdx.x * 256 + threadIdx.x;
    int b = blockIdx.y;
    int z = blockIdx.z;
    int g = c >> 6;
    float mu = g_mu[b * 16 + g], rs = g_rs[b * 16 + g];
    float w = gmw[c], bb = gmb[c];
    const float* col = g_hm + ((size_t)b * NPTS + z * 256) * 1024 + c;
    float m = -FINF;
#pragma unroll 4
    for (int n = 0; n < 256; n++) {
        float v = (col[(size_t)n * 1024] - mu) * rs * w + bb;
        m = fmaxf(m, leaky02(v));
    }
    g_pmax[((size_t)b * 8 + z) * 1024 + c] = m;
}

__global__ __launch_bounds__(256) void seq_max_combine() {
    int c = blockIdx.x * 256 + threadIdx.x;
    int b = blockIdx.y;
    float m = -FINF;
#pragma unroll
    for (int z = 0; z < 8; z++)
        m = fmaxf(m, g_pmax[((size_t)b * 8 + z) * 1024 + c]);
    g_gvec[b * 1024 + c] = m;
}

// --------------------------------- MLP head ---------------------------------
__device__ __forceinline__ float bsum256(float v, float* red, int t) {
    red[t] = v; __syncthreads();
    for (int s = 128; s > 0; s >>= 1) {
        if (t < s) red[t] += red[t + s];
        __syncthreads();
    }
    float r = red[0]; __syncthreads();
    return r;
}

__device__ __forceinline__ void ln_leaky(float* buf, int L,
                                         const float* __restrict__ w,
                                         const float* __restrict__ b,
                                         float* red, int t) {
    float s = 0.f, q = 0.f;
    for (int i = t; i < L; i += 256) { float v = buf[i]; s += v; q += v * v; }
    float S = bsum256(s, red, t);
    float Q = bsum256(q, red, t);
    float mu = S / (float)L;
    float var = Q / (float)L - mu * mu;
    float rs = rsqrtf(var + 1e-5f);
    for (int i = t; i < L; i += 256) {
        float v = (buf[i] - mu) * rs * w[i] + b[i];
        buf[i] = leaky02(v);
    }
    __syncthreads();
}

__global__ __launch_bounds__(256) void mlp_kernel(
    const float* __restrict__ fc1w, const float* __restrict__ fc1b,
    const float* __restrict__ ln1w, const float* __restrict__ ln1b,
    const float* __restrict__ fc2w, const float* __restrict__ fc2b,
    const float* __restrict__ ln2w, const float* __restrict__ ln2b,
    const float* __restrict__ fc3w, const float* __restrict__ fc3b,
    const float* __restrict__ ln3w, const float* __restrict__ ln3b,
    const float* __restrict__ fc4w, const float* __restrict__ fc4b,
    float* __restrict__ out)
{
    __shared__ __align__(16) float sin_[1024];
    __shared__ __align__(16) float t1[512];
    __shared__ __align__(16) float t2[256];
    __shared__ __align__(16) float t3[64];
    __shared__ float red[256];
    int b = blockIdx.x, t = threadIdx.x;
    for (int i = t; i < 1024; i += 256) sin_[i] = g_gvec[b * 1024 + i];
    __syncthreads();
    for (int o = t; o < 512; o += 256) {
        float acc = fc1b[o];
        const float4* wr = (const float4*)(fc1w + (size_t)o * 1024);
        const float4* xr = (const float4*)sin_;
        for (int c = 0; c < 256; c++) {
            float4 w4 = wr[c], x4 = xr[c];
            acc += w4.x * x4.x + w4.y * x4.y + w4.z * x4.z + w4.w * x4.w;
        }
        t1[o] = acc;
    }
    __syncthreads();
    ln_leaky(t1, 512, ln1w, ln1b, red, t);
    if (t < 256) {
        float acc = fc2b[t];
        const float4* wr = (const float4*)(fc2w + (size_t)t * 512);
        const float4* xr = (const float4*)t1;
        for (int c = 0; c < 128; c++) {
            float4 w4 = wr[c], x4 = xr[c];
            acc += w4.x * x4.x + w4.y * x4.y + w4.z * x4.z + w4.w * x4.w;
        }
        t2[t] = acc;
    }
    __syncthreads();
    ln_leaky(t2, 256, ln2w, ln2b, red, t);
    if (t < 64) {
        float acc = fc3b[t];
        const float4* wr = (const float4*)(fc3w + (size_t)t * 256);
        const float4* xr = (const float4*)t2;
        for (int c = 0; c < 64; c++) {
            float4 w4 = wr[c], x4 = xr[c];
            acc += w4.x * x4.x + w4.y * x4.y + w4.z * x4.z + w4.w * x4.w;
        }
        t3[t] = acc;
    }
    __syncthreads();
    ln_leaky(t3, 64, ln3w, ln3b, red, t);
    if (t < 2) {
        float acc = fc4b[t];
        for (int c = 0; c < 64; c++) acc += fc4w[t * 64 + c] * t3[c];
        out[b * 2 + t] = acc;
    }
}

// =============================== host driver ================================
extern "C" void kernel_launch(void* const* d_in, const int* in_sizes, int n_in,
                              void* d_out, int out_size)
{
    const float* x    = (const float*)d_in[0];
    const float* w1   = (const float*)d_in[1];
    const float* g1w  = (const float*)d_in[2];
    const float* g1b  = (const float*)d_in[3];
    const float* w2   = (const float*)d_in[4];
    const float* g2w  = (const float*)d_in[5];
    const float* g2b  = (const float*)d_in[6];
    const float* w3   = (const float*)d_in[7];
    const float* g3w  = (const float*)d_in[8];
    const float* g3b  = (const float*)d_in[9];
    const float* w4   = (const float*)d_in[10];
    const float* g4w  = (const float*)d_in[11];
    const float* g4b  = (const float*)d_in[12];
    const float* wm   = (const float*)d_in[13];
    const float* gmw  = (const float*)d_in[14];
    const float* gmb  = (const float*)d_in[15];
    const float* fc1w = (const float*)d_in[16];
    const float* fc1b = (const float*)d_in[17];
    const float* ln1w = (const float*)d_in[18];
    const float* ln1b = (const float*)d_in[19];
    const float* fc2w = (const float*)d_in[20];
    const float* fc2b = (const float*)d_in[21];
    const float* ln2w = (const float*)d_in[22];
    const float* ln2b = (const float*)d_in[23];
    const float* fc3w = (const float*)d_in[24];
    const float* fc3b = (const float*)d_in[25];
    const float* ln3w = (const float*)d_in[26];
    const float* ln3b = (const float*)d_in[27];
    const float* fc4w = (const float*)d_in[28];
    const float* fc4b = (const float*)d_in[29];
    float* out = (float*)d_out;

    float *pGram, *pConcat, *pHH, *pHm, *pWtmp;
    cudaGetSymbolAddress((void**)&pGram,   g_gram);
    cudaGetSymbolAddress((void**)&pConcat, g_concat);
    cudaGetSymbolAddress((void**)&pHH,     g_hh);
    cudaGetSymbolAddress((void**)&pHm,     g_hm);
    cudaGetSymbolAddress((void**)&pWtmp,   g_wtmp);

    // ---------------- layer 1 (C=3, O=64) ----------------------------------
    sq_kernel<<<(NROWS + 255) / 256, 256>>>(x);
    wtmp_kernel<<<(3 * 128 + 255) / 256, 256>>>(w1, 3, 64);
    hh3_kernel<<<NROWS, 128>>>(x);
    select3_kernel<<<NROWS / 4, 128>>>(x);
    edge_gather_kernel<<<NROWS, 64>>>(64);
    stats_reduce_kernel<<<dim3(4, NB), 256>>>(8, 4, (float)(NPTS * KNN * 16));
    edge_final_kernel<<<NROWS, 64>>>(64, 0, g1w, g1b);

    // ---------------- layers 2-4 ------------------------------------------
    struct LayerCfg {
        const float* X; int C; int O;
        const float* w; const float* gw; const float* gb; int coff;
    };
    LayerCfg layers[3] = {
        { pConcat + 0,   64,  64,  w2, g2w, g2b, 64  },
        { pConcat + 64,  64,  128, w3, g3w, g3b, 128 },
        { pConcat + 128, 128, 256, w4, g4w, g4b, 256 },
    };

    for (int l = 0; l < 3; l++) {
        const LayerCfg& L = layers[l];
        // per-batch Gram via tensor cores (split bf16)
        mmagemm<true><<<dim3(NPTS / 128, NPTS / 128, NB), 256>>>(
            L.X, 512, (size_t)NPTS * 512,
            L.X, 512, (size_t)NPTS * 512,
            pGram, NPTS, (size_t)NPTS * NPTS, L.C);
        select_gram_kernel<<<NROWS / 4, 128>>>();
        wtmp_kernel<<<(L.C * 2 * L.O + 255) / 256, 256>>>(L.w, L.C, L.O);
        mmagemm<false><<<dim3(2 * L.O / 128, NROWS / 128, 1), 256>>>(
            L.X, 512, 0,
            pWtmp, 2 * L.O, 0,
            pHH, 2 * L.O, 0, L.C);
        edge_gather_kernel<<<NROWS, L.O>>>(L.O);
        stats_reduce_kernel<<<dim3(4, NB), 256>>>(8, 4, (float)(NPTS * KNN * (L.O / 4)));
        edge_final_kernel<<<NROWS, L.O>>>(L.O, L.coff, L.gw, L.gb);
    }

    // mid: hm = concat @ wm^T  (16384 x 512 -> 1024) on tensor cores
    mmagemm<true><<<dim3(1024 / 128, NROWS / 128, 1), 256>>>(
        pConcat, 512, 0, wm, 512, 0, pHm, 1024, 0, 512);
    seq_stats_kernel<<<NROWS, 256>>>();
    stats_reduce_kernel<<<dim3(16, NB), 256>>>(32, 16, (float)(NPTS * 64));
    seq_max_part<<<dim3(4, NB, 8), 256>>>(gmw, gmb);
    seq_max_combine<<<dim3(4, NB), 256>>>();

    // head MLP
    mlp_kernel<<<NB, 256>>>(fc1w, fc1b, ln1w, ln1b,
                            fc2w, fc2b, ln2w, ln2b,
                            fc3w, fc3b, ln3w, ln3b,
                            fc4w, fc4b, out);
}

// round 8
// speedup vs baseline: 6.4064x; 1.1903x over previous
#include <cuda_runtime.h>
#include <cuda_bf16.h>
#include <cstdint>
#include <cstddef>

// ---------------------------------------------------------------------------
// DGCNN pipeline. B=8, N=2048, K=20.
// Round 8: round 7 (pre-split bf16 hi/lo operands, pure-bf16 HMMA GEMM)
// with the smem load-width bug fixed: 16 bf16 per thread = TWO uint4 copies
// (round 7 wrote only 8, leaving half of each tile uninitialized -> NaN).
// ---------------------------------------------------------------------------

#define NPTS   2048
#define NB     8
#define NROWS  (NB*NPTS)   // 16384
#define KNN    20
#define FINF   3.4e38f

// ------------------------- device scratch (no allocs) ----------------------
__device__ float  g_gram[(size_t)NB * NPTS * NPTS];   // reused per layer
__device__ float  g_hh[(size_t)NROWS * 512];          // [rows x 2O], hc | hn
__device__ float  g_hm[(size_t)NROWS * 1024];         // seq features
__device__ float  g_hmax[(size_t)NROWS * 256];
__device__ float  g_hmin[(size_t)NROWS * 256];
__device__ float  g_sq[NROWS];
__device__ int    g_idx[(size_t)NROWS * KNN];
__device__ float  g_wtmp[3 * 128];                    // layer-1 fp32 weights
__device__ float  g_part[(size_t)NROWS * 32];         // per-row group partials
__device__ float  g_mu[128];
__device__ float  g_rs[128];
__device__ float  g_pmax[NB * 8 * 1024];              // seq max partials
__device__ float  g_gvec[NB * 1024];
// bf16 split operands
__device__ __align__(16) __nv_bfloat16 g_ch[(size_t)NROWS * 512];   // concat hi
__device__ __align__(16) __nv_bfloat16 g_cl[(size_t)NROWS * 512];   // concat lo
__device__ __align__(16) __nv_bfloat16 g_wth[512 * 128];            // wtmp^T hi [2O][C]
__device__ __align__(16) __nv_bfloat16 g_wtl[512 * 128];            // wtmp^T lo
__device__ __align__(16) __nv_bfloat16 g_wmh[1024 * 512];           // wm hi
__device__ __align__(16) __nv_bfloat16 g_wml[1024 * 512];           // wm lo

__device__ __forceinline__ float leaky02(float v) { return v > 0.f ? v : 0.2f * v; }
__device__ __forceinline__ int   skew(int m)      { return m + (m >> 5); }
#define SD_LEN 2112

__device__ __forceinline__ void split_bf16(float v, __nv_bfloat16& h, __nv_bfloat16& l) {
    h = __float2bfloat16(v);
    l = __float2bfloat16(v - __bfloat162float(h));
}

// ------------------------------ sq kernel (layer 1 only) -------------------
__global__ void sq_kernel(const float* __restrict__ X) {
    int r = blockIdx.x * 256 + threadIdx.x;
    if (r < NROWS) {
        float a = X[r * 3], b = X[r * 3 + 1], c = X[r * 3 + 2];
        g_sq[r] = a * a + b * b + c * c;
    }
}

// ================= tensor-core GEMM: pre-split bf16, fp32 accum =============
// C[m,n] = sum_k A[m,k]*B[n,k]  (both k-major; B "transposed" layout).
// M,N multiples of 128; K multiple of 32.
__device__ __forceinline__ void mma16816(float c[4], const uint32_t a[4],
                                         const uint32_t b[2]) {
    asm volatile(
        "mma.sync.aligned.m16n8k16.row.col.f32.bf16.bf16.f32 "
        "{%0,%1,%2,%3}, {%4,%5,%6,%7}, {%8,%9}, {%0,%1,%2,%3};\n"
        : "+f"(c[0]), "+f"(c[1]), "+f"(c[2]), "+f"(c[3])
        : "r"(a[0]), "r"(a[1]), "r"(a[2]), "r"(a[3]), "r"(b[0]), "r"(b[1]));
}

#define SMS 40   // smem k-stride in u16 (32 + 8 pad)

__global__ __launch_bounds__(256, 2) void mmagemm_bf(
    const __nv_bfloat16* __restrict__ pAh, const __nv_bfloat16* __restrict__ pAl,
    int lda, size_t sA,
    const __nv_bfloat16* __restrict__ pBh, const __nv_bfloat16* __restrict__ pBl,
    int ldb, size_t sB,
    float* __restrict__ Cp, int ldc, size_t sC, int K)
{
    __shared__ __align__(16) uint16_t Ah[128 * SMS], Al[128 * SMS];
    __shared__ __align__(16) uint16_t Bh[128 * SMS], Bl[128 * SMS];
    const __nv_bfloat16* Abh = pAh + (size_t)blockIdx.z * sA;
    const __nv_bfloat16* Abl = pAl + (size_t)blockIdx.z * sA;
    const __nv_bfloat16* Bbh = pBh + (size_t)blockIdx.z * sB;
    const __nv_bfloat16* Bbl = pBl + (size_t)blockIdx.z * sB;
    float* Cb = Cp + (size_t)blockIdx.z * sC;
    const int m0 = blockIdx.y * 128, n0 = blockIdx.x * 128;
    const int tid = threadIdx.x;
    const int warp = tid >> 5, lane = tid & 31;
    const int wrm = warp >> 1, wrn = warp & 1;      // 4 x 2 warp grid
    const int g = lane >> 2, q = lane & 3;
    const int row = tid >> 1, c0 = (tid & 1) * 16;

    float acc[2][8][4];
#pragma unroll
    for (int mt = 0; mt < 2; mt++)
#pragma unroll
        for (int nt = 0; nt < 8; nt++)
#pragma unroll
            for (int j = 0; j < 4; j++) acc[mt][nt][j] = 0.f;

    for (int k0 = 0; k0 < K; k0 += 32) {
        __syncthreads();
        // 16 bf16 per thread per array = TWO uint4 copies (uint4 = 8 bf16)
        const size_t aoff = (size_t)(m0 + row) * lda + k0 + c0;
        const size_t boff = (size_t)(n0 + row) * ldb + k0 + c0;
        *(uint4*)&Ah[row * SMS + c0]     = *(const uint4*)&Abh[aoff];
        *(uint4*)&Ah[row * SMS + c0 + 8] = *(const uint4*)&Abh[aoff + 8];
        *(uint4*)&Al[row * SMS + c0]     = *(const uint4*)&Abl[aoff];
        *(uint4*)&Al[row * SMS + c0 + 8] = *(const uint4*)&Abl[aoff + 8];
        *(uint4*)&Bh[row * SMS + c0]     = *(const uint4*)&Bbh[boff];
        *(uint4*)&Bh[row * SMS + c0 + 8] = *(const uint4*)&Bbh[boff + 8];
        *(uint4*)&Bl[row * SMS + c0]     = *(const uint4*)&Bbl[boff];
        *(uint4*)&Bl[row * SMS + c0 + 8] = *(const uint4*)&Bbl[boff + 8];
        __syncthreads();

#pragma unroll
        for (int ks = 0; ks < 32; ks += 16) {
            const int cb = ks + q * 2;
            uint32_t afh[2][4], afl[2][4];
#pragma unroll
            for (int mt = 0; mt < 2; mt++) {
                int r = wrm * 32 + mt * 16 + g;
                afh[mt][0] = *(const uint32_t*)&Ah[r * SMS + cb];
                afh[mt][1] = *(const uint32_t*)&Ah[(r + 8) * SMS + cb];
                afh[mt][2] = *(const uint32_t*)&Ah[r * SMS + cb + 8];
                afh[mt][3] = *(const uint32_t*)&Ah[(r + 8) * SMS + cb + 8];
                afl[mt][0] = *(const uint32_t*)&Al[r * SMS + cb];
                afl[mt][1] = *(const uint32_t*)&Al[(r + 8) * SMS + cb];
                afl[mt][2] = *(const uint32_t*)&Al[r * SMS + cb + 8];
                afl[mt][3] = *(const uint32_t*)&Al[(r + 8) * SMS + cb + 8];
            }
#pragma unroll
            for (int nt = 0; nt < 8; nt++) {
                int n = wrn * 64 + nt * 8 + g;
                uint32_t bfh[2], bfl[2];
                bfh[0] = *(const uint32_t*)&Bh[n * SMS + cb];
                bfh[1] = *(const uint32_t*)&Bh[n * SMS + cb + 8];
                bfl[0] = *(const uint32_t*)&Bl[n * SMS + cb];
                bfl[1] = *(const uint32_t*)&Bl[n * SMS + cb + 8];
#pragma unroll
                for (int mt = 0; mt < 2; mt++) {
                    mma16816(acc[mt][nt], afh[mt], bfh);
                    mma16816(acc[mt][nt], afh[mt], bfl);
                    mma16816(acc[mt][nt], afl[mt], bfh);
                }
            }
        }
    }

#pragma unroll
    for (int mt = 0; mt < 2; mt++) {
        int r0 = m0 + wrm * 32 + mt * 16 + g;
#pragma unroll
        for (int nt = 0; nt < 8; nt++) {
            int cc = n0 + wrn * 64 + nt * 8 + q * 2;
            *(float2*)&Cb[(size_t)r0 * ldc + cc] =
                make_float2(acc[mt][nt][0], acc[mt][nt][1]);
            *(float2*)&Cb[(size_t)(r0 + 8) * ldc + cc] =
                make_float2(acc[mt][nt][2], acc[mt][nt][3]);
        }
    }
}

// -------------------- warp-per-query top-20, skewed smem --------------------
__device__ __forceinline__ void topk_from_smem(float* sd, int row, int lane,
                                               float bv, int bi) {
#pragma unroll 1
    for (int it = 0; it < KNN; it++) {
        float v = bv; int idx = bi;
#pragma unroll
        for (int off = 16; off > 0; off >>= 1) {
            float v2 = __shfl_xor_sync(0xffffffffu, v, off);
            int   i2 = __shfl_xor_sync(0xffffffffu, idx, off);
            if (v2 < v || (v2 == v && i2 < idx)) { v = v2; idx = i2; }
        }
        if (lane == 0) {
            g_idx[(size_t)row * KNN + it] = idx;
            sd[skew(idx)] = FINF;
        }
        __syncwarp();
        int wl = idx & 31;
        float rv = FINF; int rb = 0x7fffffff;
#pragma unroll
        for (int q = 0; q < 2; q++) {
            int m = wl + 32 * (2 * lane + q);
            float d = sd[skew(m)];
            if (d < rv || (d == rv && m < rb)) { rv = d; rb = m; }
        }
#pragma unroll
        for (int off = 16; off > 0; off >>= 1) {
            float v2 = __shfl_xor_sync(0xffffffffu, rv, off);
            int   i2 = __shfl_xor_sync(0xffffffffu, rb, off);
            if (v2 < rv || (v2 == rv && i2 < rb)) { rv = v2; rb = i2; }
        }
        if (lane == wl) { bv = rv; bi = rb; }
    }
}

__global__ __launch_bounds__(128) void select_gram_kernel() {
    __shared__ float sd[4][SD_LEN];
    int warp = threadIdx.x >> 5, lane = threadIdx.x & 31;
    int row = blockIdx.x * 4 + warp;
    int b = row >> 11, n = row & 2047;
    const float* drow = g_gram + (size_t)b * NPTS * NPTS + (size_t)n * NPTS;
    float sqn = g_sq[row];
    float* sdw = sd[warp];
    float bv = FINF; int bi = 0x7fffffff;
#pragma unroll 8
    for (int j = 0; j < 64; j++) {
        int m = lane + 32 * j;
        float d = sqn + g_sq[(b << 11) + m] - 2.f * drow[m];
        if (m == n) d = FINF;
        sdw[skew(m)] = d;
        if (d < bv || (d == bv && m < bi)) { bv = d; bi = m; }
    }
    __syncwarp();
    topk_from_smem(sdw, row, lane, bv, bi);
}

__global__ __launch_bounds__(128) void select3_kernel(const float* __restrict__ X) {
    __shared__ float sd[4][SD_LEN];
    int warp = threadIdx.x >> 5, lane = threadIdx.x & 31;
    int row = blockIdx.x * 4 + warp;
    int b = row >> 11, n = row & 2047;
    const float* Xb = X + (size_t)(b << 11) * 3;
    float xn = Xb[n * 3], yn = Xb[n * 3 + 1], zn = Xb[n * 3 + 2];
    float sqn = g_sq[row];
    float* sdw = sd[warp];
    float bv = FINF; int bi = 0x7fffffff;
#pragma unroll 4
    for (int j = 0; j < 64; j++) {
        int m = lane + 32 * j;
        float px = Xb[m * 3], py = Xb[m * 3 + 1], pz = Xb[m * 3 + 2];
        float dot = xn * px + yn * py + zn * pz;
        float d = sqn + g_sq[(b << 11) + m] - 2.f * dot;
        if (m == n) d = FINF;
        sdw[skew(m)] = d;
        if (d < bv || (d == bv && m < bi)) { bv = d; bi = m; }
    }
    __syncwarp();
    topk_from_smem(sdw, row, lane, bv, bi);
}

// ------------------- weight transforms (pre-split bf16) --------------------
__global__ void wtmp_kernel(const float* __restrict__ w, int C, int O) {
    int i = blockIdx.x * 256 + threadIdx.x;
    int tot = C * 2 * O;
    if (i < tot) {
        int c = i / (2 * O);
        int o = i % (2 * O);
        float v;
        if (o < O) v = w[(size_t)o * (2 * C) + c] - w[(size_t)o * (2 * C) + C + c];
        else       v = w[(size_t)(o - O) * (2 * C) + C + c];
        g_wtmp[i] = v;
    }
}

// layers 2-4: transposed [2O][C], bf16 hi/lo
__global__ void wtmp_bf_kernel(const float* __restrict__ w, int C, int O) {
    int i = blockIdx.x * 256 + threadIdx.x;
    int tot = 2 * O * C;
    if (i < tot) {
        int o = i / C;
        int c = i % C;
        float v;
        if (o < O) v = w[(size_t)o * (2 * C) + c] - w[(size_t)o * (2 * C) + C + c];
        else       v = w[(size_t)(o - O) * (2 * C) + C + c];
        __nv_bfloat16 h, l; split_bf16(v, h, l);
        g_wth[i] = h; g_wtl[i] = l;
    }
}

__global__ void wm_conv_kernel(const float* __restrict__ wm) {
    int i = blockIdx.x * 256 + threadIdx.x;   // 1024*512
    float v = wm[i];
    __nv_bfloat16 h, l; split_bf16(v, h, l);
    g_wmh[i] = h; g_wml[i] = l;
}

// ----------------------- layer-1 hh (K=3 feature GEMM) ---------------------
__global__ void hh3_kernel(const float* __restrict__ X) {
    __shared__ float w[3 * 128];
    int row = blockIdx.x;
    int t = threadIdx.x;   // 128
    w[t] = g_wtmp[t]; w[128 + t] = g_wtmp[128 + t]; w[256 + t] = g_wtmp[256 + t];
    __syncthreads();
    float x0 = X[row * 3], x1 = X[row * 3 + 1], x2 = X[row * 3 + 2];
    g_hh[(size_t)row * 128 + t] = x0 * w[t] + x1 * w[128 + t] + x2 * w[256 + t];
}

// ------------------- fused edge gather: stats + hmax/hmin -------------------
__global__ void edge_gather_kernel(int O) {
    __shared__ int   sidx[KNN];
    __shared__ float sacc[8];
    int row = blockIdx.x;
    int b = row >> 11;
    int t = threadIdx.x;     // == c
    if (t < KNN) sidx[t] = g_idx[(size_t)row * KNN + t];
    if (t < 8) sacc[t] = 0.f;
    __syncthreads();
    int twoO = 2 * O;
    float hcv = g_hh[(size_t)row * twoO + t];
    size_t bbase = ((size_t)(b << 11)) * twoO + O + t;
    float s = 0.f, q = 0.f, mx = -FINF, mn = FINF;
#pragma unroll
    for (int k = 0; k < KNN; k++) {
        float h = hcv + g_hh[bbase + (size_t)sidx[k] * twoO];
        s += h; q += h * h;
        mx = fmaxf(mx, h); mn = fminf(mn, h);
    }
    g_hmax[(size_t)row * O + t] = mx;
    g_hmin[(size_t)row * O + t] = mn;
    int gsz = O >> 2;
    int rw = gsz < 32 ? gsz : 32;
#pragma unroll
    for (int off = 16; off > 0; off >>= 1) {
        if (off < rw) {
            s += __shfl_down_sync(0xffffffffu, s, off, 32);
            q += __shfl_down_sync(0xffffffffu, q, off, 32);
        }
    }
    int g = t / gsz;
    if ((t & (rw - 1)) == 0) {
        atomicAdd(&sacc[g * 2 + 0], s);
        atomicAdd(&sacc[g * 2 + 1], q);
    }
    __syncthreads();
    if (t < 8) g_part[(size_t)row * 8 + t] = sacc[t];
}

// ------------------- cross-block stats reduce (edge & seq) ------------------
__global__ __launch_bounds__(256) void stats_reduce_kernel(int perrow, int ngroups,
                                                           float cnt) {
    __shared__ double ds[256], dq[256];
    int g = blockIdx.x, b = blockIdx.y, t = threadIdx.x;
    double s = 0.0, q = 0.0;
    for (int r = t; r < NPTS; r += 256) {
        size_t base = ((size_t)((b << 11) + r)) * perrow + g * 2;
        s += (double)g_part[base];
        q += (double)g_part[base + 1];
    }
    ds[t] = s; dq[t] = q;
    __syncthreads();
    for (int st = 128; st > 0; st >>= 1) {
        if (t < st) { ds[t] += ds[t + st]; dq[t] += dq[t + st]; }
        __syncthreads();
    }
    if (t == 0) {
        double mu = ds[0] / (double)cnt;
        double var = dq[0] / (double)cnt - mu * mu;
        g_mu[b * ngroups + g] = (float)mu;
        g_rs[b * ngroups + g] = rsqrtf((float)var + 1e-5f);
    }
}

// ---- edge final: affine+leaky of hmax/hmin; writes bf16 hi/lo + fused sq ---
__global__ void edge_final_kernel(int O, int coff,
                                  const float* __restrict__ gw,
                                  const float* __restrict__ gb) {
    __shared__ float red[256];
    int row = blockIdx.x;
    int b = row >> 11;
    int t = threadIdx.x;      // == c
    int g = t / (O >> 2);
    float mu = g_mu[b * 4 + g], rs = g_rs[b * 4 + g];
    float a = rs * gw[t];
    float b2 = gb[t] - mu * a;
    float h = (a >= 0.f) ? g_hmax[(size_t)row * O + t] : g_hmin[(size_t)row * O + t];
    float v = leaky02(a * h + b2);
    __nv_bfloat16 vh, vl; split_bf16(v, vh, vl);
    g_ch[(size_t)row * 512 + coff + t] = vh;
    g_cl[(size_t)row * 512 + coff + t] = vl;
    red[t] = v * v;
    __syncthreads();
    for (int st = O >> 1; st > 0; st >>= 1) {
        if (t < st) red[t] += red[t + st];
        __syncthreads();
    }
    if (t == 0) g_sq[row] = red[0];
}

// ------------------------------ seq GN stats --------------------------------
__global__ __launch_bounds__(256) void seq_stats_kernel() {
    __shared__ float sacc[32];
    int row = blockIdx.x;
    int t = threadIdx.x;
    if (t < 32) sacc[t] = 0.f;
    __syncthreads();
    const float* hr = g_hm + (size_t)row * 1024;
    float s = 0.f, q = 0.f;
#pragma unroll
    for (int j = 0; j < 4; j++) { float v = hr[t * 4 + j]; s += v; q += v * v; }
    s += __shfl_down_sync(0xffffffffu, s, 8, 16);
    s += __shfl_down_sync(0xffffffffu, s, 4, 16);
    s += __shfl_down_sync(0xffffffffu, s, 2, 16);
    s += __shfl_down_sync(0xffffffffu, s, 1, 16);
    q += __shfl_down_sync(0xffffffffu, q, 8, 16);
    q += __shfl_down_sync(0xffffffffu, q, 4, 16);
    q += __shfl_down_sync(0xffffffffu, q, 2, 16);
    q += __shfl_down_sync(0xffffffffu, q, 1, 16);
    int g = t >> 4;
    if ((t & 15) == 0) {
        atomicAdd(&sacc[g * 2 + 0], s);
        atomicAdd(&sacc[g * 2 + 1], q);
    }
    __syncthreads();
    if (t < 32) g_part[(size_t)row * 32 + t] = sacc[t];
}

// ------------------- seq normalize + leaky + max over N ---------------------
__global__ __launch_bounds__(256) void seq_max_part(const float* __restrict__ gmw,
                                                    const float* __restrict__ gmb) {
    int c = blockIdx.x * 256 + threadIdx.x;
    int b = blockIdx.y;
    int z = blockIdx.z;
    int g = c >> 6;
    float mu = g_mu[b * 16 + g], rs = g_rs[b * 16 + g];
    float w = gmw[c], bb = gmb[c];
    const float* col = g_hm + ((size_t)b * NPTS + z * 256) * 1024 + c;
    float m = -FINF;
#pragma unroll 4
    for (int n = 0; n < 256; n++) {
        float v = (col[(size_t)n * 1024] - mu) * rs * w + bb;
        m = fmaxf(m, leaky02(v));
    }
    g_pmax[((size_t)b * 8 + z) * 1024 + c] = m;
}

__global__ __launch_bounds__(256) void seq_max_combine() {
    int c = blockIdx.x * 256 + threadIdx.x;
    int b = blockIdx.y;
    float m = -FINF;
#pragma unroll
    for (int z = 0; z < 8; z++)
        m = fmaxf(m, g_pmax[((size_t)b * 8 + z) * 1024 + c]);
    g_gvec[b * 1024 + c] = m;
}

// --------------------------------- MLP head ---------------------------------
__device__ __forceinline__ float bsum256(float v, float* red, int t) {
    red[t] = v; __syncthreads();
    for (int s = 128; s > 0; s >>= 1) {
        if (t < s) red[t] += red[t + s];
        __syncthreads();
    }
    float r = red[0]; __syncthreads();
    return r;
}

__device__ __forceinline__ void ln_leaky(float* buf, int L,
                                         const float* __restrict__ w,
                                         const float* __restrict__ b,
                                         float* red, int t) {
    float s = 0.f, q = 0.f;
    for (int i = t; i < L; i += 256) { float v = buf[i]; s += v; q += v * v; }
    float S = bsum256(s, red, t);
    float Q = bsum256(q, red, t);
    float mu = S / (float)L;
    float var = Q / (float)L - mu * mu;
    float rs = rsqrtf(var + 1e-5f);
    for (int i = t; i < L; i += 256) {
        float v = (buf[i] - mu) * rs * w[i] + b[i];
        buf[i] = leaky02(v);
    }
    __syncthreads();
}

__global__ __launch_bounds__(256) void mlp_kernel(
    const float* __restrict__ fc1w, const float* __restrict__ fc1b,
    const float* __restrict__ ln1w, const float* __restrict__ ln1b,
    const float* __restrict__ fc2w, const float* __restrict__ fc2b,
    const float* __restrict__ ln2w, const float* __restrict__ ln2b,
    const float* __restrict__ fc3w, const float* __restrict__ fc3b,
    const float* __restrict__ ln3w, const float* __restrict__ ln3b,
    const float* __restrict__ fc4w, const float* __restrict__ fc4b,
    float* __restrict__ out)
{
    __shared__ __align__(16) float sin_[1024];
    __shared__ __align__(16) float t1[512];
    __shared__ __align__(16) float t2[256];
    __shared__ __align__(16) float t3[64];
    __shared__ float red[256];
    int b = blockIdx.x, t = threadIdx.x;
    for (int i = t; i < 1024; i += 256) sin_[i] = g_gvec[b * 1024 + i];
    __syncthreads();
    for (int o = t; o < 512; o += 256) {
        float acc = fc1b[o];
        const float4* wr = (const float4*)(fc1w + (size_t)o * 1024);
        const float4* xr = (const float4*)sin_;
        for (int c = 0; c < 256; c++) {
            float4 w4 = wr[c], x4 = xr[c];
            acc += w4.x * x4.x + w4.y * x4.y + w4.z * x4.z + w4.w * x4.w;
        }
        t1[o] = acc;
    }
    __syncthreads();
    ln_leaky(t1, 512, ln1w, ln1b, red, t);
    if (t < 256) {
        float acc = fc2b[t];
        const float4* wr = (const float4*)(fc2w + (size_t)t * 512);
        const float4* xr = (const float4*)t1;
        for (int c = 0; c < 128; c++) {
            float4 w4 = wr[c], x4 = xr[c];
            acc += w4.x * x4.x + w4.y * x4.y + w4.z * x4.z + w4.w * x4.w;
        }
        t2[t] = acc;
    }
    __syncthreads();
    ln_leaky(t2, 256, ln2w, ln2b, red, t);
    if (t < 64) {
        float acc = fc3b[t];
        const float4* wr = (const float4*)(fc3w + (size_t)t * 256);
        const float4* xr = (const float4*)t2;
        for (int c = 0; c < 64; c++) {
            float4 w4 = wr[c], x4 = xr[c];
            acc += w4.x * x4.x + w4.y * x4.y + w4.z * x4.z + w4.w * x4.w;
        }
        t3[t] = acc;
    }
    __syncthreads();
    ln_leaky(t3, 64, ln3w, ln3b, red, t);
    if (t < 2) {
        float acc = fc4b[t];
        for (int c = 0; c < 64; c++) acc += fc4w[t * 64 + c] * t3[c];
        out[b * 2 + t] = acc;
    }
}

// =============================== host driver ================================
extern "C" void kernel_launch(void* const* d_in, const int* in_sizes, int n_in,
                              void* d_out, int out_size)
{
    const float* x    = (const float*)d_in[0];
    const float* w1   = (const float*)d_in[1];
    const float* g1w  = (const float*)d_in[2];
    const float* g1b  = (const float*)d_in[3];
    const float* w2   = (const float*)d_in[4];
    const float* g2w  = (const float*)d_in[5];
    const float* g2b  = (const float*)d_in[6];
    const float* w3   = (const float*)d_in[7];
    const float* g3w  = (const float*)d_in[8];
    const float* g3b  = (const float*)d_in[9];
    const float* w4   = (const float*)d_in[10];
    const float* g4w  = (const float*)d_in[11];
    const float* g4b  = (const float*)d_in[12];
    const float* wm   = (const float*)d_in[13];
    const float* gmw  = (const float*)d_in[14];
    const float* gmb  = (const float*)d_in[15];
    const float* fc1w = (const float*)d_in[16];
    const float* fc1b = (const float*)d_in[17];
    const float* ln1w = (const float*)d_in[18];
    const float* ln1b = (const float*)d_in[19];
    const float* fc2w = (const float*)d_in[20];
    const float* fc2b = (const float*)d_in[21];
    const float* ln2w = (const float*)d_in[22];
    const float* ln2b = (const float*)d_in[23];
    const float* fc3w = (const float*)d_in[24];
    const float* fc3b = (const float*)d_in[25];
    const float* ln3w = (const float*)d_in[26];
    const float* ln3b = (const float*)d_in[27];
    const float* fc4w = (const float*)d_in[28];
    const float* fc4b = (const float*)d_in[29];
    float* out = (float*)d_out;

    float *pGram, *pHH, *pHm;
    __nv_bfloat16 *pCh, *pCl, *pWth, *pWtl, *pWmh, *pWml;
    cudaGetSymbolAddress((void**)&pGram, g_gram);
    cudaGetSymbolAddress((void**)&pHH,   g_hh);
    cudaGetSymbolAddress((void**)&pHm,   g_hm);
    cudaGetSymbolAddress((void**)&pCh,   g_ch);
    cudaGetSymbolAddress((void**)&pCl,   g_cl);
    cudaGetSymbolAddress((void**)&pWth,  g_wth);
    cudaGetSymbolAddress((void**)&pWtl,  g_wtl);
    cudaGetSymbolAddress((void**)&pWmh,  g_wmh);
    cudaGetSymbolAddress((void**)&pWml,  g_wml);

    // weight prep (independent of pipeline; run first)
    wm_conv_kernel<<<(1024 * 512) / 256, 256>>>(wm);

    // ---------------- layer 1 (C=3, O=64) ----------------------------------
    sq_kernel<<<(NROWS + 255) / 256, 256>>>(x);
    wtmp_kernel<<<(3 * 128 + 255) / 256, 256>>>(w1, 3, 64);
    hh3_kernel<<<NROWS, 128>>>(x);
    select3_kernel<<<NROWS / 4, 128>>>(x);
    edge_gather_kernel<<<NROWS, 64>>>(64);
    stats_reduce_kernel<<<dim3(4, NB), 256>>>(8, 4, (float)(NPTS * KNN * 16));
    edge_final_kernel<<<NROWS, 64>>>(64, 0, g1w, g1b);

    // ---------------- layers 2-4 ------------------------------------------
    struct LayerCfg {
        int coffin;   // input slice offset in g_ch/g_cl
        int C; int O;
        const float* w; const float* gw; const float* gb; int coff;
    };
    LayerCfg layers[3] = {
        { 0,   64,  64,  w2, g2w, g2b, 64  },
        { 64,  64,  128, w3, g3w, g3b, 128 },
        { 128, 128, 256, w4, g4w, g4b, 256 },
    };

    for (int l = 0; l < 3; l++) {
        const LayerCfg& L = layers[l];
        // per-batch Gram via tensor cores (pre-split bf16)
        mmagemm_bf<<<dim3(NPTS / 128, NPTS / 128, NB), 256>>>(
            pCh + L.coffin, pCl + L.coffin, 512, (size_t)NPTS * 512,
            pCh + L.coffin, pCl + L.coffin, 512, (size_t)NPTS * 512,
            pGram, NPTS, (size_t)NPTS * NPTS, L.C);
        select_gram_kernel<<<NROWS / 4, 128>>>();
        wtmp_bf_kernel<<<(2 * L.O * L.C + 255) / 256, 256>>>(L.w, L.C, L.O);
        mmagemm_bf<<<dim3(2 * L.O / 128, NROWS / 128, 1), 256>>>(
            pCh + L.coffin, pCl + L.coffin, 512, 0,
            pWth, pWtl, L.C, 0,
            pHH, 2 * L.O, 0, L.C);
        edge_gather_kernel<<<NROWS, L.O>>>(L.O);
        stats_reduce_kernel<<<dim3(4, NB), 256>>>(8, 4, (float)(NPTS * KNN * (L.O / 4)));
        edge_final_kernel<<<NROWS, L.O>>>(L.O, L.coff, L.gw, L.gb);
    }

    // mid: hm = concat @ wm^T  (16384 x 512 -> 1024)
    mmagemm_bf<<<dim3(1024 / 128, NROWS / 128, 1), 256>>>(
        pCh, pCl, 512, 0, pWmh, pWml, 512, 0, pHm, 1024, 0, 512);
    seq_stats_kernel<<<NROWS, 256>>>();
    stats_reduce_kernel<<<dim3(16, NB), 256>>>(32, 16, (float)(NPTS * 64));
    seq_max_part<<<dim3(4, NB, 8), 256>>>(gmw, gmb);
    seq_max_combine<<<dim3(4, NB), 256>>>();

    // head MLP
    mlp_kernel<<<NB, 256>>>(fc1w, fc1b, ln1w, ln1b,
                            fc2w, fc2b, ln2w, ln2b,
                            fc3w, fc3b, ln3w, ln3b,
                            fc4w, fc4b, out);
}

// round 9
// speedup vs baseline: 7.0720x; 1.1039x over previous
#include <cuda_runtime.h>
#include <cuda_bf16.h>
#include <cstdint>
#include <cstddef>

// ---------------------------------------------------------------------------
// DGCNN pipeline. B=8, N=2048, K=20.
// Round 9: GEMM upgrades only —
//   (a) symmetric Gram: compute 136/256 tiles, mirror in epilogue
//   (b) cp.async double-buffered smem pipeline (overlap loads with HMMA)
// Everything else as round 8 (pre-split bf16 hi/lo, fused gather, etc).
// ---------------------------------------------------------------------------

#define NPTS   2048
#define NB     8
#define NROWS  (NB*NPTS)   // 16384
#define KNN    20
#define FINF   3.4e38f

// ------------------------- device scratch (no allocs) ----------------------
__device__ float  g_gram[(size_t)NB * NPTS * NPTS];   // reused per layer
__device__ float  g_hh[(size_t)NROWS * 512];          // [rows x 2O], hc | hn
__device__ float  g_hm[(size_t)NROWS * 1024];         // seq features
__device__ float  g_hmax[(size_t)NROWS * 256];
__device__ float  g_hmin[(size_t)NROWS * 256];
__device__ float  g_sq[NROWS];
__device__ int    g_idx[(size_t)NROWS * KNN];
__device__ float  g_wtmp[3 * 128];                    // layer-1 fp32 weights
__device__ float  g_part[(size_t)NROWS * 32];         // per-row group partials
__device__ float  g_mu[128];
__device__ float  g_rs[128];
__device__ float  g_pmax[NB * 8 * 1024];              // seq max partials
__device__ float  g_gvec[NB * 1024];
// bf16 split operands
__device__ __align__(16) __nv_bfloat16 g_ch[(size_t)NROWS * 512];   // concat hi
__device__ __align__(16) __nv_bfloat16 g_cl[(size_t)NROWS * 512];   // concat lo
__device__ __align__(16) __nv_bfloat16 g_wth[512 * 128];            // wtmp^T hi [2O][C]
__device__ __align__(16) __nv_bfloat16 g_wtl[512 * 128];            // wtmp^T lo
__device__ __align__(16) __nv_bfloat16 g_wmh[1024 * 512];           // wm hi
__device__ __align__(16) __nv_bfloat16 g_wml[1024 * 512];           // wm lo

__device__ __forceinline__ float leaky02(float v) { return v > 0.f ? v : 0.2f * v; }
__device__ __forceinline__ int   skew(int m)      { return m + (m >> 5); }
#define SD_LEN 2112

__device__ __forceinline__ void split_bf16(float v, __nv_bfloat16& h, __nv_bfloat16& l) {
    h = __float2bfloat16(v);
    l = __float2bfloat16(v - __bfloat162float(h));
}

// --------------------------- cp.async helpers -------------------------------
__device__ __forceinline__ void cp16(void* smem, const void* g) {
    uint32_t s = (uint32_t)__cvta_generic_to_shared(smem);
    asm volatile("cp.async.cg.shared.global [%0], [%1], 16;" :: "r"(s), "l"(g));
}
__device__ __forceinline__ void cp_commit() {
    asm volatile("cp.async.commit_group;");
}
template <int N>
__device__ __forceinline__ void cp_wait() {
    asm volatile("cp.async.wait_group %0;" :: "n"(N));
}

// ------------------------------ sq kernel (layer 1 only) -------------------
__global__ void sq_kernel(const float* __restrict__ X) {
    int r = blockIdx.x * 256 + threadIdx.x;
    if (r < NROWS) {
        float a = X[r * 3], b = X[r * 3 + 1], c = X[r * 3 + 2];
        g_sq[r] = a * a + b * b + c * c;
    }
}

// ================= tensor-core GEMM: pre-split bf16, fp32 accum =============
// C[m,n] = sum_k A[m,k]*B[n,k]  (both k-major). M,N mult of 128; K mult of 32.
// SYM: A==B (Gram); grid.x = triangular tile index; mirrored epilogue.
__device__ __forceinline__ void mma16816(float c[4], const uint32_t a[4],
                                         const uint32_t b[2]) {
    asm volatile(
        "mma.sync.aligned.m16n8k16.row.col.f32.bf16.bf16.f32 "
        "{%0,%1,%2,%3}, {%4,%5,%6,%7}, {%8,%9}, {%0,%1,%2,%3};\n"
        : "+f"(c[0]), "+f"(c[1]), "+f"(c[2]), "+f"(c[3])
        : "r"(a[0]), "r"(a[1]), "r"(a[2]), "r"(a[3]), "r"(b[0]), "r"(b[1]));
}

#define SMS 40                 // smem k-stride in u16 (32 + 8 pad, conflict-free)
#define STAGE_U16 (4 * 128 * SMS)   // Ah|Al|Bh|Bl per stage = 20480 u16 = 40KB
#define GEMM_SMEM (2 * STAGE_U16 * 2)  // bytes: 81920

template <bool SYM>
__global__ __launch_bounds__(256, 2) void mmagemm_bf(
    const __nv_bfloat16* __restrict__ pAh, const __nv_bfloat16* __restrict__ pAl,
    int lda, size_t sA,
    const __nv_bfloat16* __restrict__ pBh, const __nv_bfloat16* __restrict__ pBl,
    int ldb, size_t sB,
    float* __restrict__ Cp, int ldc, size_t sC, int K)
{
    extern __shared__ __align__(16) uint16_t dyn[];
    const __nv_bfloat16* Abh = pAh + (size_t)blockIdx.z * sA;
    const __nv_bfloat16* Abl = pAl + (size_t)blockIdx.z * sA;
    const __nv_bfloat16* Bbh = pBh + (size_t)blockIdx.z * sB;
    const __nv_bfloat16* Bbl = pBl + (size_t)blockIdx.z * sB;
    float* Cb = Cp + (size_t)blockIdx.z * sC;

    int m0, n0;
    if (SYM) {
        // triangular tile index -> (bx >= by); m-tile = by, n-tile = bx
        int i = blockIdx.x;
        int bx = (int)((sqrtf(8.f * (float)i + 1.f) - 1.f) * 0.5f);
        while ((bx + 1) * (bx + 2) / 2 <= i) bx++;
        while (bx * (bx + 1) / 2 > i) bx--;
        int by = i - bx * (bx + 1) / 2;
        m0 = by * 128; n0 = bx * 128;
    } else {
        m0 = blockIdx.y * 128; n0 = blockIdx.x * 128;
    }

    const int tid = threadIdx.x;
    const int warp = tid >> 5, lane = tid & 31;
    const int wrm = warp >> 1, wrn = warp & 1;      // 4 x 2 warp grid
    const int g = lane >> 2, q = lane & 3;
    const int row = tid >> 1, c0 = (tid & 1) * 16;

    float acc[2][8][4];
#pragma unroll
    for (int mt = 0; mt < 2; mt++)
#pragma unroll
        for (int nt = 0; nt < 8; nt++)
#pragma unroll
            for (int j = 0; j < 4; j++) acc[mt][nt][j] = 0.f;

    const int nk = K >> 5;

    // async stage loader: 8 x 16B per thread
    auto load_stage = [&](int st, int k0) {
        uint16_t* S  = dyn + st * STAGE_U16;
        uint16_t* Ah = S;
        uint16_t* Al = S + 128 * SMS;
        uint16_t* Bh = S + 2 * 128 * SMS;
        uint16_t* Bl = S + 3 * 128 * SMS;
        const size_t aoff = (size_t)(m0 + row) * lda + k0 + c0;
        const size_t boff = (size_t)(n0 + row) * ldb + k0 + c0;
        cp16(&Ah[row * SMS + c0],     &Abh[aoff]);
        cp16(&Ah[row * SMS + c0 + 8], &Abh[aoff + 8]);
        cp16(&Al[row * SMS + c0],     &Abl[aoff]);
        cp16(&Al[row * SMS + c0 + 8], &Abl[aoff + 8]);
        cp16(&Bh[row * SMS + c0],     &Bbh[boff]);
        cp16(&Bh[row * SMS + c0 + 8], &Bbh[boff + 8]);
        cp16(&Bl[row * SMS + c0],     &Bbl[boff]);
        cp16(&Bl[row * SMS + c0 + 8], &Bbl[boff + 8]);
        cp_commit();
    };

    load_stage(0, 0);

    for (int kc = 0; kc < nk; kc++) {
        if (kc + 1 < nk) {
            load_stage((kc + 1) & 1, (kc + 1) << 5);
            cp_wait<1>();                 // oldest (current stage) complete
        } else {
            cp_wait<0>();
        }
        __syncthreads();

        uint16_t* S  = dyn + (kc & 1) * STAGE_U16;
        uint16_t* Ah = S;
        uint16_t* Al = S + 128 * SMS;
        uint16_t* Bh = S + 2 * 128 * SMS;
        uint16_t* Bl = S + 3 * 128 * SMS;

#pragma unroll
        for (int ks = 0; ks < 32; ks += 16) {
            const int cb = ks + q * 2;
            uint32_t afh[2][4], afl[2][4];
#pragma unroll
            for (int mt = 0; mt < 2; mt++) {
                int r = wrm * 32 + mt * 16 + g;
                afh[mt][0] = *(const uint32_t*)&Ah[r * SMS + cb];
                afh[mt][1] = *(const uint32_t*)&Ah[(r + 8) * SMS + cb];
                afh[mt][2] = *(const uint32_t*)&Ah[r * SMS + cb + 8];
                afh[mt][3] = *(const uint32_t*)&Ah[(r + 8) * SMS + cb + 8];
                afl[mt][0] = *(const uint32_t*)&Al[r * SMS + cb];
                afl[mt][1] = *(const uint32_t*)&Al[(r + 8) * SMS + cb];
                afl[mt][2] = *(const uint32_t*)&Al[r * SMS + cb + 8];
                afl[mt][3] = *(const uint32_t*)&Al[(r + 8) * SMS + cb + 8];
            }
#pragma unroll
            for (int nt = 0; nt < 8; nt++) {
                int n = wrn * 64 + nt * 8 + g;
                uint32_t bfh[2], bfl[2];
                bfh[0] = *(const uint32_t*)&Bh[n * SMS + cb];
                bfh[1] = *(const uint32_t*)&Bh[n * SMS + cb + 8];
                bfl[0] = *(const uint32_t*)&Bl[n * SMS + cb];
                bfl[1] = *(const uint32_t*)&Bl[n * SMS + cb + 8];
#pragma unroll
                for (int mt = 0; mt < 2; mt++) {
                    mma16816(acc[mt][nt], afh[mt], bfh);
                    mma16816(acc[mt][nt], afh[mt], bfl);
                    mma16816(acc[mt][nt], afl[mt], bfh);
                }
            }
        }
        __syncthreads();   // protect this stage before it is overwritten
    }

    // ---- epilogue ----
#pragma unroll
    for (int mt = 0; mt < 2; mt++) {
        int r0 = m0 + wrm * 32 + mt * 16 + g;
#pragma unroll
        for (int nt = 0; nt < 8; nt++) {
            int cc = n0 + wrn * 64 + nt * 8 + q * 2;
            *(float2*)&Cb[(size_t)r0 * ldc + cc] =
                make_float2(acc[mt][nt][0], acc[mt][nt][1]);
            *(float2*)&Cb[(size_t)(r0 + 8) * ldc + cc] =
                make_float2(acc[mt][nt][2], acc[mt][nt][3]);
            if (SYM && n0 != m0) {
                Cb[(size_t)cc * ldc + r0]           = acc[mt][nt][0];
                Cb[(size_t)(cc + 1) * ldc + r0]     = acc[mt][nt][1];
                Cb[(size_t)cc * ldc + r0 + 8]       = acc[mt][nt][2];
                Cb[(size_t)(cc + 1) * ldc + r0 + 8] = acc[mt][nt][3];
            }
        }
    }
}

// -------------------- warp-per-query top-20, skewed smem --------------------
__device__ __forceinline__ void topk_from_smem(float* sd, int row, int lane,
                                               float bv, int bi) {
#pragma unroll 1
    for (int it = 0; it < KNN; it++) {
        float v = bv; int idx = bi;
#pragma unroll
        for (int off = 16; off > 0; off >>= 1) {
            float v2 = __shfl_xor_sync(0xffffffffu, v, off);
            int   i2 = __shfl_xor_sync(0xffffffffu, idx, off);
            if (v2 < v || (v2 == v && i2 < idx)) { v = v2; idx = i2; }
        }
        if (lane == 0) {
            g_idx[(size_t)row * KNN + it] = idx;
            sd[skew(idx)] = FINF;
        }
        __syncwarp();
        int wl = idx & 31;
        float rv = FINF; int rb = 0x7fffffff;
#pragma unroll
        for (int q = 0; q < 2; q++) {
            int m = wl + 32 * (2 * lane + q);
            float d = sd[skew(m)];
            if (d < rv || (d == rv && m < rb)) { rv = d; rb = m; }
        }
#pragma unroll
        for (int off = 16; off > 0; off >>= 1) {
            float v2 = __shfl_xor_sync(0xffffffffu, rv, off);
            int   i2 = __shfl_xor_sync(0xffffffffu, rb, off);
            if (v2 < rv || (v2 == rv && i2 < rb)) { rv = v2; rb = i2; }
        }
        if (lane == wl) { bv = rv; bi = rb; }
    }
}

__global__ __launch_bounds__(128) void select_gram_kernel() {
    __shared__ float sd[4][SD_LEN];
    int warp = threadIdx.x >> 5, lane = threadIdx.x & 31;
    int row = blockIdx.x * 4 + warp;
    int b = row >> 11, n = row & 2047;
    const float* drow = g_gram + (size_t)b * NPTS * NPTS + (size_t)n * NPTS;
    float sqn = g_sq[row];
    float* sdw = sd[warp];
    float bv = FINF; int bi = 0x7fffffff;
#pragma unroll 8
    for (int j = 0; j < 64; j++) {
        int m = lane + 32 * j;
        float d = sqn + g_sq[(b << 11) + m] - 2.f * drow[m];
        if (m == n) d = FINF;
        sdw[skew(m)] = d;
        if (d < bv || (d == bv && m < bi)) { bv = d; bi = m; }
    }
    __syncwarp();
    topk_from_smem(sdw, row, lane, bv, bi);
}

__global__ __launch_bounds__(128) void select3_kernel(const float* __restrict__ X) {
    __shared__ float sd[4][SD_LEN];
    int warp = threadIdx.x >> 5, lane = threadIdx.x & 31;
    int row = blockIdx.x * 4 + warp;
    int b = row >> 11, n = row & 2047;
    const float* Xb = X + (size_t)(b << 11) * 3;
    float xn = Xb[n * 3], yn = Xb[n * 3 + 1], zn = Xb[n * 3 + 2];
    float sqn = g_sq[row];
    float* sdw = sd[warp];
    float bv = FINF; int bi = 0x7fffffff;
#pragma unroll 4
    for (int j = 0; j < 64; j++) {
        int m = lane + 32 * j;
        float px = Xb[m * 3], py = Xb[m * 3 + 1], pz = Xb[m * 3 + 2];
        float dot = xn * px + yn * py + zn * pz;
        float d = sqn + g_sq[(b << 11) + m] - 2.f * dot;
        if (m == n) d = FINF;
        sdw[skew(m)] = d;
        if (d < bv || (d == bv && m < bi)) { bv = d; bi = m; }
    }
    __syncwarp();
    topk_from_smem(sdw, row, lane, bv, bi);
}

// ------------------- weight transforms (pre-split bf16) --------------------
__global__ void wtmp_kernel(const float* __restrict__ w, int C, int O) {
    int i = blockIdx.x * 256 + threadIdx.x;
    int tot = C * 2 * O;
    if (i < tot) {
        int c = i / (2 * O);
        int o = i % (2 * O);
        float v;
        if (o < O) v = w[(size_t)o * (2 * C) + c] - w[(size_t)o * (2 * C) + C + c];
        else       v = w[(size_t)(o - O) * (2 * C) + C + c];
        g_wtmp[i] = v;
    }
}

// layers 2-4: transposed [2O][C], bf16 hi/lo
__global__ void wtmp_bf_kernel(const float* __restrict__ w, int C, int O) {
    int i = blockIdx.x * 256 + threadIdx.x;
    int tot = 2 * O * C;
    if (i < tot) {
        int o = i / C;
        int c = i % C;
        float v;
        if (o < O) v = w[(size_t)o * (2 * C) + c] - w[(size_t)o * (2 * C) + C + c];
        else       v = w[(size_t)(o - O) * (2 * C) + C + c];
        __nv_bfloat16 h, l; split_bf16(v, h, l);
        g_wth[i] = h; g_wtl[i] = l;
    }
}

__global__ void wm_conv_kernel(const float* __restrict__ wm) {
    int i = blockIdx.x * 256 + threadIdx.x;   // 1024*512
    float v = wm[i];
    __nv_bfloat16 h, l; split_bf16(v, h, l);
    g_wmh[i] = h; g_wml[i] = l;
}

// ----------------------- layer-1 hh (K=3 feature GEMM) ---------------------
__global__ void hh3_kernel(const float* __restrict__ X) {
    __shared__ float w[3 * 128];
    int row = blockIdx.x;
    int t = threadIdx.x;   // 128
    w[t] = g_wtmp[t]; w[128 + t] = g_wtmp[128 + t]; w[256 + t] = g_wtmp[256 + t];
    __syncthreads();
    float x0 = X[row * 3], x1 = X[row * 3 + 1], x2 = X[row * 3 + 2];
    g_hh[(size_t)row * 128 + t] = x0 * w[t] + x1 * w[128 + t] + x2 * w[256 + t];
}

// ------------------- fused edge gather: stats + hmax/hmin -------------------
__global__ void edge_gather_kernel(int O) {
    __shared__ int   sidx[KNN];
    __shared__ float sacc[8];
    int row = blockIdx.x;
    int b = row >> 11;
    int t = threadIdx.x;     // == c
    if (t < KNN) sidx[t] = g_idx[(size_t)row * KNN + t];
    if (t < 8) sacc[t] = 0.f;
    __syncthreads();
    int twoO = 2 * O;
    float hcv = g_hh[(size_t)row * twoO + t];
    size_t bbase = ((size_t)(b << 11)) * twoO + O + t;
    float s = 0.f, q = 0.f, mx = -FINF, mn = FINF;
#pragma unroll
    for (int k = 0; k < KNN; k++) {
        float h = hcv + g_hh[bbase + (size_t)sidx[k] * twoO];
        s += h; q += h * h;
        mx = fmaxf(mx, h); mn = fminf(mn, h);
    }
    g_hmax[(size_t)row * O + t] = mx;
    g_hmin[(size_t)row * O + t] = mn;
    int gsz = O >> 2;
    int rw = gsz < 32 ? gsz : 32;
#pragma unroll
    for (int off = 16; off > 0; off >>= 1) {
        if (off < rw) {
            s += __shfl_down_sync(0xffffffffu, s, off, 32);
            q += __shfl_down_sync(0xffffffffu, q, off, 32);
        }
    }
    int g = t / gsz;
    if ((t & (rw - 1)) == 0) {
        atomicAdd(&sacc[g * 2 + 0], s);
        atomicAdd(&sacc[g * 2 + 1], q);
    }
    __syncthreads();
    if (t < 8) g_part[(size_t)row * 8 + t] = sacc[t];
}

// ------------------- cross-block stats reduce (edge & seq) ------------------
__global__ __launch_bounds__(256) void stats_reduce_kernel(int perrow, int ngroups,
                                                           float cnt) {
    __shared__ double ds[256], dq[256];
    int g = blockIdx.x, b = blockIdx.y, t = threadIdx.x;
    double s = 0.0, q = 0.0;
    for (int r = t; r < NPTS; r += 256) {
        size_t base = ((size_t)((b << 11) + r)) * perrow + g * 2;
        s += (double)g_part[base];
        q += (double)g_part[base + 1];
    }
    ds[t] = s; dq[t] = q;
    __syncthreads();
    for (int st = 128; st > 0; st >>= 1) {
        if (t < st) { ds[t] += ds[t + st]; dq[t] += dq[t + st]; }
        __syncthreads();
    }
    if (t == 0) {
        double mu = ds[0] / (double)cnt;
        double var = dq[0] / (double)cnt - mu * mu;
        g_mu[b * ngroups + g] = (float)mu;
        g_rs[b * ngroups + g] = rsqrtf((float)var + 1e-5f);
    }
}

// ---- edge final: affine+leaky of hmax/hmin; writes bf16 hi/lo + fused sq ---
__global__ void edge_final_kernel(int O, int coff,
                                  const float* __restrict__ gw,
                                  const float* __restrict__ gb) {
    __shared__ float red[256];
    int row = blockIdx.x;
    int b = row >> 11;
    int t = threadIdx.x;      // == c
    int g = t / (O >> 2);
    float mu = g_mu[b * 4 + g], rs = g_rs[b * 4 + g];
    float a = rs * gw[t];
    float b2 = gb[t] - mu * a;
    float h = (a >= 0.f) ? g_hmax[(size_t)row * O + t] : g_hmin[(size_t)row * O + t];
    float v = leaky02(a * h + b2);
    __nv_bfloat16 vh, vl; split_bf16(v, vh, vl);
    g_ch[(size_t)row * 512 + coff + t] = vh;
    g_cl[(size_t)row * 512 + coff + t] = vl;
    red[t] = v * v;
    __syncthreads();
    for (int st = O >> 1; st > 0; st >>= 1) {
        if (t < st) red[t] += red[t + st];
        __syncthreads();
    }
    if (t == 0) g_sq[row] = red[0];
}

// ------------------------------ seq GN stats --------------------------------
__global__ __launch_bounds__(256) void seq_stats_kernel() {
    __shared__ float sacc[32];
    int row = blockIdx.x;
    int t = threadIdx.x;
    if (t < 32) sacc[t] = 0.f;
    __syncthreads();
    const float* hr = g_hm + (size_t)row * 1024;
    float s = 0.f, q = 0.f;
#pragma unroll
    for (int j = 0; j < 4; j++) { float v = hr[t * 4 + j]; s += v; q += v * v; }
    s += __shfl_down_sync(0xffffffffu, s, 8, 16);
    s += __shfl_down_sync(0xffffffffu, s, 4, 16);
    s += __shfl_down_sync(0xffffffffu, s, 2, 16);
    s += __shfl_down_sync(0xffffffffu, s, 1, 16);
    q += __shfl_down_sync(0xffffffffu, q, 8, 16);
    q += __shfl_down_sync(0xffffffffu, q, 4, 16);
    q += __shfl_down_sync(0xffffffffu, q, 2, 16);
    q += __shfl_down_sync(0xffffffffu, q, 1, 16);
    int g = t >> 4;
    if ((t & 15) == 0) {
        atomicAdd(&sacc[g * 2 + 0], s);
        atomicAdd(&sacc[g * 2 + 1], q);
    }
    __syncthreads();
    if (t < 32) g_part[(size_t)row * 32 + t] = sacc[t];
}

// ------------------- seq normalize + leaky + max over N ---------------------
__global__ __launch_bounds__(256) void seq_max_part(const float* __restrict__ gmw,
                                                    const float* __restrict__ gmb) {
    int c = blockIdx.x * 256 + threadIdx.x;
    int b = blockIdx.y;
    int z = blockIdx.z;
    int g = c >> 6;
    float mu = g_mu[b * 16 + g], rs = g_rs[b * 16 + g];
    float w = gmw[c], bb = gmb[c];
    const float* col = g_hm + ((size_t)b * NPTS + z * 256) * 1024 + c;
    float m = -FINF;
#pragma unroll 4
    for (int n = 0; n < 256; n++) {
        float v = (col[(size_t)n * 1024] - mu) * rs * w + bb;
        m = fmaxf(m, leaky02(v));
    }
    g_pmax[((size_t)b * 8 + z) * 1024 + c] = m;
}

__global__ __launch_bounds__(256) void seq_max_combine() {
    int c = blockIdx.x * 256 + threadIdx.x;
    int b = blockIdx.y;
    float m = -FINF;
#pragma unroll
    for (int z = 0; z < 8; z++)
        m = fmaxf(m, g_pmax[((size_t)b * 8 + z) * 1024 + c]);
    g_gvec[b * 1024 + c] = m;
}

// --------------------------------- MLP head ---------------------------------
__device__ __forceinline__ float bsum256(float v, float* red, int t) {
    red[t] = v; __syncthreads();
    for (int s = 128; s > 0; s >>= 1) {
        if (t < s) red[t] += red[t + s];
        __syncthreads();
    }
    float r = red[0]; __syncthreads();
    return r;
}

__device__ __forceinline__ void ln_leaky(float* buf, int L,
                                         const float* __restrict__ w,
                                         const float* __restrict__ b,
                                         float* red, int t) {
    float s = 0.f, q = 0.f;
    for (int i = t; i < L; i += 256) { float v = buf[i]; s += v; q += v * v; }
    float S = bsum256(s, red, t);
    float Q = bsum256(q, red, t);
    float mu = S / (float)L;
    float var = Q / (float)L - mu * mu;
    float rs = rsqrtf(var + 1e-5f);
    for (int i = t; i < L; i += 256) {
        float v = (buf[i] - mu) * rs * w[i] + b[i];
        buf[i] = leaky02(v);
    }
    __syncthreads();
}

__global__ __launch_bounds__(256) void mlp_kernel(
    const float* __restrict__ fc1w, const float* __restrict__ fc1b,
    const float* __restrict__ ln1w, const float* __restrict__ ln1b,
    const float* __restrict__ fc2w, const float* __restrict__ fc2b,
    const float* __restrict__ ln2w, const float* __restrict__ ln2b,
    const float* __restrict__ fc3w, const float* __restrict__ fc3b,
    const float* __restrict__ ln3w, const float* __restrict__ ln3b,
    const float* __restrict__ fc4w, const float* __restrict__ fc4b,
    float* __restrict__ out)
{
    __shared__ __align__(16) float sin_[1024];
    __shared__ __align__(16) float t1[512];
    __shared__ __align__(16) float t2[256];
    __shared__ __align__(16) float t3[64];
    __shared__ float red[256];
    int b = blockIdx.x, t = threadIdx.x;
    for (int i = t; i < 1024; i += 256) sin_[i] = g_gvec[b * 1024 + i];
    __syncthreads();
    for (int o = t; o < 512; o += 256) {
        float acc = fc1b[o];
        const float4* wr = (const float4*)(fc1w + (size_t)o * 1024);
        const float4* xr = (const float4*)sin_;
        for (int c = 0; c < 256; c++) {
            float4 w4 = wr[c], x4 = xr[c];
            acc += w4.x * x4.x + w4.y * x4.y + w4.z * x4.z + w4.w * x4.w;
        }
        t1[o] = acc;
    }
    __syncthreads();
    ln_leaky(t1, 512, ln1w, ln1b, red, t);
    if (t < 256) {
        float acc = fc2b[t];
        const float4* wr = (const float4*)(fc2w + (size_t)t * 512);
        const float4* xr = (const float4*)t1;
        for (int c = 0; c < 128; c++) {
            float4 w4 = wr[c], x4 = xr[c];
            acc += w4.x * x4.x + w4.y * x4.y + w4.z * x4.z + w4.w * x4.w;
        }
        t2[t] = acc;
    }
    __syncthreads();
    ln_leaky(t2, 256, ln2w, ln2b, red, t);
    if (t < 64) {
        float acc = fc3b[t];
        const float4* wr = (const float4*)(fc3w + (size_t)t * 256);
        const float4* xr = (const float4*)t2;
        for (int c = 0; c < 64; c++) {
            float4 w4 = wr[c], x4 = xr[c];
            acc += w4.x * x4.x + w4.y * x4.y + w4.z * x4.z + w4.w * x4.w;
        }
        t3[t] = acc;
    }
    __syncthreads();
    ln_leaky(t3, 64, ln3w, ln3b, red, t);
    if (t < 2) {
        float acc = fc4b[t];
        for (int c = 0; c < 64; c++) acc += fc4w[t * 64 + c] * t3[c];
        out[b * 2 + t] = acc;
    }
}

// =============================== host driver ================================
extern "C" void kernel_launch(void* const* d_in, const int* in_sizes, int n_in,
                              void* d_out, int out_size)
{
    const float* x    = (const float*)d_in[0];
    const float* w1   = (const float*)d_in[1];
    const float* g1w  = (const float*)d_in[2];
    const float* g1b  = (const float*)d_in[3];
    const float* w2   = (const float*)d_in[4];
    const float* g2w  = (const float*)d_in[5];
    const float* g2b  = (const float*)d_in[6];
    const float* w3   = (const float*)d_in[7];
    const float* g3w  = (const float*)d_in[8];
    const float* g3b  = (const float*)d_in[9];
    const float* w4   = (const float*)d_in[10];
    const float* g4w  = (const float*)d_in[11];
    const float* g4b  = (const float*)d_in[12];
    const float* wm   = (const float*)d_in[13];
    const float* gmw  = (const float*)d_in[14];
    const float* gmb  = (const float*)d_in[15];
    const float* fc1w = (const float*)d_in[16];
    const float* fc1b = (const float*)d_in[17];
    const float* ln1w = (const float*)d_in[18];
    const float* ln1b = (const float*)d_in[19];
    const float* fc2w = (const float*)d_in[20];
    const float* fc2b = (const float*)d_in[21];
    const float* ln2w = (const float*)d_in[22];
    const float* ln2b = (const float*)d_in[23];
    const float* fc3w = (const float*)d_in[24];
    const float* fc3b = (const float*)d_in[25];
    const float* ln3w = (const float*)d_in[26];
    const float* ln3b = (const float*)d_in[27];
    const float* fc4w = (const float*)d_in[28];
    const float* fc4b = (const float*)d_in[29];
    float* out = (float*)d_out;

    float *pGram, *pHH, *pHm;
    __nv_bfloat16 *pCh, *pCl, *pWth, *pWtl, *pWmh, *pWml;
    cudaGetSymbolAddress((void**)&pGram, g_gram);
    cudaGetSymbolAddress((void**)&pHH,   g_hh);
    cudaGetSymbolAddress((void**)&pHm,   g_hm);
    cudaGetSymbolAddress((void**)&pCh,   g_ch);
    cudaGetSymbolAddress((void**)&pCl,   g_cl);
    cudaGetSymbolAddress((void**)&pWth,  g_wth);
    cudaGetSymbolAddress((void**)&pWtl,  g_wtl);
    cudaGetSymbolAddress((void**)&pWmh,  g_wmh);
    cudaGetSymbolAddress((void**)&pWml,  g_wml);

    cudaFuncSetAttribute(mmagemm_bf<true>,
                         cudaFuncAttributeMaxDynamicSharedMemorySize, GEMM_SMEM);
    cudaFuncSetAttribute(mmagemm_bf<false>,
                         cudaFuncAttributeMaxDynamicSharedMemorySize, GEMM_SMEM);

    // weight prep (independent of pipeline; run first)
    wm_conv_kernel<<<(1024 * 512) / 256, 256>>>(wm);

    // ---------------- layer 1 (C=3, O=64) ----------------------------------
    sq_kernel<<<(NROWS + 255) / 256, 256>>>(x);
    wtmp_kernel<<<(3 * 128 + 255) / 256, 256>>>(w1, 3, 64);
    hh3_kernel<<<NROWS, 128>>>(x);
    select3_kernel<<<NROWS / 4, 128>>>(x);
    edge_gather_kernel<<<NROWS, 64>>>(64);
    stats_reduce_kernel<<<dim3(4, NB), 256>>>(8, 4, (float)(NPTS * KNN * 16));
    edge_final_kernel<<<NROWS, 64>>>(64, 0, g1w, g1b);

    // ---------------- layers 2-4 ------------------------------------------
    struct LayerCfg {
        int coffin;   // input slice offset in g_ch/g_cl
        int C; int O;
        const float* w; const float* gw; const float* gb; int coff;
    };
    LayerCfg layers[3] = {
        { 0,   64,  64,  w2, g2w, g2b, 64  },
        { 64,  64,  128, w3, g3w, g3b, 128 },
        { 128, 128, 256, w4, g4w, g4b, 256 },
    };

    const int NTILES = (NPTS / 128) * (NPTS / 128 + 1) / 2;   // 136

    for (int l = 0; l < 3; l++) {
        const LayerCfg& L = layers[l];
        // per-batch symmetric Gram via tensor cores (pre-split bf16)
        mmagemm_bf<true><<<dim3(NTILES, 1, NB), 256, GEMM_SMEM>>>(
            pCh + L.coffin, pCl + L.coffin, 512, (size_t)NPTS * 512,
            pCh + L.coffin, pCl + L.coffin, 512, (size_t)NPTS * 512,
            pGram, NPTS, (size_t)NPTS * NPTS, L.C);
        select_gram_kernel<<<NROWS / 4, 128>>>();
        wtmp_bf_kernel<<<(2 * L.O * L.C + 255) / 256, 256>>>(L.w, L.C, L.O);
        mmagemm_bf<false><<<dim3(2 * L.O / 128, NROWS / 128, 1), 256, GEMM_SMEM>>>(
            pCh + L.coffin, pCl + L.coffin, 512, 0,
            pWth, pWtl, L.C, 0,
            pHH, 2 * L.O, 0, L.C);
        edge_gather_kernel<<<NROWS, L.O>>>(L.O);
        stats_reduce_kernel<<<dim3(4, NB), 256>>>(8, 4, (float)(NPTS * KNN * (L.O / 4)));
        edge_final_kernel<<<NROWS, L.O>>>(L.O, L.coff, L.gw, L.gb);
    }

    // mid: hm = concat @ wm^T  (16384 x 512 -> 1024)
    mmagemm_bf<false><<<dim3(1024 / 128, NROWS / 128, 1), 256, GEMM_SMEM>>>(
        pCh, pCl, 512, 0, pWmh, pWml, 512, 0, pHm, 1024, 0, 512);
    seq_stats_kernel<<<NROWS, 256>>>();
    stats_reduce_kernel<<<dim3(16, NB), 256>>>(32, 16, (float)(NPTS * 64));
    seq_max_part<<<dim3(4, NB, 8), 256>>>(gmw, gmb);
    seq_max_combine<<<dim3(4, NB), 256>>>();

    // head MLP
    mlp_kernel<<<NB, 256>>>(fc1w, fc1b, ln1w, ln1b,
                            fc2w, fc2b, ln2w, ln2b,
                            fc3w, fc3b, ln3w, ln3b,
                            fc4w, fc4b, out);
}